// round 5
// baseline (speedup 1.0000x reference)
#include <cuda_runtime.h>
#include <cstdint>
#include <math.h>

// Problem constants
#define NOBS   65536
#define DIM    64
#define HID    256
#define NELEM  (NOBS * DIM)      // 4194304 per sample

// ---------------------------------------------------------------------------
// Scratch (no dynamic allocation allowed -> __device__ globals)
// ---------------------------------------------------------------------------
__device__ float g_h1[(size_t)NOBS * HID];   // 64 MB
__device__ float g_h2[(size_t)NOBS * HID];   // 64 MB
__device__ float g_bd[(size_t)NOBS * DIM];   // 16 MB  (drift b)
__device__ float g_p0[(size_t)NOBS * HID];   // 64 MB  (X0 @ W1[64:128], step-invariant)

// ---------------------------------------------------------------------------
// threefry2x32 (JAX-exact), usable host+device
// ---------------------------------------------------------------------------
__host__ __device__ __forceinline__ void tf2x32(uint32_t k0, uint32_t k1,
                                                uint32_t& x0, uint32_t& x1) {
  uint32_t ks2 = k0 ^ k1 ^ 0x1BD11BDAu;
  x0 += k0; x1 += k1;
#define TFR(r) { x0 += x1; x1 = (x1 << (r)) | (x1 >> (32 - (r))); x1 ^= x0; }
  TFR(13) TFR(15) TFR(26) TFR(6)
  x0 += k1;  x1 += ks2 + 1u;
  TFR(17) TFR(29) TFR(16) TFR(24)
  x0 += ks2; x1 += k0 + 2u;
  TFR(13) TFR(15) TFR(26) TFR(6)
  x0 += k0;  x1 += k1 + 3u;
  TFR(17) TFR(29) TFR(16) TFR(24)
  x0 += k1;  x1 += ks2 + 4u;
  TFR(13) TFR(15) TFR(26) TFR(6)
  x0 += ks2; x1 += k0 + 5u;
#undef TFR
}

// XLA's f32 erf_inv (Giles polynomial) — matches lax.erf_inv lowering
__device__ __forceinline__ float erfinv_xla(float x) {
  float w = -log1pf(-x * x);
  float p;
  if (w < 5.0f) {
    w -= 2.5f;
    p = 2.81022636e-08f;
    p = fmaf(p, w, 3.43273939e-07f);
    p = fmaf(p, w, -3.5233877e-06f);
    p = fmaf(p, w, -4.39150654e-06f);
    p = fmaf(p, w, 0.00021858087f);
    p = fmaf(p, w, -0.00125372503f);
    p = fmaf(p, w, -0.00417768164f);
    p = fmaf(p, w, 0.246640727f);
    p = fmaf(p, w, 1.50140941f);
  } else {
    w = sqrtf(w) - 3.0f;
    p = -0.000200214257f;
    p = fmaf(p, w, 0.000100950558f);
    p = fmaf(p, w, 0.00134934322f);
    p = fmaf(p, w, -0.00367342844f);
    p = fmaf(p, w, 0.00573950773f);
    p = fmaf(p, w, -0.0076224613f);
    p = fmaf(p, w, 0.00943887047f);
    p = fmaf(p, w, 1.00167406f);
    p = fmaf(p, w, 2.83297682f);
  }
  return p * x;
}

// JAX normal from 32 random bits: u = max(lo, f*2 + lo), f in [0,1); sqrt(2)*erfinv(u)
__device__ __forceinline__ float bits_to_normal(uint32_t bits) {
  float f = __uint_as_float((bits >> 9) | 0x3F800000u) - 1.0f;
  const float lo = -0.99999994f;                 // nextafter(-1, 0)
  float u = fmaxf(lo, f * 2.0f + lo);            // (hi-lo) rounds to exactly 2.0f
  return 1.41421356237f * erfinv_xla(u);         // f32(sqrt(2)) = 0x3FB504F3
}

// ---------------------------------------------------------------------------
// SDE update: X_new = X_old + ds*(b + cf*(s*b - X_old + X0)) + 0.125*eta
// eta element i (partitionable threefry): bits = x0^x1 of tf(key, (0, i))
// ---------------------------------------------------------------------------
__global__ void update_kernel(const float* Xold, const float* __restrict__ X0,
                              float* Xnew, float s, float cf,
                              uint32_t k0, uint32_t k1) {
  int i = blockIdx.x * blockDim.x + threadIdx.x;   // grid sized exactly NELEM
  uint32_t x0 = 0u, x1 = (uint32_t)i;
  tf2x32(k0, k1, x0, x1);
  float eta = bits_to_normal(x0 ^ x1);
  float b  = g_bd[i];
  float Xo = Xold[i];
  float drift = b + cf * (s * b - Xo + X0[i]);
  Xnew[i] = Xo + 0.015625f * drift + 0.125f * eta;   // ds = 1/64, G*sqrt(ds) = 1/8
}

// ---------------------------------------------------------------------------
// Register-tiled fp32 GEMM: C[M x BN*gridDim.x] = A[M x K] @ B[K x N]
// BM=128, BK=8, BN=16*TN, 256 threads, 8xTN micro-tile, double-buffered smem.
// Optional epilogue: +initC (full tile), +scoef*srow[col], +bias[col], relu.
// M, N, K all divisible by tile sizes here (65536 / 256|64 / 64|256).
// ---------------------------------------------------------------------------
template<int TN, bool ADD_INIT, bool ADD_SROW, bool ADD_BIAS, bool RELU>
__global__ __launch_bounds__(256, 2)
void gemm_kernel(const float* __restrict__ A, int lda,
                 const float* __restrict__ B, int ldb,
                 const float* __restrict__ initC,
                 const float* __restrict__ srow, float scoef,
                 const float* __restrict__ bias,
                 float* __restrict__ C, int ldc, int K) {
  constexpr int BM = 128, BK = 8, BN = 16 * TN;
  __shared__ float As[2][BK][BM];
  __shared__ float Bs[2][BK][BN];

  const int tid     = threadIdx.x;
  const int rowBase = blockIdx.y * BM;
  const int colBase = blockIdx.x * BN;

  // A staging: 128 rows x 8 k -> one float4 per thread, stored transposed
  const int aRow = tid >> 1;
  const int aK   = (tid & 1) << 2;
  const float* Ap = A + (rowBase + aRow) * lda + aK;

  // B staging: 8 k x BN cols -> one float4 per (active) thread
  int bRow, bCol;
  bool bAct;
  if constexpr (TN == 8) { bRow = tid >> 5; bCol = (tid & 31) << 2; bAct = true; }
  else                   { bRow = tid >> 4; bCol = (tid & 15) << 2; bAct = (tid < 128); }
  const float* Bp = B + bRow * ldb + colBase + bCol;

  const int cCol = (tid & 15) * TN;
  const int cRow = (tid >> 4) * 8;

  float acc[8][TN];
#pragma unroll
  for (int i = 0; i < 8; i++)
#pragma unroll
    for (int j = 0; j < TN; j++) acc[i][j] = 0.0f;

  const int nStages = K >> 3;

  float4 aReg = *(const float4*)Ap;
  float4 bReg = make_float4(0.f, 0.f, 0.f, 0.f);
  if (bAct) bReg = *(const float4*)Bp;
  As[0][aK + 0][aRow] = aReg.x;
  As[0][aK + 1][aRow] = aReg.y;
  As[0][aK + 2][aRow] = aReg.z;
  As[0][aK + 3][aRow] = aReg.w;
  if (bAct) *(float4*)&Bs[0][bRow][bCol] = bReg;
  __syncthreads();

  int buf = 0;
  for (int st = 0; st < nStages; ++st) {
    if (st + 1 < nStages) {
      aReg = *(const float4*)(Ap + (st + 1) * BK);
      if (bAct) bReg = *(const float4*)(Bp + (st + 1) * BK * ldb);
    }
#pragma unroll
    for (int kk = 0; kk < BK; kk++) {
      float a[8], b[TN];
      *(float4*)&a[0] = *(const float4*)&As[buf][kk][cRow];
      *(float4*)&a[4] = *(const float4*)&As[buf][kk][cRow + 4];
      *(float4*)&b[0] = *(const float4*)&Bs[buf][kk][cCol];
      if constexpr (TN == 8) *(float4*)&b[4] = *(const float4*)&Bs[buf][kk][cCol + 4];
#pragma unroll
      for (int i = 0; i < 8; i++)
#pragma unroll
        for (int j = 0; j < TN; j++)
          acc[i][j] = fmaf(a[i], b[j], acc[i][j]);
    }
    if (st + 1 < nStages) {
      buf ^= 1;
      As[buf][aK + 0][aRow] = aReg.x;
      As[buf][aK + 1][aRow] = aReg.y;
      As[buf][aK + 2][aRow] = aReg.z;
      As[buf][aK + 3][aRow] = aReg.w;
      if (bAct) *(float4*)&Bs[buf][bRow][bCol] = bReg;
      __syncthreads();
    }
  }

#pragma unroll
  for (int i = 0; i < 8; i++) {
    const int r = rowBase + cRow + i;
    float out[TN];
#pragma unroll
    for (int j = 0; j < TN; j++) {
      const int c = colBase + cCol + j;
      float v = acc[i][j];
      if constexpr (ADD_INIT) v += initC[r * ldc + c];
      if constexpr (ADD_SROW) v += scoef * srow[c];
      if constexpr (ADD_BIAS) v += bias[c];
      if constexpr (RELU)     v = fmaxf(v, 0.0f);
      out[j] = v;
    }
#pragma unroll
    for (int j = 0; j < TN; j += 4)
      *(float4*)&C[r * ldc + colBase + cCol + j] = *(const float4*)&out[j];
  }
}

// ---------------------------------------------------------------------------
// Host-side key derivation (partitionable threefry):
//   split(key)[j] = full pair of tf(key, (0, j))
// ---------------------------------------------------------------------------
static inline void host_split2(uint32_t k0, uint32_t k1, uint32_t out[2][2]) {
  for (uint32_t j = 0; j < 2; j++) {
    uint32_t a = 0u, b = j;
    tf2x32(k0, k1, a, b);
    out[j][0] = a; out[j][1] = b;
  }
}

extern "C" void kernel_launch(void* const* d_in, const int* in_sizes, int n_in,
                              void* d_out, int out_size) {
  (void)in_sizes; (void)n_in; (void)out_size;
  const float* X0 = (const float*)d_in[0];
  const float* W1 = (const float*)d_in[1];   // [129, 256]
  const float* b1 = (const float*)d_in[2];
  const float* W2 = (const float*)d_in[3];   // [256, 256]
  const float* b2 = (const float*)d_in[4];
  const float* W3 = (const float*)d_in[5];   // [256, 64]
  const float* b3 = (const float*)d_in[6];
  float* out = (float*)d_out;                // [2, 65536, 64]

  float *h1, *h2, *bd, *p0;
  cudaGetSymbolAddress((void**)&h1, g_h1);
  cudaGetSymbolAddress((void**)&h2, g_h2);
  cudaGetSymbolAddress((void**)&bd, g_bd);
  cudaGetSymbolAddress((void**)&p0, g_p0);

  // key chain: root = jax.random.key(1) -> data (0, 1)
  uint32_t sk[2][2];
  host_split2(0u, 1u, sk);   // per-sample keys

  const dim3 g256(2, 512), g64(1, 512);
  const int UPD_BLOCKS = NELEM / 256;

  // Step-invariant partial: P0 = X0 @ W1[64:128]   (no bias, no relu)
  gemm_kernel<8, false, false, false, false><<<g256, 256>>>(
      X0, DIM, W1 + 64 * HID, HID, nullptr, nullptr, 0.f, nullptr, p0, HID, 64);

  for (int smp = 0; smp < 2; ++smp) {
    uint32_t ks[2][2];
    host_split2(sk[smp][0], sk[smp][1], ks);   // k0 (eta0), kloop
    uint32_t ke0 = ks[0][0], ke1 = ks[0][1];
    uint32_t kl0 = ks[1][0], kl1 = ks[1][1];
    float* X = out + (size_t)smp * NELEM;

    for (int n = 0; n < 64; ++n) {
      const float s = (float)n * 0.015625f;   // exact n/64
      float cf = 0.0f;
      uint32_t nk0, nk1;
      const float* Xin;
      if (n == 0) {
        nk0 = ke0; nk1 = ke1; Xin = X0;       // first Euler step from X0
      } else {
        uint32_t kk[2][2];
        host_split2(kl0, kl1, kk);            // key, kn = split(key)
        kl0 = kk[0][0]; kl1 = kk[0][1];
        nk0 = kk[1][0]; nk1 = kk[1][1];
        Xin = X;
        const float sg = 1.0f - s;
        const float A  = 1.0f / (s * sg);
        cf = 0.5f * (1.0f - sg * sg) * A;     // 0.5*(G^2 - sigma^2) * A
      }

      // h1 = relu(Xin @ W1[0:64] + P0 + s*W1[128] + b1)
      gemm_kernel<8, true, true, true, true><<<g256, 256>>>(
          Xin, DIM, W1, HID, p0, W1 + 128 * HID, s, b1, h1, HID, 64);
      // h2 = relu(h1 @ W2 + b2)
      gemm_kernel<8, false, false, true, true><<<g256, 256>>>(
          h1, HID, W2, HID, nullptr, nullptr, 0.f, b2, h2, HID, HID);
      // b  = h2 @ W3 + b3
      gemm_kernel<4, false, false, true, false><<<g64, 256>>>(
          h2, HID, W3, DIM, nullptr, nullptr, 0.f, b3, bd, DIM, HID);
      // X <- X + ds*(b + cf*(s*b - X + X0)) + 0.125*eta(key_n)
      update_kernel<<<UPD_BLOCKS, 256>>>(Xin, X0, X, s, cf, nk0, nk1);
    }
  }
}

// round 7
// speedup vs baseline: 1.9082x; 1.9082x over previous
#include <cuda_runtime.h>
#include <cuda_bf16.h>
#include <cstdint>
#include <math.h>

#define NOBS   65536
#define DIM    64
#define NELEM  (NOBS * DIM)

// ---------------------------------------------------------------------------
// Weight fragment arrays (prepped once per launch): B-fragment order for
// mma.sync.m16n8k16: entry ((nj*KT + ki)*32 + lane)*2 + {0,1}
//   b0 = {W[k=ki*16+2t][n], W[k+1][n]},  b1 = {W[k+8][n], W[k+9][n]},  n = nj*8 + (lane>>2)
// plane 0 = bf16 hi, plane 1 = bf16 residual (lo)
// ---------------------------------------------------------------------------
__device__ uint32_t g_w1f[2][256 * 64];   // 32 nj x  8 ki tiles
__device__ uint32_t g_w2f[2][512 * 64];   // 32 nj x 16 ki
__device__ uint32_t g_w3f[2][128 * 64];   //  8 nj x 16 ki

// ---------------------------------------------------------------------------
// threefry2x32 (JAX partitionable, exact) — host + device
// ---------------------------------------------------------------------------
__host__ __device__ __forceinline__ void tf2x32(uint32_t k0, uint32_t k1,
                                                uint32_t& x0, uint32_t& x1) {
  uint32_t ks2 = k0 ^ k1 ^ 0x1BD11BDAu;
  x0 += k0; x1 += k1;
#define TFR(r) { x0 += x1; x1 = (x1 << (r)) | (x1 >> (32 - (r))); x1 ^= x0; }
  TFR(13) TFR(15) TFR(26) TFR(6)
  x0 += k1;  x1 += ks2 + 1u;
  TFR(17) TFR(29) TFR(16) TFR(24)
  x0 += ks2; x1 += k0 + 2u;
  TFR(13) TFR(15) TFR(26) TFR(6)
  x0 += k0;  x1 += k1 + 3u;
  TFR(17) TFR(29) TFR(16) TFR(24)
  x0 += k1;  x1 += ks2 + 4u;
  TFR(13) TFR(15) TFR(26) TFR(6)
  x0 += ks2; x1 += k0 + 5u;
#undef TFR
}

__device__ __forceinline__ float erfinv_xla(float x) {
  float w = -log1pf(-x * x);
  float p;
  if (w < 5.0f) {
    w -= 2.5f;
    p = 2.81022636e-08f;
    p = fmaf(p, w, 3.43273939e-07f);
    p = fmaf(p, w, -3.5233877e-06f);
    p = fmaf(p, w, -4.39150654e-06f);
    p = fmaf(p, w, 0.00021858087f);
    p = fmaf(p, w, -0.00125372503f);
    p = fmaf(p, w, -0.00417768164f);
    p = fmaf(p, w, 0.246640727f);
    p = fmaf(p, w, 1.50140941f);
  } else {
    w = sqrtf(w) - 3.0f;
    p = -0.000200214257f;
    p = fmaf(p, w, 0.000100950558f);
    p = fmaf(p, w, 0.00134934322f);
    p = fmaf(p, w, -0.00367342844f);
    p = fmaf(p, w, 0.00573950773f);
    p = fmaf(p, w, -0.0076224613f);
    p = fmaf(p, w, 0.00943887047f);
    p = fmaf(p, w, 1.00167406f);
    p = fmaf(p, w, 2.83297682f);
  }
  return p * x;
}
__device__ __forceinline__ float bits_to_normal(uint32_t bits) {
  float f = __uint_as_float((bits >> 9) | 0x3F800000u) - 1.0f;
  const float lo = -0.99999994f;
  float u = fmaxf(lo, f * 2.0f + lo);
  return 1.41421356237f * erfinv_xla(u);
}

// ---------------------------------------------------------------------------
// bf16 helpers
// ---------------------------------------------------------------------------
__device__ __forceinline__ uint32_t pack_bf2(float a, float b) {
  uint32_t la = (uint32_t)__bfloat16_as_ushort(__float2bfloat16_rn(a));
  uint32_t hb = (uint32_t)__bfloat16_as_ushort(__float2bfloat16_rn(b));
  return la | (hb << 16);
}
__device__ __forceinline__ void split_pack(float a, float b,
                                           uint32_t& hi, uint32_t& lo) {
  __nv_bfloat16 ah = __float2bfloat16_rn(a), bh = __float2bfloat16_rn(b);
  hi = (uint32_t)__bfloat16_as_ushort(ah) |
       ((uint32_t)__bfloat16_as_ushort(bh) << 16);
  lo = pack_bf2(a - __bfloat162float(ah), b - __bfloat162float(bh));
}

__device__ __forceinline__ void mma_bf16(float (&d)[4], const uint32_t (&a)[4],
                                         const uint32_t (&b)[2]) {
  asm volatile(
      "mma.sync.aligned.m16n8k16.row.col.f32.bf16.bf16.f32 "
      "{%0,%1,%2,%3}, {%4,%5,%6,%7}, {%8,%9}, {%0,%1,%2,%3};"
      : "+f"(d[0]), "+f"(d[1]), "+f"(d[2]), "+f"(d[3])
      : "r"(a[0]), "r"(a[1]), "r"(a[2]), "r"(a[3]), "r"(b[0]), "r"(b[1]));
}

// ---------------------------------------------------------------------------
// Weight prep: one thread per (frag tile, lane); produces hi+lo b0,b1
// ---------------------------------------------------------------------------
__global__ void prep_weights(const float* __restrict__ W1,
                             const float* __restrict__ W2,
                             const float* __restrict__ W3) {
  int tid = blockIdx.x * 256 + threadIdx.x;
  int T = tid >> 5, lane = tid & 31;
  if (T >= 896) return;
  int g = lane >> 2, t = lane & 3;
  const float* W; int ldn, ni, ki, idx; uint32_t *dh, *dl;
  if (T < 256)      { ni = T >> 3;  ki = T & 7;  W = W1; ldn = 256; dh = g_w1f[0]; dl = g_w1f[1]; idx = T; }
  else if (T < 768) { int T2 = T - 256; ni = T2 >> 4; ki = T2 & 15; W = W2; ldn = 256; dh = g_w2f[0]; dl = g_w2f[1]; idx = T2; }
  else              { int T3 = T - 768; ni = T3 >> 4; ki = T3 & 15; W = W3; ldn = 64;  dh = g_w3f[0]; dl = g_w3f[1]; idx = T3; }
  int n  = ni * 8 + g;
  int k0 = ki * 16 + 2 * t;
  float w00 = W[(k0    ) * ldn + n], w01 = W[(k0 + 1) * ldn + n];
  float w10 = W[(k0 + 8) * ldn + n], w11 = W[(k0 + 9) * ldn + n];
  uint32_t h0, l0, h1, l1;
  split_pack(w00, w01, h0, l0);
  split_pack(w10, w11, h1, l1);
  int e = (idx * 32 + lane) * 2;
  dh[e] = h0; dh[e + 1] = h1;
  dl[e] = l0; dl[e + 1] = l1;
}

// ---------------------------------------------------------------------------
// Generic fragment GEMM phase: acc[MT][NJ][4] += A(frags in smem) @ B(frags gmem)
// A tile address: base + ((mBase+mt)*KT + ki)*512 + lane*16  (uint4 = a0..a3)
// 3-pass split accumulation: hi*hi + lo*hi + hi*lo
// ---------------------------------------------------------------------------
template<int KT, int NJ, int MT>
__device__ __forceinline__ void gemm_frags(
    float (&acc)[MT][NJ][4],
    const char* __restrict__ aHi, const char* __restrict__ aLo,
    int mBase, int lane,
    const uint32_t* __restrict__ Bh, const uint32_t* __restrict__ Bl,
    int njBase) {
#pragma unroll
  for (int ki = 0; ki < KT; ++ki) {
    uint32_t ah[MT][4], al[MT][4];
#pragma unroll
    for (int mt = 0; mt < MT; ++mt) {
      uint4 vh = *(const uint4*)(aHi + (size_t)(((mBase + mt) * KT + ki) * 512 + lane * 16));
      ah[mt][0] = vh.x; ah[mt][1] = vh.y; ah[mt][2] = vh.z; ah[mt][3] = vh.w;
      uint4 vl = *(const uint4*)(aLo + (size_t)(((mBase + mt) * KT + ki) * 512 + lane * 16));
      al[mt][0] = vl.x; al[mt][1] = vl.y; al[mt][2] = vl.z; al[mt][3] = vl.w;
    }
    uint32_t bh[NJ][2], bl[NJ][2];
#pragma unroll
    for (int j = 0; j < NJ; ++j) {
      uint2 vh = *(const uint2*)&Bh[(((njBase + j) * KT + ki) * 32 + lane) * 2];
      bh[j][0] = vh.x; bh[j][1] = vh.y;
      uint2 vl = *(const uint2*)&Bl[(((njBase + j) * KT + ki) * 32 + lane) * 2];
      bl[j][0] = vl.x; bl[j][1] = vl.y;
    }
#pragma unroll
    for (int mt = 0; mt < MT; ++mt)
#pragma unroll
      for (int j = 0; j < NJ; ++j) {
        mma_bf16(acc[mt][j], ah[mt], bh[j]);
        mma_bf16(acc[mt][j], al[mt], bh[j]);
        mma_bf16(acc[mt][j], ah[mt], bl[j]);
      }
  }
}

// ---------------------------------------------------------------------------
// Fused SDE step: per 128-row CTA: stage [X|X0] -> MLP (3 GEMMs) -> update
// smem: actHi 0..32K, actLo 32K..64K, hHi 64K..128K, hLo 128K..192K
// ---------------------------------------------------------------------------
__global__ void __launch_bounds__(256, 1)
fused_step(const float* __restrict__ Xin, const float* __restrict__ X0,
           float* __restrict__ Xout,
           const float* __restrict__ b1, const float* __restrict__ w1s,
           const float* __restrict__ b2, const float* __restrict__ b3,
           float s, float cf, uint32_t rk0, uint32_t rk1) {
  extern __shared__ char sm[];
  char* actHi = sm;
  char* actLo = sm + 32768;
  char* hHi   = sm + 65536;
  char* hLo   = sm + 131072;

  const int tid  = threadIdx.x;
  const int wid  = tid >> 5;
  const int lane = tid & 31;
  const int g    = lane >> 2;
  const int t    = lane & 3;
  const int rowBase = blockIdx.x * 128;

  // ---- phase 0: stage A1 = [Xin | X0] as bf16 hi/lo fragments ----
#pragma unroll
  for (int it = 0; it < 8; ++it) {
    int tile = wid * 8 + it;              // 64 tiles: mi(8) x ki(8)
    int mi = tile >> 3, ki = tile & 7;
    const float* src = (ki < 4) ? Xin : X0;
    int kc = (ki & 3) * 16;
    const float* p0 = src + (size_t)(rowBase + mi * 16 + g) * DIM + kc;
    const float* p1 = p0 + 8 * DIM;
    float2 v00 = *(const float2*)(p0 + 2 * t);
    float2 v01 = *(const float2*)(p0 + 2 * t + 8);
    float2 v10 = *(const float2*)(p1 + 2 * t);
    float2 v11 = *(const float2*)(p1 + 2 * t + 8);
    uint32_t h0, l0, h1, l1, h2, l2, h3, l3;
    split_pack(v00.x, v00.y, h0, l0);   // a0: (row g,   k 2t..2t+1)
    split_pack(v10.x, v10.y, h1, l1);   // a1: (row g+8, k 2t..2t+1)
    split_pack(v01.x, v01.y, h2, l2);   // a2: (row g,   k 2t+8..)
    split_pack(v11.x, v11.y, h3, l3);   // a3: (row g+8, k 2t+8..)
    int off = (mi * 8 + ki) * 512 + lane * 16;
    *(uint4*)(actHi + off) = make_uint4(h0, h1, h2, h3);
    *(uint4*)(actLo + off) = make_uint4(l0, l1, l2, l3);
  }
  __syncthreads();

  const int mrow = wid >> 2, ncol = wid & 3;   // 2x4 warp grid, 64x64 tiles

  // ---- phase 1: h1 = relu(A1 @ W1' + s*w1s + b1) -> h frags ----
  {
    float acc[4][8][4];
#pragma unroll
    for (int a = 0; a < 4; ++a)
#pragma unroll
      for (int b = 0; b < 8; ++b)
#pragma unroll
        for (int c = 0; c < 4; ++c) acc[a][b][c] = 0.f;
    gemm_frags<8, 8, 4>(acc, actHi, actLo, mrow * 4, lane,
                        g_w1f[0], g_w1f[1], ncol * 8);
#pragma unroll
    for (int j = 0; j < 8; ++j) {
      int nj = ncol * 8 + j;
      int c0 = nj * 8 + 2 * t;
      float bb0 = b1[c0]     + s * w1s[c0];
      float bb1 = b1[c0 + 1] + s * w1s[c0 + 1];
#pragma unroll
      for (int mt = 0; mt < 4; ++mt) {
        int mi = mrow * 4 + mt;
        float v00 = fmaxf(acc[mt][j][0] + bb0, 0.f);
        float v01 = fmaxf(acc[mt][j][1] + bb1, 0.f);
        float v10 = fmaxf(acc[mt][j][2] + bb0, 0.f);
        float v11 = fmaxf(acc[mt][j][3] + bb1, 0.f);
        uint32_t h0, l0, h1, l1;
        split_pack(v00, v01, h0, l0);
        split_pack(v10, v11, h1, l1);
        int off = (mi * 16 + (nj >> 1)) * 512 + lane * 16 + (nj & 1) * 8;
        *(uint2*)(hHi + off) = make_uint2(h0, h1);
        *(uint2*)(hLo + off) = make_uint2(l0, l1);
      }
    }
  }
  __syncthreads();

  // ---- phase 2: h2 = relu(h1 @ W2' + b2) -> overwrite h frags ----
  {
    float acc[4][8][4];
#pragma unroll
    for (int a = 0; a < 4; ++a)
#pragma unroll
      for (int b = 0; b < 8; ++b)
#pragma unroll
        for (int c = 0; c < 4; ++c) acc[a][b][c] = 0.f;
    gemm_frags<16, 8, 4>(acc, hHi, hLo, mrow * 4, lane,
                         g_w2f[0], g_w2f[1], ncol * 8);
    __syncthreads();   // all warps done reading h1 before overwrite
#pragma unroll
    for (int j = 0; j < 8; ++j) {
      int nj = ncol * 8 + j;
      int c0 = nj * 8 + 2 * t;
      float bb0 = b2[c0];
      float bb1 = b2[c0 + 1];
#pragma unroll
      for (int mt = 0; mt < 4; ++mt) {
        int mi = mrow * 4 + mt;
        float v00 = fmaxf(acc[mt][j][0] + bb0, 0.f);
        float v01 = fmaxf(acc[mt][j][1] + bb1, 0.f);
        float v10 = fmaxf(acc[mt][j][2] + bb0, 0.f);
        float v11 = fmaxf(acc[mt][j][3] + bb1, 0.f);
        uint32_t h0, l0, h1, l1;
        split_pack(v00, v01, h0, l0);
        split_pack(v10, v11, h1, l1);
        int off = (mi * 16 + (nj >> 1)) * 512 + lane * 16 + (nj & 1) * 8;
        *(uint2*)(hHi + off) = make_uint2(h0, h1);
        *(uint2*)(hLo + off) = make_uint2(l0, l1);
      }
    }
  }
  __syncthreads();

  // ---- phase 3: bd = h2 @ W3' + b3, fused SDE update + threefry noise ----
  {
    const int mrow3 = wid >> 1, ncol3 = wid & 1;   // 4x2 warp grid, 32x32
    float acc[2][4][4];
#pragma unroll
    for (int a = 0; a < 2; ++a)
#pragma unroll
      for (int b = 0; b < 4; ++b)
#pragma unroll
        for (int c = 0; c < 4; ++c) acc[a][b][c] = 0.f;
    gemm_frags<16, 4, 2>(acc, hHi, hLo, mrow3 * 2, lane,
                         g_w3f[0], g_w3f[1], ncol3 * 4);
#pragma unroll
    for (int j = 0; j < 4; ++j) {
      int nj = ncol3 * 4 + j;
      int c0 = nj * 8 + 2 * t;
      float bb0 = b3[c0], bb1 = b3[c0 + 1];
#pragma unroll
      for (int mt = 0; mt < 2; ++mt) {
        int mi = mrow3 * 2 + mt;
#pragma unroll
        for (int half = 0; half < 2; ++half) {
          int r = rowBase + mi * 16 + g + half * 8;
          float bA = acc[mt][j][half * 2 + 0] + bb0;
          float bB = acc[mt][j][half * 2 + 1] + bb1;
          int i0 = r * DIM + c0;
          float2 Xo  = *(const float2*)(Xin + i0);
          float2 x0v = *(const float2*)(X0  + i0);
          uint32_t u0 = 0u, u1 = (uint32_t)i0;
          tf2x32(rk0, rk1, u0, u1);
          float e0 = bits_to_normal(u0 ^ u1);
          uint32_t w0 = 0u, w1 = (uint32_t)(i0 + 1);
          tf2x32(rk0, rk1, w0, w1);
          float e1 = bits_to_normal(w0 ^ w1);
          float d0 = bA + cf * (s * bA - Xo.x + x0v.x);
          float d1 = bB + cf * (s * bB - Xo.y + x0v.y);
          float2 o;
          o.x = Xo.x + 0.015625f * d0 + 0.125f * e0;
          o.y = Xo.y + 0.015625f * d1 + 0.125f * e1;
          *(float2*)(Xout + i0) = o;
        }
      }
    }
  }
}

// ---------------------------------------------------------------------------
// Host
// ---------------------------------------------------------------------------
static inline void host_split2(uint32_t k0, uint32_t k1, uint32_t out[2][2]) {
  for (uint32_t j = 0; j < 2; j++) {
    uint32_t a = 0u, b = j;
    tf2x32(k0, k1, a, b);
    out[j][0] = a; out[j][1] = b;
  }
}

extern "C" void kernel_launch(void* const* d_in, const int* in_sizes, int n_in,
                              void* d_out, int out_size) {
  (void)in_sizes; (void)n_in; (void)out_size;
  const float* X0 = (const float*)d_in[0];
  const float* W1 = (const float*)d_in[1];   // [129, 256]
  const float* b1 = (const float*)d_in[2];
  const float* W2 = (const float*)d_in[3];   // [256, 256]
  const float* b2 = (const float*)d_in[4];
  const float* W3 = (const float*)d_in[5];   // [256, 64]
  const float* b3 = (const float*)d_in[6];
  float* out = (float*)d_out;                // [2, 65536, 64]

  const float* w1s = W1 + 128 * 256;         // s-feature row

  constexpr int SMEM = 196608;
  static bool attr_set = false;
  cudaFuncSetAttribute((const void*)fused_step,
                       cudaFuncAttributeMaxDynamicSharedMemorySize, SMEM);
  (void)attr_set;

  prep_weights<<<112, 256>>>(W1, W2, W3);

  uint32_t sk[2][2];
  host_split2(0u, 1u, sk);   // jax.random.key(1) -> 2 sample keys

  for (int smp = 0; smp < 2; ++smp) {
    uint32_t ks[2][2];
    host_split2(sk[smp][0], sk[smp][1], ks);
    uint32_t ke0 = ks[0][0], ke1 = ks[0][1];   // k0 (eta at step 0)
    uint32_t kl0 = ks[1][0], kl1 = ks[1][1];   // kloop
    float* X = out + (size_t)smp * NELEM;

    for (int n = 0; n < 64; ++n) {
      const float s = (float)n * 0.015625f;
      float cf = 0.0f;
      uint32_t nk0, nk1;
      const float* Xin;
      if (n == 0) {
        nk0 = ke0; nk1 = ke1; Xin = X0;
      } else {
        uint32_t kk[2][2];
        host_split2(kl0, kl1, kk);
        kl0 = kk[0][0]; kl1 = kk[0][1];
        nk0 = kk[1][0]; nk1 = kk[1][1];
        Xin = X;
        const float sg = 1.0f - s;
        cf = 0.5f * (1.0f - sg * sg) / (s * sg);
      }
      fused_step<<<NOBS / 128, 256, SMEM>>>(
          Xin, X0, X, b1, w1s, b2, b3, s, cf, nk0, nk1);
    }
  }
}

// round 8
// speedup vs baseline: 2.3391x; 1.2258x over previous
#include <cuda_runtime.h>
#include <cuda_bf16.h>
#include <cstdint>
#include <math.h>

#define NOBS   65536
#define DIM    64
#define NELEM  (NOBS * DIM)

// ---------------------------------------------------------------------------
// Weight fragment arrays (prepped once per launch): B-fragment order for
// mma.sync.m16n8k16: entry ((nj*KT + ki)*32 + lane)*2 + {0,1}
//   b0 = {W[k=ki*16+2t][n], W[k+1][n]},  b1 = {W[k+8][n], W[k+9][n]},  n = nj*8 + (lane>>2)
// plane 0 = bf16 hi, plane 1 = bf16 residual (lo)
// ---------------------------------------------------------------------------
__device__ uint32_t g_w1f[2][256 * 64];   // 32 nj x  8 ki tiles
__device__ uint32_t g_w2f[2][512 * 64];   // 32 nj x 16 ki
__device__ uint32_t g_w3f[2][128 * 64];   //  8 nj x 16 ki

// ---------------------------------------------------------------------------
// threefry2x32 (JAX partitionable, exact) — host + device
// ---------------------------------------------------------------------------
__host__ __device__ __forceinline__ void tf2x32(uint32_t k0, uint32_t k1,
                                                uint32_t& x0, uint32_t& x1) {
  uint32_t ks2 = k0 ^ k1 ^ 0x1BD11BDAu;
  x0 += k0; x1 += k1;
#define TFR(r) { x0 += x1; x1 = (x1 << (r)) | (x1 >> (32 - (r))); x1 ^= x0; }
  TFR(13) TFR(15) TFR(26) TFR(6)
  x0 += k1;  x1 += ks2 + 1u;
  TFR(17) TFR(29) TFR(16) TFR(24)
  x0 += ks2; x1 += k0 + 2u;
  TFR(13) TFR(15) TFR(26) TFR(6)
  x0 += k0;  x1 += k1 + 3u;
  TFR(17) TFR(29) TFR(16) TFR(24)
  x0 += k1;  x1 += ks2 + 4u;
  TFR(13) TFR(15) TFR(26) TFR(6)
  x0 += ks2; x1 += k0 + 5u;
#undef TFR
}

__device__ __forceinline__ float erfinv_xla(float x) {
  float w = -log1pf(-x * x);
  float p;
  if (w < 5.0f) {
    w -= 2.5f;
    p = 2.81022636e-08f;
    p = fmaf(p, w, 3.43273939e-07f);
    p = fmaf(p, w, -3.5233877e-06f);
    p = fmaf(p, w, -4.39150654e-06f);
    p = fmaf(p, w, 0.00021858087f);
    p = fmaf(p, w, -0.00125372503f);
    p = fmaf(p, w, -0.00417768164f);
    p = fmaf(p, w, 0.246640727f);
    p = fmaf(p, w, 1.50140941f);
  } else {
    w = sqrtf(w) - 3.0f;
    p = -0.000200214257f;
    p = fmaf(p, w, 0.000100950558f);
    p = fmaf(p, w, 0.00134934322f);
    p = fmaf(p, w, -0.00367342844f);
    p = fmaf(p, w, 0.00573950773f);
    p = fmaf(p, w, -0.0076224613f);
    p = fmaf(p, w, 0.00943887047f);
    p = fmaf(p, w, 1.00167406f);
    p = fmaf(p, w, 2.83297682f);
  }
  return p * x;
}
__device__ __forceinline__ float bits_to_normal(uint32_t bits) {
  float f = __uint_as_float((bits >> 9) | 0x3F800000u) - 1.0f;
  const float lo = -0.99999994f;
  float u = fmaxf(lo, f * 2.0f + lo);
  return 1.41421356237f * erfinv_xla(u);
}

// ---------------------------------------------------------------------------
// bf16 helpers
// ---------------------------------------------------------------------------
__device__ __forceinline__ uint32_t pack_bf2(float a, float b) {
  uint32_t la = (uint32_t)__bfloat16_as_ushort(__float2bfloat16_rn(a));
  uint32_t hb = (uint32_t)__bfloat16_as_ushort(__float2bfloat16_rn(b));
  return la | (hb << 16);
}
__device__ __forceinline__ void split_pack(float a, float b,
                                           uint32_t& hi, uint32_t& lo) {
  __nv_bfloat16 ah = __float2bfloat16_rn(a), bh = __float2bfloat16_rn(b);
  hi = (uint32_t)__bfloat16_as_ushort(ah) |
       ((uint32_t)__bfloat16_as_ushort(bh) << 16);
  lo = pack_bf2(a - __bfloat162float(ah), b - __bfloat162float(bh));
}

__device__ __forceinline__ void mma_bf16(float (&d)[4], const uint32_t (&a)[4],
                                         const uint32_t (&b)[2]) {
  asm volatile(
      "mma.sync.aligned.m16n8k16.row.col.f32.bf16.bf16.f32 "
      "{%0,%1,%2,%3}, {%4,%5,%6,%7}, {%8,%9}, {%0,%1,%2,%3};"
      : "+f"(d[0]), "+f"(d[1]), "+f"(d[2]), "+f"(d[3])
      : "r"(a[0]), "r"(a[1]), "r"(a[2]), "r"(a[3]), "r"(b[0]), "r"(b[1]));
}

// ---------------------------------------------------------------------------
// Weight prep: one thread per (frag tile, lane); produces hi+lo b0,b1
// ---------------------------------------------------------------------------
__global__ void prep_weights(const float* __restrict__ W1,
                             const float* __restrict__ W2,
                             const float* __restrict__ W3) {
  int tid = blockIdx.x * 256 + threadIdx.x;
  int T = tid >> 5, lane = tid & 31;
  if (T >= 896) return;
  int g = lane >> 2, t = lane & 3;
  const float* W; int ldn, ni, ki, idx; uint32_t *dh, *dl;
  if (T < 256)      { ni = T >> 3;  ki = T & 7;  W = W1; ldn = 256; dh = g_w1f[0]; dl = g_w1f[1]; idx = T; }
  else if (T < 768) { int T2 = T - 256; ni = T2 >> 4; ki = T2 & 15; W = W2; ldn = 256; dh = g_w2f[0]; dl = g_w2f[1]; idx = T2; }
  else              { int T3 = T - 768; ni = T3 >> 4; ki = T3 & 15; W = W3; ldn = 64;  dh = g_w3f[0]; dl = g_w3f[1]; idx = T3; }
  int n  = ni * 8 + g;
  int k0 = ki * 16 + 2 * t;
  float w00 = W[(k0    ) * ldn + n], w01 = W[(k0 + 1) * ldn + n];
  float w10 = W[(k0 + 8) * ldn + n], w11 = W[(k0 + 9) * ldn + n];
  uint32_t h0, l0, h1, l1;
  split_pack(w00, w01, h0, l0);
  split_pack(w10, w11, h1, l1);
  int e = (idx * 32 + lane) * 2;
  dh[e] = h0; dh[e + 1] = h1;
  dl[e] = l0; dl[e + 1] = l1;
}

// ---------------------------------------------------------------------------
// Fragment GEMM phase: acc[MT][NJ][4] += A(frags smem) @ B(frags gmem)
// B loads chunked 4-wide in nj to bound live registers (128-reg cap).
// ---------------------------------------------------------------------------
template<int KT, int NJ, int MT>
__device__ __forceinline__ void gemm_frags(
    float (&acc)[MT][NJ][4],
    const char* __restrict__ aHi, const char* __restrict__ aLo,
    int mBase, int lane,
    const uint32_t* __restrict__ Bh, const uint32_t* __restrict__ Bl,
    int njBase) {
#pragma unroll
  for (int ki = 0; ki < KT; ++ki) {
    uint32_t ah[MT][4], al[MT][4];
#pragma unroll
    for (int mt = 0; mt < MT; ++mt) {
      uint4 vh = *(const uint4*)(aHi + (size_t)(((mBase + mt) * KT + ki) * 512 + lane * 16));
      ah[mt][0] = vh.x; ah[mt][1] = vh.y; ah[mt][2] = vh.z; ah[mt][3] = vh.w;
      uint4 vl = *(const uint4*)(aLo + (size_t)(((mBase + mt) * KT + ki) * 512 + lane * 16));
      al[mt][0] = vl.x; al[mt][1] = vl.y; al[mt][2] = vl.z; al[mt][3] = vl.w;
    }
#pragma unroll
    for (int jc = 0; jc < NJ; jc += 4) {
      constexpr int JW = (NJ < 4) ? NJ : 4;
      uint32_t bh[JW][2], bl[JW][2];
#pragma unroll
      for (int j = 0; j < JW; ++j) {
        uint2 vh = *(const uint2*)&Bh[(((njBase + jc + j) * KT + ki) * 32 + lane) * 2];
        bh[j][0] = vh.x; bh[j][1] = vh.y;
        uint2 vl = *(const uint2*)&Bl[(((njBase + jc + j) * KT + ki) * 32 + lane) * 2];
        bl[j][0] = vl.x; bl[j][1] = vl.y;
      }
#pragma unroll
      for (int mt = 0; mt < MT; ++mt)
#pragma unroll
        for (int j = 0; j < JW; ++j) {
          mma_bf16(acc[mt][jc + j], ah[mt], bh[j]);
          mma_bf16(acc[mt][jc + j], al[mt], bh[j]);
          mma_bf16(acc[mt][jc + j], ah[mt], bl[j]);
        }
    }
  }
}

// ---------------------------------------------------------------------------
// Fused SDE step, 512 threads (16 warps) per 128-row CTA.
// smem: actHi 0..32K, actLo 32K..64K, hHi 64K..128K, hLo 128K..192K
// ---------------------------------------------------------------------------
__global__ void __launch_bounds__(512, 1)
fused_step(const float* __restrict__ Xin, const float* __restrict__ X0,
           float* __restrict__ Xout,
           const float* __restrict__ b1, const float* __restrict__ w1s,
           const float* __restrict__ b2, const float* __restrict__ b3,
           float s, float cf, uint32_t rk0, uint32_t rk1) {
  extern __shared__ char sm[];
  char* actHi = sm;
  char* actLo = sm + 32768;
  char* hHi   = sm + 65536;
  char* hLo   = sm + 131072;

  const int tid  = threadIdx.x;
  const int wid  = tid >> 5;
  const int lane = tid & 31;
  const int g    = lane >> 2;
  const int t    = lane & 3;
  const int rowBase = blockIdx.x * 128;

  // ---- phase 0: stage A1 = [Xin | X0] as bf16 hi/lo fragments ----
#pragma unroll
  for (int it = 0; it < 4; ++it) {
    int tile = wid * 4 + it;              // 64 tiles: mi(8) x ki(8)
    int mi = tile >> 3, ki = tile & 7;
    const float* src = (ki < 4) ? Xin : X0;
    int kc = (ki & 3) * 16;
    const float* p0 = src + (size_t)(rowBase + mi * 16 + g) * DIM + kc;
    const float* p1 = p0 + 8 * DIM;
    float2 v00 = *(const float2*)(p0 + 2 * t);
    float2 v01 = *(const float2*)(p0 + 2 * t + 8);
    float2 v10 = *(const float2*)(p1 + 2 * t);
    float2 v11 = *(const float2*)(p1 + 2 * t + 8);
    uint32_t h0, l0, h1, l1, h2, l2, h3, l3;
    split_pack(v00.x, v00.y, h0, l0);
    split_pack(v10.x, v10.y, h1, l1);
    split_pack(v01.x, v01.y, h2, l2);
    split_pack(v11.x, v11.y, h3, l3);
    int off = (mi * 8 + ki) * 512 + lane * 16;
    *(uint4*)(actHi + off) = make_uint4(h0, h1, h2, h3);
    *(uint4*)(actLo + off) = make_uint4(l0, l1, l2, l3);
  }
  __syncthreads();

  const int mrow = wid >> 2, ncol = wid & 3;   // 4x4 warp grid, 32x64 tiles

  // ---- phase 1: h1 = relu(A1 @ W1' + s*w1s + b1) -> h frags ----
  {
    float acc[2][8][4];
#pragma unroll
    for (int a = 0; a < 2; ++a)
#pragma unroll
      for (int b = 0; b < 8; ++b)
#pragma unroll
        for (int c = 0; c < 4; ++c) acc[a][b][c] = 0.f;
    gemm_frags<8, 8, 2>(acc, actHi, actLo, mrow * 2, lane,
                        g_w1f[0], g_w1f[1], ncol * 8);
#pragma unroll
    for (int j = 0; j < 8; ++j) {
      int nj = ncol * 8 + j;
      int c0 = nj * 8 + 2 * t;
      float bb0 = b1[c0]     + s * w1s[c0];
      float bb1 = b1[c0 + 1] + s * w1s[c0 + 1];
#pragma unroll
      for (int mt = 0; mt < 2; ++mt) {
        int mi = mrow * 2 + mt;
        float v00 = fmaxf(acc[mt][j][0] + bb0, 0.f);
        float v01 = fmaxf(acc[mt][j][1] + bb1, 0.f);
        float v10 = fmaxf(acc[mt][j][2] + bb0, 0.f);
        float v11 = fmaxf(acc[mt][j][3] + bb1, 0.f);
        uint32_t h0, l0, h1, l1;
        split_pack(v00, v01, h0, l0);
        split_pack(v10, v11, h1, l1);
        int off = (mi * 16 + (nj >> 1)) * 512 + lane * 16 + (nj & 1) * 8;
        *(uint2*)(hHi + off) = make_uint2(h0, h1);
        *(uint2*)(hLo + off) = make_uint2(l0, l1);
      }
    }
  }
  __syncthreads();

  // ---- phase 2: h2 = relu(h1 @ W2' + b2) -> overwrite h frags ----
  {
    float acc[2][8][4];
#pragma unroll
    for (int a = 0; a < 2; ++a)
#pragma unroll
      for (int b = 0; b < 8; ++b)
#pragma unroll
        for (int c = 0; c < 4; ++c) acc[a][b][c] = 0.f;
    gemm_frags<16, 8, 2>(acc, hHi, hLo, mrow * 2, lane,
                         g_w2f[0], g_w2f[1], ncol * 8);
    __syncthreads();   // all warps done reading h1 before overwrite
#pragma unroll
    for (int j = 0; j < 8; ++j) {
      int nj = ncol * 8 + j;
      int c0 = nj * 8 + 2 * t;
      float bb0 = b2[c0];
      float bb1 = b2[c0 + 1];
#pragma unroll
      for (int mt = 0; mt < 2; ++mt) {
        int mi = mrow * 2 + mt;
        float v00 = fmaxf(acc[mt][j][0] + bb0, 0.f);
        float v01 = fmaxf(acc[mt][j][1] + bb1, 0.f);
        float v10 = fmaxf(acc[mt][j][2] + bb0, 0.f);
        float v11 = fmaxf(acc[mt][j][3] + bb1, 0.f);
        uint32_t h0, l0, h1, l1;
        split_pack(v00, v01, h0, l0);
        split_pack(v10, v11, h1, l1);
        int off = (mi * 16 + (nj >> 1)) * 512 + lane * 16 + (nj & 1) * 8;
        *(uint2*)(hHi + off) = make_uint2(h0, h1);
        *(uint2*)(hLo + off) = make_uint2(l0, l1);
      }
    }
  }
  __syncthreads();

  // ---- phase 3: bd = h2 @ W3' + b3, fused SDE update + threefry noise ----
  {
    const int mrow3 = wid >> 1, ncol3 = wid & 1;   // 8x2 warp grid, 16x32
    float acc[1][4][4];
#pragma unroll
    for (int b = 0; b < 4; ++b)
#pragma unroll
      for (int c = 0; c < 4; ++c) acc[0][b][c] = 0.f;
    gemm_frags<16, 4, 1>(acc, hHi, hLo, mrow3, lane,
                         g_w3f[0], g_w3f[1], ncol3 * 4);
#pragma unroll
    for (int j = 0; j < 4; ++j) {
      int nj = ncol3 * 4 + j;
      int c0 = nj * 8 + 2 * t;
      float bb0 = b3[c0], bb1 = b3[c0 + 1];
#pragma unroll
      for (int half = 0; half < 2; ++half) {
        int r = rowBase + mrow3 * 16 + g + half * 8;
        float bA = acc[0][j][half * 2 + 0] + bb0;
        float bB = acc[0][j][half * 2 + 1] + bb1;
        int i0 = r * DIM + c0;
        float2 Xo  = *(const float2*)(Xin + i0);
        float2 x0v = *(const float2*)(X0  + i0);
        uint32_t u0 = 0u, u1 = (uint32_t)i0;
        tf2x32(rk0, rk1, u0, u1);
        float e0 = bits_to_normal(u0 ^ u1);
        uint32_t w0 = 0u, w1 = (uint32_t)(i0 + 1);
        tf2x32(rk0, rk1, w0, w1);
        float e1 = bits_to_normal(w0 ^ w1);
        float d0 = bA + cf * (s * bA - Xo.x + x0v.x);
        float d1 = bB + cf * (s * bB - Xo.y + x0v.y);
        float2 o;
        o.x = Xo.x + 0.015625f * d0 + 0.125f * e0;
        o.y = Xo.y + 0.015625f * d1 + 0.125f * e1;
        *(float2*)(Xout + i0) = o;
      }
    }
  }
}

// ---------------------------------------------------------------------------
// Host
// ---------------------------------------------------------------------------
static inline void host_split2(uint32_t k0, uint32_t k1, uint32_t out[2][2]) {
  for (uint32_t j = 0; j < 2; j++) {
    uint32_t a = 0u, b = j;
    tf2x32(k0, k1, a, b);
    out[j][0] = a; out[j][1] = b;
  }
}

extern "C" void kernel_launch(void* const* d_in, const int* in_sizes, int n_in,
                              void* d_out, int out_size) {
  (void)in_sizes; (void)n_in; (void)out_size;
  const float* X0 = (const float*)d_in[0];
  const float* W1 = (const float*)d_in[1];   // [129, 256]
  const float* b1 = (const float*)d_in[2];
  const float* W2 = (const float*)d_in[3];   // [256, 256]
  const float* b2 = (const float*)d_in[4];
  const float* W3 = (const float*)d_in[5];   // [256, 64]
  const float* b3 = (const float*)d_in[6];
  float* out = (float*)d_out;                // [2, 65536, 64]

  const float* w1s = W1 + 128 * 256;         // s-feature row

  constexpr int SMEM = 196608;
  cudaFuncSetAttribute((const void*)fused_step,
                       cudaFuncAttributeMaxDynamicSharedMemorySize, SMEM);

  prep_weights<<<112, 256>>>(W1, W2, W3);

  uint32_t sk[2][2];
  host_split2(0u, 1u, sk);   // jax.random.key(1) -> 2 sample keys

  for (int smp = 0; smp < 2; ++smp) {
    uint32_t ks[2][2];
    host_split2(sk[smp][0], sk[smp][1], ks);
    uint32_t ke0 = ks[0][0], ke1 = ks[0][1];
    uint32_t kl0 = ks[1][0], kl1 = ks[1][1];
    float* X = out + (size_t)smp * NELEM;

    for (int n = 0; n < 64; ++n) {
      const float s = (float)n * 0.015625f;
      float cf = 0.0f;
      uint32_t nk0, nk1;
      const float* Xin;
      if (n == 0) {
        nk0 = ke0; nk1 = ke1; Xin = X0;
      } else {
        uint32_t kk[2][2];
        host_split2(kl0, kl1, kk);
        kl0 = kk[0][0]; kl1 = kk[0][1];
        nk0 = kk[1][0]; nk1 = kk[1][1];
        Xin = X;
        const float sg = 1.0f - s;
        cf = 0.5f * (1.0f - sg * sg) / (s * sg);
      }
      fused_step<<<NOBS / 128, 512, SMEM>>>(
          Xin, X0, X, b1, w1s, b2, b3, s, cf, nk0, nk1);
    }
  }
}

// round 9
// speedup vs baseline: 3.0164x; 1.2896x over previous
#include <cuda_runtime.h>
#include <cuda_bf16.h>
#include <cstdint>
#include <math.h>

#define NOBS   65536
#define DIM    64
#define NELEM  (NOBS * DIM)

// ---------------------------------------------------------------------------
// Weight fragment arrays (prepped once per launch): B-fragment order for
// mma.sync.m16n8k16: entry ((nj*KT + ki)*32 + lane)*2 + {0,1}
//   b0 = {W[k=ki*16+2t][n], W[k+1][n]},  b1 = {W[k+8][n], W[k+9][n]},  n = nj*8 + (lane>>2)
// plane 0 = bf16 hi, plane 1 = bf16 residual (lo)
// ---------------------------------------------------------------------------
__device__ uint32_t g_w1f[2][256 * 64];   // 32 nj x  8 ki tiles
__device__ uint32_t g_w2f[2][512 * 64];   // 32 nj x 16 ki
__device__ uint32_t g_w3f[2][128 * 64];   //  8 nj x 16 ki

// ---------------------------------------------------------------------------
// threefry2x32 (JAX partitionable, exact) — host + device
// ---------------------------------------------------------------------------
__host__ __device__ __forceinline__ void tf2x32(uint32_t k0, uint32_t k1,
                                                uint32_t& x0, uint32_t& x1) {
  uint32_t ks2 = k0 ^ k1 ^ 0x1BD11BDAu;
  x0 += k0; x1 += k1;
#define TFR(r) { x0 += x1; x1 = (x1 << (r)) | (x1 >> (32 - (r))); x1 ^= x0; }
  TFR(13) TFR(15) TFR(26) TFR(6)
  x0 += k1;  x1 += ks2 + 1u;
  TFR(17) TFR(29) TFR(16) TFR(24)
  x0 += ks2; x1 += k0 + 2u;
  TFR(13) TFR(15) TFR(26) TFR(6)
  x0 += k0;  x1 += k1 + 3u;
  TFR(17) TFR(29) TFR(16) TFR(24)
  x0 += k1;  x1 += ks2 + 4u;
  TFR(13) TFR(15) TFR(26) TFR(6)
  x0 += ks2; x1 += k0 + 5u;
#undef TFR
}

__device__ __forceinline__ float erfinv_xla(float x) {
  float w = -log1pf(-x * x);
  float p;
  if (w < 5.0f) {
    w -= 2.5f;
    p = 2.81022636e-08f;
    p = fmaf(p, w, 3.43273939e-07f);
    p = fmaf(p, w, -3.5233877e-06f);
    p = fmaf(p, w, -4.39150654e-06f);
    p = fmaf(p, w, 0.00021858087f);
    p = fmaf(p, w, -0.00125372503f);
    p = fmaf(p, w, -0.00417768164f);
    p = fmaf(p, w, 0.246640727f);
    p = fmaf(p, w, 1.50140941f);
  } else {
    w = sqrtf(w) - 3.0f;
    p = -0.000200214257f;
    p = fmaf(p, w, 0.000100950558f);
    p = fmaf(p, w, 0.00134934322f);
    p = fmaf(p, w, -0.00367342844f);
    p = fmaf(p, w, 0.00573950773f);
    p = fmaf(p, w, -0.0076224613f);
    p = fmaf(p, w, 0.00943887047f);
    p = fmaf(p, w, 1.00167406f);
    p = fmaf(p, w, 2.83297682f);
  }
  return p * x;
}
__device__ __forceinline__ float bits_to_normal(uint32_t bits) {
  float f = __uint_as_float((bits >> 9) | 0x3F800000u) - 1.0f;
  const float lo = -0.99999994f;
  float u = fmaxf(lo, f * 2.0f + lo);
  return 1.41421356237f * erfinv_xla(u);
}

// ---------------------------------------------------------------------------
// bf16 helpers
// ---------------------------------------------------------------------------
__device__ __forceinline__ uint32_t pack_bf2(float a, float b) {
  uint32_t la = (uint32_t)__bfloat16_as_ushort(__float2bfloat16_rn(a));
  uint32_t hb = (uint32_t)__bfloat16_as_ushort(__float2bfloat16_rn(b));
  return la | (hb << 16);
}
__device__ __forceinline__ void split_pack(float a, float b,
                                           uint32_t& hi, uint32_t& lo) {
  __nv_bfloat16 ah = __float2bfloat16_rn(a), bh = __float2bfloat16_rn(b);
  hi = (uint32_t)__bfloat16_as_ushort(ah) |
       ((uint32_t)__bfloat16_as_ushort(bh) << 16);
  lo = pack_bf2(a - __bfloat162float(ah), b - __bfloat162float(bh));
}

__device__ __forceinline__ void mma_bf16(float (&d)[4], const uint32_t (&a)[4],
                                         const uint32_t (&b)[2]) {
  asm volatile(
      "mma.sync.aligned.m16n8k16.row.col.f32.bf16.bf16.f32 "
      "{%0,%1,%2,%3}, {%4,%5,%6,%7}, {%8,%9}, {%0,%1,%2,%3};"
      : "+f"(d[0]), "+f"(d[1]), "+f"(d[2]), "+f"(d[3])
      : "r"(a[0]), "r"(a[1]), "r"(a[2]), "r"(a[3]), "r"(b[0]), "r"(b[1]));
}

// ---------------------------------------------------------------------------
// Weight prep: one thread per (frag tile, lane); produces hi+lo b0,b1
// ---------------------------------------------------------------------------
__global__ void prep_weights(const float* __restrict__ W1,
                             const float* __restrict__ W2,
                             const float* __restrict__ W3) {
  int tid = blockIdx.x * 256 + threadIdx.x;
  int T = tid >> 5, lane = tid & 31;
  if (T >= 896) return;
  int g = lane >> 2, t = lane & 3;
  const float* W; int ldn, ni, ki, idx; uint32_t *dh, *dl;
  if (T < 256)      { ni = T >> 3;  ki = T & 7;  W = W1; ldn = 256; dh = g_w1f[0]; dl = g_w1f[1]; idx = T; }
  else if (T < 768) { int T2 = T - 256; ni = T2 >> 4; ki = T2 & 15; W = W2; ldn = 256; dh = g_w2f[0]; dl = g_w2f[1]; idx = T2; }
  else              { int T3 = T - 768; ni = T3 >> 4; ki = T3 & 15; W = W3; ldn = 64;  dh = g_w3f[0]; dl = g_w3f[1]; idx = T3; }
  int n  = ni * 8 + g;
  int k0 = ki * 16 + 2 * t;
  float w00 = W[(k0    ) * ldn + n], w01 = W[(k0 + 1) * ldn + n];
  float w10 = W[(k0 + 8) * ldn + n], w11 = W[(k0 + 9) * ldn + n];
  uint32_t h0, l0, h1, l1;
  split_pack(w00, w01, h0, l0);
  split_pack(w10, w11, h1, l1);
  int e = (idx * 32 + lane) * 2;
  dh[e] = h0; dh[e + 1] = h1;
  dl[e] = l0; dl[e + 1] = l1;
}

// ---------------------------------------------------------------------------
// Fragment GEMM phase: acc[MT][NJ][4] += A(frags smem) @ B(frags gmem)
// B loads chunked 4-wide in nj to bound live registers (128-reg cap).
// ---------------------------------------------------------------------------
template<int KT, int NJ, int MT>
__device__ __forceinline__ void gemm_frags(
    float (&acc)[MT][NJ][4],
    const char* __restrict__ aHi, const char* __restrict__ aLo,
    int mBase, int lane,
    const uint32_t* __restrict__ Bh, const uint32_t* __restrict__ Bl,
    int njBase) {
#pragma unroll
  for (int ki = 0; ki < KT; ++ki) {
    uint32_t ah[MT][4], al[MT][4];
#pragma unroll
    for (int mt = 0; mt < MT; ++mt) {
      uint4 vh = *(const uint4*)(aHi + (size_t)(((mBase + mt) * KT + ki) * 512 + lane * 16));
      ah[mt][0] = vh.x; ah[mt][1] = vh.y; ah[mt][2] = vh.z; ah[mt][3] = vh.w;
      uint4 vl = *(const uint4*)(aLo + (size_t)(((mBase + mt) * KT + ki) * 512 + lane * 16));
      al[mt][0] = vl.x; al[mt][1] = vl.y; al[mt][2] = vl.z; al[mt][3] = vl.w;
    }
#pragma unroll
    for (int jc = 0; jc < NJ; jc += 4) {
      constexpr int JW = (NJ < 4) ? NJ : 4;
      uint32_t bh[JW][2], bl[JW][2];
#pragma unroll
      for (int j = 0; j < JW; ++j) {
        uint2 vh = *(const uint2*)&Bh[(((njBase + jc + j) * KT + ki) * 32 + lane) * 2];
        bh[j][0] = vh.x; bh[j][1] = vh.y;
        uint2 vl = *(const uint2*)&Bl[(((njBase + jc + j) * KT + ki) * 32 + lane) * 2];
        bl[j][0] = vl.x; bl[j][1] = vl.y;
      }
#pragma unroll
      for (int mt = 0; mt < MT; ++mt)
#pragma unroll
        for (int j = 0; j < JW; ++j) {
          mma_bf16(acc[mt][jc + j], ah[mt], bh[j]);
          mma_bf16(acc[mt][jc + j], al[mt], bh[j]);
          mma_bf16(acc[mt][jc + j], ah[mt], bl[j]);
        }
    }
  }
}

// ---------------------------------------------------------------------------
// Fused SDE step: 64-row CTA, 256 threads (8 warps), 96KB smem -> 2 CTAs/SM.
// smem: actHi 0..16K, actLo 16K..32K, hHi 32K..64K, hLo 64K..96K
// ---------------------------------------------------------------------------
__global__ void __launch_bounds__(256, 2)
fused_step(const float* __restrict__ Xin, const float* __restrict__ X0,
           float* __restrict__ Xout,
           const float* __restrict__ b1, const float* __restrict__ w1s,
           const float* __restrict__ b2, const float* __restrict__ b3,
           float s, float cf, uint32_t rk0, uint32_t rk1) {
  extern __shared__ char sm[];
  char* actHi = sm;
  char* actLo = sm + 16384;
  char* hHi   = sm + 32768;
  char* hLo   = sm + 65536;

  const int tid  = threadIdx.x;
  const int wid  = tid >> 5;
  const int lane = tid & 31;
  const int g    = lane >> 2;
  const int t    = lane & 3;
  const int rowBase = blockIdx.x * 64;

  // ---- phase 0: stage A1 = [Xin | X0] as bf16 hi/lo fragments ----
  // 32 tiles: mi(4) x ki(8); 4 tiles per warp
#pragma unroll
  for (int it = 0; it < 4; ++it) {
    int tile = wid * 4 + it;
    int mi = tile >> 3, ki = tile & 7;
    const float* src = (ki < 4) ? Xin : X0;
    int kc = (ki & 3) * 16;
    const float* p0 = src + (size_t)(rowBase + mi * 16 + g) * DIM + kc;
    const float* p1 = p0 + 8 * DIM;
    float2 v00 = *(const float2*)(p0 + 2 * t);
    float2 v01 = *(const float2*)(p0 + 2 * t + 8);
    float2 v10 = *(const float2*)(p1 + 2 * t);
    float2 v11 = *(const float2*)(p1 + 2 * t + 8);
    uint32_t h0, l0, h1, l1, h2, l2, h3, l3;
    split_pack(v00.x, v00.y, h0, l0);
    split_pack(v10.x, v10.y, h1, l1);
    split_pack(v01.x, v01.y, h2, l2);
    split_pack(v11.x, v11.y, h3, l3);
    int off = (mi * 8 + ki) * 512 + lane * 16;
    *(uint4*)(actHi + off) = make_uint4(h0, h1, h2, h3);
    *(uint4*)(actLo + off) = make_uint4(l0, l1, l2, l3);
  }
  __syncthreads();

  const int mrow = wid >> 2, ncol = wid & 3;   // 2x4 warp grid, 32x64 tiles

  // ---- phase 1: h1 = relu(A1 @ W1' + s*w1s + b1) -> h frags ----
  {
    float acc[2][8][4];
#pragma unroll
    for (int a = 0; a < 2; ++a)
#pragma unroll
      for (int b = 0; b < 8; ++b)
#pragma unroll
        for (int c = 0; c < 4; ++c) acc[a][b][c] = 0.f;
    gemm_frags<8, 8, 2>(acc, actHi, actLo, mrow * 2, lane,
                        g_w1f[0], g_w1f[1], ncol * 8);
#pragma unroll
    for (int j = 0; j < 8; ++j) {
      int nj = ncol * 8 + j;
      int c0 = nj * 8 + 2 * t;
      float bb0 = b1[c0]     + s * w1s[c0];
      float bb1 = b1[c0 + 1] + s * w1s[c0 + 1];
#pragma unroll
      for (int mt = 0; mt < 2; ++mt) {
        int mi = mrow * 2 + mt;
        float v00 = fmaxf(acc[mt][j][0] + bb0, 0.f);
        float v01 = fmaxf(acc[mt][j][1] + bb1, 0.f);
        float v10 = fmaxf(acc[mt][j][2] + bb0, 0.f);
        float v11 = fmaxf(acc[mt][j][3] + bb1, 0.f);
        uint32_t h0, l0, h1, l1;
        split_pack(v00, v01, h0, l0);
        split_pack(v10, v11, h1, l1);
        int off = (mi * 16 + (nj >> 1)) * 512 + lane * 16 + (nj & 1) * 8;
        *(uint2*)(hHi + off) = make_uint2(h0, h1);
        *(uint2*)(hLo + off) = make_uint2(l0, l1);
      }
    }
  }
  __syncthreads();

  // ---- phase 2: h2 = relu(h1 @ W2' + b2) -> overwrite h frags ----
  {
    float acc[2][8][4];
#pragma unroll
    for (int a = 0; a < 2; ++a)
#pragma unroll
      for (int b = 0; b < 8; ++b)
#pragma unroll
        for (int c = 0; c < 4; ++c) acc[a][b][c] = 0.f;
    gemm_frags<16, 8, 2>(acc, hHi, hLo, mrow * 2, lane,
                         g_w2f[0], g_w2f[1], ncol * 8);
    __syncthreads();   // all warps done reading h1 before overwrite
#pragma unroll
    for (int j = 0; j < 8; ++j) {
      int nj = ncol * 8 + j;
      int c0 = nj * 8 + 2 * t;
      float bb0 = b2[c0];
      float bb1 = b2[c0 + 1];
#pragma unroll
      for (int mt = 0; mt < 2; ++mt) {
        int mi = mrow * 2 + mt;
        float v00 = fmaxf(acc[mt][j][0] + bb0, 0.f);
        float v01 = fmaxf(acc[mt][j][1] + bb1, 0.f);
        float v10 = fmaxf(acc[mt][j][2] + bb0, 0.f);
        float v11 = fmaxf(acc[mt][j][3] + bb1, 0.f);
        uint32_t h0, l0, h1, l1;
        split_pack(v00, v01, h0, l0);
        split_pack(v10, v11, h1, l1);
        int off = (mi * 16 + (nj >> 1)) * 512 + lane * 16 + (nj & 1) * 8;
        *(uint2*)(hHi + off) = make_uint2(h0, h1);
        *(uint2*)(hLo + off) = make_uint2(l0, l1);
      }
    }
  }
  __syncthreads();

  // ---- phase 3: bd = h2 @ W3' + b3, fused SDE update + threefry noise ----
  {
    const int mrow3 = wid >> 1, ncol3 = wid & 1;   // 4x2 warp grid, 16x32
    float acc[1][4][4];
#pragma unroll
    for (int b = 0; b < 4; ++b)
#pragma unroll
      for (int c = 0; c < 4; ++c) acc[0][b][c] = 0.f;
    gemm_frags<16, 4, 1>(acc, hHi, hLo, mrow3, lane,
                         g_w3f[0], g_w3f[1], ncol3 * 4);
#pragma unroll
    for (int j = 0; j < 4; ++j) {
      int nj = ncol3 * 4 + j;
      int c0 = nj * 8 + 2 * t;
      float bb0 = b3[c0], bb1 = b3[c0 + 1];
#pragma unroll
      for (int half = 0; half < 2; ++half) {
        int r = rowBase + mrow3 * 16 + g + half * 8;
        float bA = acc[0][j][half * 2 + 0] + bb0;
        float bB = acc[0][j][half * 2 + 1] + bb1;
        int i0 = r * DIM + c0;
        float2 Xo  = *(const float2*)(Xin + i0);
        float2 x0v = *(const float2*)(X0  + i0);
        uint32_t u0 = 0u, u1 = (uint32_t)i0;
        tf2x32(rk0, rk1, u0, u1);
        float e0 = bits_to_normal(u0 ^ u1);
        uint32_t w0 = 0u, w1 = (uint32_t)(i0 + 1);
        tf2x32(rk0, rk1, w0, w1);
        float e1 = bits_to_normal(w0 ^ w1);
        float d0 = bA + cf * (s * bA - Xo.x + x0v.x);
        float d1 = bB + cf * (s * bB - Xo.y + x0v.y);
        float2 o;
        o.x = Xo.x + 0.015625f * d0 + 0.125f * e0;
        o.y = Xo.y + 0.015625f * d1 + 0.125f * e1;
        *(float2*)(Xout + i0) = o;
      }
    }
  }
}

// ---------------------------------------------------------------------------
// Host
// ---------------------------------------------------------------------------
static inline void host_split2(uint32_t k0, uint32_t k1, uint32_t out[2][2]) {
  for (uint32_t j = 0; j < 2; j++) {
    uint32_t a = 0u, b = j;
    tf2x32(k0, k1, a, b);
    out[j][0] = a; out[j][1] = b;
  }
}

extern "C" void kernel_launch(void* const* d_in, const int* in_sizes, int n_in,
                              void* d_out, int out_size) {
  (void)in_sizes; (void)n_in; (void)out_size;
  const float* X0 = (const float*)d_in[0];
  const float* W1 = (const float*)d_in[1];   // [129, 256]
  const float* b1 = (const float*)d_in[2];
  const float* W2 = (const float*)d_in[3];   // [256, 256]
  const float* b2 = (const float*)d_in[4];
  const float* W3 = (const float*)d_in[5];   // [256, 64]
  const float* b3 = (const float*)d_in[6];
  float* out = (float*)d_out;                // [2, 65536, 64]

  const float* w1s = W1 + 128 * 256;         // s-feature row

  constexpr int SMEM = 98304;                // 96KB -> 2 CTAs/SM
  cudaFuncSetAttribute((const void*)fused_step,
                       cudaFuncAttributeMaxDynamicSharedMemorySize, SMEM);

  prep_weights<<<112, 256>>>(W1, W2, W3);

  uint32_t sk[2][2];
  host_split2(0u, 1u, sk);   // jax.random.key(1) -> 2 sample keys

  for (int smp = 0; smp < 2; ++smp) {
    uint32_t ks[2][2];
    host_split2(sk[smp][0], sk[smp][1], ks);
    uint32_t ke0 = ks[0][0], ke1 = ks[0][1];
    uint32_t kl0 = ks[1][0], kl1 = ks[1][1];
    float* X = out + (size_t)smp * NELEM;

    for (int n = 0; n < 64; ++n) {
      const float s = (float)n * 0.015625f;
      float cf = 0.0f;
      uint32_t nk0, nk1;
      const float* Xin;
      if (n == 0) {
        nk0 = ke0; nk1 = ke1; Xin = X0;
      } else {
        uint32_t kk[2][2];
        host_split2(kl0, kl1, kk);
        kl0 = kk[0][0]; kl1 = kk[0][1];
        nk0 = kk[1][0]; nk1 = kk[1][1];
        Xin = X;
        const float sg = 1.0f - s;
        cf = 0.5f * (1.0f - sg * sg) / (s * sg);
      }
      fused_step<<<NOBS / 64, 256, SMEM>>>(
          Xin, X0, X, b1, w1s, b2, b3, s, cf, nk0, nk1);
    }
  }
}

// round 10
// speedup vs baseline: 3.1068x; 1.0300x over previous
#include <cuda_runtime.h>
#include <cuda_bf16.h>
#include <cstdint>
#include <math.h>

#define NOBS   65536
#define DIM    64
#define NELEM  (NOBS * DIM)

// ---------------------------------------------------------------------------
// Weight fragments, interleaved: one uint4 = {b0_hi, b1_hi, b0_lo, b1_lo}
// entry (nj*KT + ki)*32 + lane, for mma.sync.m16n8k16 B-fragment order:
//   b0 = {W[k=ki*16+2t][n], W[k+1][n]}, b1 = {W[k+8][n], W[k+9][n]}, n = nj*8+(lane>>2)
// ---------------------------------------------------------------------------
__device__ uint4 g_w1f[256 * 32];   // 32 nj x  8 ki
__device__ uint4 g_w2f[512 * 32];   // 32 nj x 16 ki
__device__ uint4 g_w3f[128 * 32];   //  8 nj x 16 ki

// ---------------------------------------------------------------------------
// threefry2x32 (JAX partitionable, exact)
// ---------------------------------------------------------------------------
__host__ __device__ __forceinline__ void tf2x32(uint32_t k0, uint32_t k1,
                                                uint32_t& x0, uint32_t& x1) {
  uint32_t ks2 = k0 ^ k1 ^ 0x1BD11BDAu;
  x0 += k0; x1 += k1;
#define TFR(r) { x0 += x1; x1 = (x1 << (r)) | (x1 >> (32 - (r))); x1 ^= x0; }
  TFR(13) TFR(15) TFR(26) TFR(6)
  x0 += k1;  x1 += ks2 + 1u;
  TFR(17) TFR(29) TFR(16) TFR(24)
  x0 += ks2; x1 += k0 + 2u;
  TFR(13) TFR(15) TFR(26) TFR(6)
  x0 += k0;  x1 += k1 + 3u;
  TFR(17) TFR(29) TFR(16) TFR(24)
  x0 += k1;  x1 += ks2 + 4u;
  TFR(13) TFR(15) TFR(26) TFR(6)
  x0 += ks2; x1 += k0 + 5u;
#undef TFR
}

__device__ __forceinline__ void dev_split2(uint32_t k0, uint32_t k1,
                                           uint32_t out[2][2]) {
#pragma unroll
  for (uint32_t j = 0; j < 2; j++) {
    uint32_t a = 0u, b = j;
    tf2x32(k0, k1, a, b);
    out[j][0] = a; out[j][1] = b;
  }
}

__device__ __forceinline__ float erfinv_xla(float x) {
  float w = -log1pf(-x * x);
  float p;
  if (w < 5.0f) {
    w -= 2.5f;
    p = 2.81022636e-08f;
    p = fmaf(p, w, 3.43273939e-07f);
    p = fmaf(p, w, -3.5233877e-06f);
    p = fmaf(p, w, -4.39150654e-06f);
    p = fmaf(p, w, 0.00021858087f);
    p = fmaf(p, w, -0.00125372503f);
    p = fmaf(p, w, -0.00417768164f);
    p = fmaf(p, w, 0.246640727f);
    p = fmaf(p, w, 1.50140941f);
  } else {
    w = sqrtf(w) - 3.0f;
    p = -0.000200214257f;
    p = fmaf(p, w, 0.000100950558f);
    p = fmaf(p, w, 0.00134934322f);
    p = fmaf(p, w, -0.00367342844f);
    p = fmaf(p, w, 0.00573950773f);
    p = fmaf(p, w, -0.0076224613f);
    p = fmaf(p, w, 0.00943887047f);
    p = fmaf(p, w, 1.00167406f);
    p = fmaf(p, w, 2.83297682f);
  }
  return p * x;
}
__device__ __forceinline__ float bits_to_normal(uint32_t bits) {
  float f = __uint_as_float((bits >> 9) | 0x3F800000u) - 1.0f;
  const float lo = -0.99999994f;
  float u = fmaxf(lo, f * 2.0f + lo);
  return 1.41421356237f * erfinv_xla(u);
}

// ---------------------------------------------------------------------------
// bf16 helpers
// ---------------------------------------------------------------------------
__device__ __forceinline__ uint32_t pack_bf2(float a, float b) {
  uint32_t la = (uint32_t)__bfloat16_as_ushort(__float2bfloat16_rn(a));
  uint32_t hb = (uint32_t)__bfloat16_as_ushort(__float2bfloat16_rn(b));
  return la | (hb << 16);
}
__device__ __forceinline__ void split_pack(float a, float b,
                                           uint32_t& hi, uint32_t& lo) {
  __nv_bfloat16 ah = __float2bfloat16_rn(a), bh = __float2bfloat16_rn(b);
  hi = (uint32_t)__bfloat16_as_ushort(ah) |
       ((uint32_t)__bfloat16_as_ushort(bh) << 16);
  lo = pack_bf2(a - __bfloat162float(ah), b - __bfloat162float(bh));
}

__device__ __forceinline__ void mma_bf16(float (&d)[4], const uint32_t (&a)[4],
                                         uint32_t b0, uint32_t b1) {
  asm volatile(
      "mma.sync.aligned.m16n8k16.row.col.f32.bf16.bf16.f32 "
      "{%0,%1,%2,%3}, {%4,%5,%6,%7}, {%8,%9}, {%0,%1,%2,%3};"
      : "+f"(d[0]), "+f"(d[1]), "+f"(d[2]), "+f"(d[3])
      : "r"(a[0]), "r"(a[1]), "r"(a[2]), "r"(a[3]), "r"(b0), "r"(b1));
}

// ---------------------------------------------------------------------------
// Weight prep
// ---------------------------------------------------------------------------
__global__ void prep_weights(const float* __restrict__ W1,
                             const float* __restrict__ W2,
                             const float* __restrict__ W3) {
  int tid = blockIdx.x * 256 + threadIdx.x;
  int T = tid >> 5, lane = tid & 31;
  if (T >= 896) return;
  int g = lane >> 2, t = lane & 3;
  const float* W; int ldn, ni, ki, idx; uint4* dst;
  if (T < 256)      { ni = T >> 3;  ki = T & 7;  W = W1; ldn = 256; dst = g_w1f; idx = T; }
  else if (T < 768) { int T2 = T - 256; ni = T2 >> 4; ki = T2 & 15; W = W2; ldn = 256; dst = g_w2f; idx = T2; }
  else              { int T3 = T - 768; ni = T3 >> 4; ki = T3 & 15; W = W3; ldn = 64;  dst = g_w3f; idx = T3; }
  int n  = ni * 8 + g;
  int k0 = ki * 16 + 2 * t;
  float w00 = W[(k0    ) * ldn + n], w01 = W[(k0 + 1) * ldn + n];
  float w10 = W[(k0 + 8) * ldn + n], w11 = W[(k0 + 9) * ldn + n];
  uint32_t h0, l0, h1, l1;
  split_pack(w00, w01, h0, l0);
  split_pack(w10, w11, h1, l1);
  dst[idx * 32 + lane] = make_uint4(h0, h1, l0, l1);
}

// ---------------------------------------------------------------------------
// Fragment GEMM phase: acc[MT][NJ][4] += A(frags smem) @ B(uint4 frags gmem)
// ---------------------------------------------------------------------------
template<int KT, int NJ, int MT>
__device__ __forceinline__ void gemm_frags(
    float (&acc)[MT][NJ][4],
    const char* __restrict__ aHi, const char* __restrict__ aLo,
    int mBase, int lane,
    const uint4* __restrict__ B, int njBase) {
#pragma unroll
  for (int ki = 0; ki < KT; ++ki) {
    uint32_t ah[MT][4], al[MT][4];
#pragma unroll
    for (int mt = 0; mt < MT; ++mt) {
      uint4 vh = *(const uint4*)(aHi + (((mBase + mt) * KT + ki) * 512 + lane * 16));
      ah[mt][0] = vh.x; ah[mt][1] = vh.y; ah[mt][2] = vh.z; ah[mt][3] = vh.w;
      uint4 vl = *(const uint4*)(aLo + (((mBase + mt) * KT + ki) * 512 + lane * 16));
      al[mt][0] = vl.x; al[mt][1] = vl.y; al[mt][2] = vl.z; al[mt][3] = vl.w;
    }
#pragma unroll
    for (int jc = 0; jc < NJ; jc += 4) {
      constexpr int JW = (NJ < 4) ? NJ : 4;
      uint4 bv[JW];
#pragma unroll
      for (int j = 0; j < JW; ++j)
        bv[j] = B[((njBase + jc + j) * KT + ki) * 32 + lane];
#pragma unroll
      for (int mt = 0; mt < MT; ++mt)
#pragma unroll
        for (int j = 0; j < JW; ++j) {
          mma_bf16(acc[mt][jc + j], ah[mt], bv[j].x, bv[j].y);
          mma_bf16(acc[mt][jc + j], al[mt], bv[j].x, bv[j].y);
          mma_bf16(acc[mt][jc + j], ah[mt], bv[j].z, bv[j].w);
        }
    }
  }
}

// ---------------------------------------------------------------------------
// Persistent fused sampler: one CTA owns 64 rows for all 64 steps.
// smem: actHi 0..16K, actLo 16K..32K, hHi 32K..64K, hLo 64K..96K,
//       Xbuf 96K.. (64 rows x 66 f32, padded stride) -> total 115200 B
// ---------------------------------------------------------------------------
#define XSTRIDE 66

__global__ void __launch_bounds__(256, 2)
persist_sde(const float* __restrict__ X0g, float* __restrict__ out,
            const float* __restrict__ b1, const float* __restrict__ w1s,
            const float* __restrict__ b2, const float* __restrict__ b3) {
  extern __shared__ char sm[];
  char*  actHi = sm;
  char*  actLo = sm + 16384;
  char*  hHi   = sm + 32768;
  char*  hLo   = sm + 65536;
  float* Xbuf  = (float*)(sm + 98304);

  const int tid  = threadIdx.x;
  const int wid  = tid >> 5;
  const int lane = tid & 31;
  const int g    = lane >> 2;
  const int t    = lane & 3;
  const int sample  = blockIdx.x >> 10;
  const int rowBase = (blockIdx.x & 1023) * 64;
  float* outp = out + (size_t)sample * NELEM;

  // ---- per-sample key chain: key(1) -> split -> sample key -> (ke, kl) ----
  uint32_t sk[2][2];
  dev_split2(0u, 1u, sk);
  uint32_t ks[2][2];
  dev_split2(sk[sample][0], sk[sample][1], ks);
  uint32_t ke0 = ks[0][0], ke1 = ks[0][1];
  uint32_t kl0 = ks[1][0], kl1 = ks[1][1];

  // ---- stage full A (Xin=X0 | X0) frags once: 32 tiles mi(4) x ki(8) ----
#pragma unroll
  for (int it = 0; it < 4; ++it) {
    int tile = wid * 4 + it;
    int mi = tile >> 3, ki = tile & 7;
    int kc = (ki & 3) * 16;
    const float* p0 = X0g + (size_t)(rowBase + mi * 16 + g) * DIM + kc;
    const float* p1 = p0 + 8 * DIM;
    float2 v00 = *(const float2*)(p0 + 2 * t);
    float2 v01 = *(const float2*)(p0 + 2 * t + 8);
    float2 v10 = *(const float2*)(p1 + 2 * t);
    float2 v11 = *(const float2*)(p1 + 2 * t + 8);
    uint32_t h0, l0, h1, l1, h2, l2, h3, l3;
    split_pack(v00.x, v00.y, h0, l0);
    split_pack(v10.x, v10.y, h1, l1);
    split_pack(v01.x, v01.y, h2, l2);
    split_pack(v11.x, v11.y, h3, l3);
    int off = (mi * 8 + ki) * 512 + lane * 16;
    *(uint4*)(actHi + off) = make_uint4(h0, h1, h2, h3);
    *(uint4*)(actLo + off) = make_uint4(l0, l1, l2, l3);
  }
  __syncthreads();

  const int mrow = wid >> 2, ncol = wid & 3;     // 2x4 warp grid (GEMM1/2)
  const int mrow3 = wid >> 1, ncol3 = wid & 1;   // 4x2 warp grid (GEMM3)

#pragma unroll 1
  for (int n = 0; n < 64; ++n) {
    const float s = (float)n * 0.015625f;
    float cf = 0.0f;
    uint32_t nk0, nk1;
    if (n == 0) {
      nk0 = ke0; nk1 = ke1;
    } else {
      uint32_t kk[2][2];
      dev_split2(kl0, kl1, kk);
      kl0 = kk[0][0]; kl1 = kk[0][1];
      nk0 = kk[1][0]; nk1 = kk[1][1];
      const float sg = 1.0f - s;
      cf = 0.5f * (1.0f - sg * sg) / (s * sg);

      // ---- phase 0 (n>=1): restage Xin frags (ki 0..3) from Xbuf ----
#pragma unroll
      for (int it = 0; it < 2; ++it) {
        int tile = wid * 2 + it;          // 16 tiles: mi(4) x ki(4)
        int mi = tile >> 2, ki = tile & 3;
        int kc = ki * 16;
        const float* p0 = Xbuf + (mi * 16 + g) * XSTRIDE + kc;
        const float* p1 = p0 + 8 * XSTRIDE;
        float2 v00 = *(const float2*)(p0 + 2 * t);
        float2 v01 = *(const float2*)(p0 + 2 * t + 8);
        float2 v10 = *(const float2*)(p1 + 2 * t);
        float2 v11 = *(const float2*)(p1 + 2 * t + 8);
        uint32_t h0, l0, h1, l1, h2, l2, h3, l3;
        split_pack(v00.x, v00.y, h0, l0);
        split_pack(v10.x, v10.y, h1, l1);
        split_pack(v01.x, v01.y, h2, l2);
        split_pack(v11.x, v11.y, h3, l3);
        int off = (mi * 8 + ki) * 512 + lane * 16;
        *(uint4*)(actHi + off) = make_uint4(h0, h1, h2, h3);
        *(uint4*)(actLo + off) = make_uint4(l0, l1, l2, l3);
      }
      __syncthreads();
    }

    // ---- phase 1: h1 = relu(A1 @ W1' + s*w1s + b1) ----
    {
      float acc[2][8][4];
#pragma unroll
      for (int a = 0; a < 2; ++a)
#pragma unroll
        for (int b = 0; b < 8; ++b)
#pragma unroll
          for (int c = 0; c < 4; ++c) acc[a][b][c] = 0.f;
      gemm_frags<8, 8, 2>(acc, actHi, actLo, mrow * 2, lane, g_w1f, ncol * 8);
#pragma unroll
      for (int j = 0; j < 8; ++j) {
        int nj = ncol * 8 + j;
        int c0 = nj * 8 + 2 * t;
        float bb0 = b1[c0]     + s * w1s[c0];
        float bb1 = b1[c0 + 1] + s * w1s[c0 + 1];
#pragma unroll
        for (int mt = 0; mt < 2; ++mt) {
          int mi = mrow * 2 + mt;
          float v00 = fmaxf(acc[mt][j][0] + bb0, 0.f);
          float v01 = fmaxf(acc[mt][j][1] + bb1, 0.f);
          float v10 = fmaxf(acc[mt][j][2] + bb0, 0.f);
          float v11 = fmaxf(acc[mt][j][3] + bb1, 0.f);
          uint32_t h0, l0, h1, l1;
          split_pack(v00, v01, h0, l0);
          split_pack(v10, v11, h1, l1);
          int off = (mi * 16 + (nj >> 1)) * 512 + lane * 16 + (nj & 1) * 8;
          *(uint2*)(hHi + off) = make_uint2(h0, h1);
          *(uint2*)(hLo + off) = make_uint2(l0, l1);
        }
      }
    }
    __syncthreads();

    // ---- phase 2: h2 = relu(h1 @ W2' + b2), overwrite h ----
    {
      float acc[2][8][4];
#pragma unroll
      for (int a = 0; a < 2; ++a)
#pragma unroll
        for (int b = 0; b < 8; ++b)
#pragma unroll
          for (int c = 0; c < 4; ++c) acc[a][b][c] = 0.f;
      gemm_frags<16, 8, 2>(acc, hHi, hLo, mrow * 2, lane, g_w2f, ncol * 8);
      __syncthreads();
#pragma unroll
      for (int j = 0; j < 8; ++j) {
        int nj = ncol * 8 + j;
        int c0 = nj * 8 + 2 * t;
        float bb0 = b2[c0];
        float bb1 = b2[c0 + 1];
#pragma unroll
        for (int mt = 0; mt < 2; ++mt) {
          int mi = mrow * 2 + mt;
          float v00 = fmaxf(acc[mt][j][0] + bb0, 0.f);
          float v01 = fmaxf(acc[mt][j][1] + bb1, 0.f);
          float v10 = fmaxf(acc[mt][j][2] + bb0, 0.f);
          float v11 = fmaxf(acc[mt][j][3] + bb1, 0.f);
          uint32_t h0, l0, h1, l1;
          split_pack(v00, v01, h0, l0);
          split_pack(v10, v11, h1, l1);
          int off = (mi * 16 + (nj >> 1)) * 512 + lane * 16 + (nj & 1) * 8;
          *(uint2*)(hHi + off) = make_uint2(h0, h1);
          *(uint2*)(hLo + off) = make_uint2(l0, l1);
        }
      }
    }
    __syncthreads();

    // ---- phase 3: bd = h2 @ W3' + b3; SDE update + threefry; X -> Xbuf ----
    {
      float acc[1][4][4];
#pragma unroll
      for (int b = 0; b < 4; ++b)
#pragma unroll
        for (int c = 0; c < 4; ++c) acc[0][b][c] = 0.f;
      gemm_frags<16, 4, 1>(acc, hHi, hLo, mrow3, lane, g_w3f, ncol3 * 4);
#pragma unroll
      for (int j = 0; j < 4; ++j) {
        int nj = ncol3 * 4 + j;
        int c0 = nj * 8 + 2 * t;
        float bb0 = b3[c0], bb1 = b3[c0 + 1];
#pragma unroll
        for (int half = 0; half < 2; ++half) {
          int rl = mrow3 * 16 + g + half * 8;     // row within tile
          int r  = rowBase + rl;                  // global row
          float bA = acc[0][j][half * 2 + 0] + bb0;
          float bB = acc[0][j][half * 2 + 1] + bb1;
          int i0 = r * DIM + c0;
          float2 x0v = *(const float2*)(X0g + i0);
          float2 Xo;
          if (n == 0) Xo = x0v;
          else        Xo = *(const float2*)&Xbuf[rl * XSTRIDE + c0];
          uint32_t u0 = 0u, u1 = (uint32_t)i0;
          tf2x32(nk0, nk1, u0, u1);
          float e0 = bits_to_normal(u0 ^ u1);
          uint32_t w0 = 0u, w1 = (uint32_t)(i0 + 1);
          tf2x32(nk0, nk1, w0, w1);
          float e1 = bits_to_normal(w0 ^ w1);
          float d0 = bA + cf * (s * bA - Xo.x + x0v.x);
          float d1 = bB + cf * (s * bB - Xo.y + x0v.y);
          float2 o;
          o.x = Xo.x + 0.015625f * d0 + 0.125f * e0;
          o.y = Xo.y + 0.015625f * d1 + 0.125f * e1;
          *(float2*)&Xbuf[rl * XSTRIDE + c0] = o;
          if (n == 63) *(float2*)(outp + i0) = o;
        }
      }
    }
    __syncthreads();   // Xbuf/h hazard barrier before next step
  }
}

// ---------------------------------------------------------------------------
// Host
// ---------------------------------------------------------------------------
extern "C" void kernel_launch(void* const* d_in, const int* in_sizes, int n_in,
                              void* d_out, int out_size) {
  (void)in_sizes; (void)n_in; (void)out_size;
  const float* X0 = (const float*)d_in[0];
  const float* W1 = (const float*)d_in[1];   // [129, 256]
  const float* b1 = (const float*)d_in[2];
  const float* W2 = (const float*)d_in[3];   // [256, 256]
  const float* b2 = (const float*)d_in[4];
  const float* W3 = (const float*)d_in[5];   // [256, 64]
  const float* b3 = (const float*)d_in[6];
  float* out = (float*)d_out;                // [2, 65536, 64]

  const float* w1s = W1 + 128 * 256;         // s-feature row

  constexpr int SMEM = 98304 + 64 * XSTRIDE * 4;   // 115200 B
  cudaFuncSetAttribute((const void*)persist_sde,
                       cudaFuncAttributeMaxDynamicSharedMemorySize, SMEM);

  prep_weights<<<112, 256>>>(W1, W2, W3);
  persist_sde<<<2048, 256, SMEM>>>(X0, out, b1, w1s, b2, b3);
}

// round 11
// speedup vs baseline: 3.2498x; 1.0460x over previous
#include <cuda_runtime.h>
#include <cuda_bf16.h>
#include <cstdint>
#include <math.h>

#define NOBS   65536
#define DIM    64
#define NELEM  (NOBS * DIM)

// ---------------------------------------------------------------------------
// Weight fragments, interleaved: one uint4 = {b0_hi, b1_hi, b0_lo, b1_lo}
// entry (nj*KT + ki)*32 + lane, mma.sync.m16n8k16 B-fragment order.
// W1 split into step-varying half (rows 0..63 -> w1a) and X0 half (64..127 -> w1b)
// ---------------------------------------------------------------------------
__device__ uint4 g_w1af[128 * 32];  // 32 nj x 4 ki  (X part)
__device__ uint4 g_w1bf[128 * 32];  // 32 nj x 4 ki  (X0 part, used once)
__device__ uint4 g_w2f[512 * 32];   // 32 nj x 16 ki
__device__ uint4 g_w3f[128 * 32];   //  8 nj x 16 ki

// Step-invariant partial: P0 = X0 @ W1[64:128] + b1   [65536 x 256] f32
__device__ float g_p0[(size_t)NOBS * 256];

// ---------------------------------------------------------------------------
// threefry2x32 (JAX partitionable, exact)
// ---------------------------------------------------------------------------
__host__ __device__ __forceinline__ void tf2x32(uint32_t k0, uint32_t k1,
                                                uint32_t& x0, uint32_t& x1) {
  uint32_t ks2 = k0 ^ k1 ^ 0x1BD11BDAu;
  x0 += k0; x1 += k1;
#define TFR(r) { x0 += x1; x1 = (x1 << (r)) | (x1 >> (32 - (r))); x1 ^= x0; }
  TFR(13) TFR(15) TFR(26) TFR(6)
  x0 += k1;  x1 += ks2 + 1u;
  TFR(17) TFR(29) TFR(16) TFR(24)
  x0 += ks2; x1 += k0 + 2u;
  TFR(13) TFR(15) TFR(26) TFR(6)
  x0 += k0;  x1 += k1 + 3u;
  TFR(17) TFR(29) TFR(16) TFR(24)
  x0 += k1;  x1 += ks2 + 4u;
  TFR(13) TFR(15) TFR(26) TFR(6)
  x0 += ks2; x1 += k0 + 5u;
#undef TFR
}

__device__ __forceinline__ void dev_split2(uint32_t k0, uint32_t k1,
                                           uint32_t out[2][2]) {
#pragma unroll
  for (uint32_t j = 0; j < 2; j++) {
    uint32_t a = 0u, b = j;
    tf2x32(k0, k1, a, b);
    out[j][0] = a; out[j][1] = b;
  }
}

__device__ __forceinline__ float erfinv_xla(float x) {
  float w = -log1pf(-x * x);
  float p;
  if (w < 5.0f) {
    w -= 2.5f;
    p = 2.81022636e-08f;
    p = fmaf(p, w, 3.43273939e-07f);
    p = fmaf(p, w, -3.5233877e-06f);
    p = fmaf(p, w, -4.39150654e-06f);
    p = fmaf(p, w, 0.00021858087f);
    p = fmaf(p, w, -0.00125372503f);
    p = fmaf(p, w, -0.00417768164f);
    p = fmaf(p, w, 0.246640727f);
    p = fmaf(p, w, 1.50140941f);
  } else {
    w = sqrtf(w) - 3.0f;
    p = -0.000200214257f;
    p = fmaf(p, w, 0.000100950558f);
    p = fmaf(p, w, 0.00134934322f);
    p = fmaf(p, w, -0.00367342844f);
    p = fmaf(p, w, 0.00573950773f);
    p = fmaf(p, w, -0.0076224613f);
    p = fmaf(p, w, 0.00943887047f);
    p = fmaf(p, w, 1.00167406f);
    p = fmaf(p, w, 2.83297682f);
  }
  return p * x;
}
__device__ __forceinline__ float bits_to_normal(uint32_t bits) {
  float f = __uint_as_float((bits >> 9) | 0x3F800000u) - 1.0f;
  const float lo = -0.99999994f;
  float u = fmaxf(lo, f * 2.0f + lo);
  return 1.41421356237f * erfinv_xla(u);
}

// ---------------------------------------------------------------------------
// bf16 helpers
// ---------------------------------------------------------------------------
__device__ __forceinline__ uint32_t pack_bf2(float a, float b) {
  uint32_t la = (uint32_t)__bfloat16_as_ushort(__float2bfloat16_rn(a));
  uint32_t hb = (uint32_t)__bfloat16_as_ushort(__float2bfloat16_rn(b));
  return la | (hb << 16);
}
__device__ __forceinline__ void split_pack(float a, float b,
                                           uint32_t& hi, uint32_t& lo) {
  __nv_bfloat16 ah = __float2bfloat16_rn(a), bh = __float2bfloat16_rn(b);
  hi = (uint32_t)__bfloat16_as_ushort(ah) |
       ((uint32_t)__bfloat16_as_ushort(bh) << 16);
  lo = pack_bf2(a - __bfloat162float(ah), b - __bfloat162float(bh));
}

__device__ __forceinline__ void mma_bf16(float (&d)[4], const uint32_t (&a)[4],
                                         uint32_t b0, uint32_t b1) {
  asm volatile(
      "mma.sync.aligned.m16n8k16.row.col.f32.bf16.bf16.f32 "
      "{%0,%1,%2,%3}, {%4,%5,%6,%7}, {%8,%9}, {%0,%1,%2,%3};"
      : "+f"(d[0]), "+f"(d[1]), "+f"(d[2]), "+f"(d[3])
      : "r"(a[0]), "r"(a[1]), "r"(a[2]), "r"(a[3]), "r"(b0), "r"(b1));
}

// ---------------------------------------------------------------------------
// Weight prep
// ---------------------------------------------------------------------------
__global__ void prep_weights(const float* __restrict__ W1,
                             const float* __restrict__ W2,
                             const float* __restrict__ W3) {
  int tid = blockIdx.x * 256 + threadIdx.x;
  int T = tid >> 5, lane = tid & 31;
  if (T >= 896) return;
  int g = lane >> 2, t = lane & 3;
  const float* W; int ldn, ni, ki, idx; uint4* dst;
  if (T < 256) {
    ni = T >> 3; ki = T & 7; W = W1; ldn = 256;
    if (ki < 4) { dst = g_w1af; idx = ni * 4 + ki; }
    else        { dst = g_w1bf; idx = ni * 4 + (ki - 4); }
  } else if (T < 768) {
    int T2 = T - 256; ni = T2 >> 4; ki = T2 & 15; W = W2; ldn = 256;
    dst = g_w2f; idx = T2;
  } else {
    int T3 = T - 768; ni = T3 >> 4; ki = T3 & 15; W = W3; ldn = 64;
    dst = g_w3f; idx = T3;
  }
  int n  = ni * 8 + g;
  int k0 = ki * 16 + 2 * t;
  float w00 = W[(k0    ) * ldn + n], w01 = W[(k0 + 1) * ldn + n];
  float w10 = W[(k0 + 8) * ldn + n], w11 = W[(k0 + 9) * ldn + n];
  uint32_t h0, l0, h1, l1;
  split_pack(w00, w01, h0, l0);
  split_pack(w10, w11, h1, l1);
  dst[idx * 32 + lane] = make_uint4(h0, h1, l0, l1);
}

// ---------------------------------------------------------------------------
// Fragment GEMM phase: acc[MT][NJ][4] += A(frags smem) @ B(uint4 frags gmem)
// ---------------------------------------------------------------------------
template<int KT, int NJ, int MT>
__device__ __forceinline__ void gemm_frags(
    float (&acc)[MT][NJ][4],
    const char* __restrict__ aHi, const char* __restrict__ aLo,
    int mBase, int lane,
    const uint4* __restrict__ B, int njBase) {
#pragma unroll
  for (int ki = 0; ki < KT; ++ki) {
    uint32_t ah[MT][4], al[MT][4];
#pragma unroll
    for (int mt = 0; mt < MT; ++mt) {
      uint4 vh = *(const uint4*)(aHi + (((mBase + mt) * KT + ki) * 512 + lane * 16));
      ah[mt][0] = vh.x; ah[mt][1] = vh.y; ah[mt][2] = vh.z; ah[mt][3] = vh.w;
      uint4 vl = *(const uint4*)(aLo + (((mBase + mt) * KT + ki) * 512 + lane * 16));
      al[mt][0] = vl.x; al[mt][1] = vl.y; al[mt][2] = vl.z; al[mt][3] = vl.w;
    }
#pragma unroll
    for (int jc = 0; jc < NJ; jc += 4) {
      constexpr int JW = (NJ < 4) ? NJ : 4;
      uint4 bv[JW];
#pragma unroll
      for (int j = 0; j < JW; ++j)
        bv[j] = B[((njBase + jc + j) * KT + ki) * 32 + lane];
#pragma unroll
      for (int mt = 0; mt < MT; ++mt)
#pragma unroll
        for (int j = 0; j < JW; ++j) {
          mma_bf16(acc[mt][jc + j], ah[mt], bv[j].x, bv[j].y);
          mma_bf16(acc[mt][jc + j], al[mt], bv[j].x, bv[j].y);
          mma_bf16(acc[mt][jc + j], ah[mt], bv[j].z, bv[j].w);
        }
    }
  }
}

// ---------------------------------------------------------------------------
// P0 prep: P0 = X0 @ W1[64:128] + b1   (64-row CTA, same frag machinery)
// smem: actHi 8K, actLo 8K
// ---------------------------------------------------------------------------
__global__ void __launch_bounds__(256)
prep_p0(const float* __restrict__ X0g, const float* __restrict__ b1) {
  extern __shared__ char sm[];
  char* actHi = sm;
  char* actLo = sm + 8192;
  const int tid = threadIdx.x;
  const int wid = tid >> 5, lane = tid & 31;
  const int g = lane >> 2, t = lane & 3;
  const int rowBase = blockIdx.x * 64;

#pragma unroll
  for (int it = 0; it < 2; ++it) {
    int tile = wid * 2 + it;         // 16 tiles: mi(4) x ki(4)
    int mi = tile >> 2, ki = tile & 3;
    int kc = ki * 16;
    const float* p0 = X0g + (size_t)(rowBase + mi * 16 + g) * DIM + kc;
    const float* p1 = p0 + 8 * DIM;
    float2 v00 = *(const float2*)(p0 + 2 * t);
    float2 v01 = *(const float2*)(p0 + 2 * t + 8);
    float2 v10 = *(const float2*)(p1 + 2 * t);
    float2 v11 = *(const float2*)(p1 + 2 * t + 8);
    uint32_t h0, l0, h1, l1, h2, l2, h3, l3;
    split_pack(v00.x, v00.y, h0, l0);
    split_pack(v10.x, v10.y, h1, l1);
    split_pack(v01.x, v01.y, h2, l2);
    split_pack(v11.x, v11.y, h3, l3);
    int off = (mi * 4 + ki) * 512 + lane * 16;
    *(uint4*)(actHi + off) = make_uint4(h0, h1, h2, h3);
    *(uint4*)(actLo + off) = make_uint4(l0, l1, l2, l3);
  }
  __syncthreads();

  const int mrow = wid >> 2, ncol = wid & 3;
  float acc[2][8][4];
#pragma unroll
  for (int a = 0; a < 2; ++a)
#pragma unroll
    for (int b = 0; b < 8; ++b)
#pragma unroll
      for (int c = 0; c < 4; ++c) acc[a][b][c] = 0.f;
  gemm_frags<4, 8, 2>(acc, actHi, actLo, mrow * 2, lane, g_w1bf, ncol * 8);

#pragma unroll
  for (int j = 0; j < 8; ++j) {
    int nj = ncol * 8 + j;
    int c0 = nj * 8 + 2 * t;
    float bb0 = b1[c0], bb1 = b1[c0 + 1];
#pragma unroll
    for (int mt = 0; mt < 2; ++mt) {
      int r = rowBase + (mrow * 2 + mt) * 16 + g;
      float2 oA = make_float2(acc[mt][j][0] + bb0, acc[mt][j][1] + bb1);
      float2 oB = make_float2(acc[mt][j][2] + bb0, acc[mt][j][3] + bb1);
      *(float2*)&g_p0[(size_t)r * 256 + c0]       = oA;
      *(float2*)&g_p0[(size_t)(r + 8) * 256 + c0] = oB;
    }
  }
}

// ---------------------------------------------------------------------------
// Persistent fused sampler: one CTA owns 64 rows for all 64 steps.
// smem: actHi 0..8K, actLo 8..16K, hHi 16..48K, hLo 48..80K, Xbuf 80K..96.5K
// ---------------------------------------------------------------------------
#define XSTRIDE 66

__global__ void __launch_bounds__(256, 2)
persist_sde(const float* __restrict__ X0g, float* __restrict__ out,
            const float* __restrict__ w1s,
            const float* __restrict__ b2, const float* __restrict__ b3) {
  extern __shared__ char sm[];
  char*  actHi = sm;
  char*  actLo = sm + 8192;
  char*  hHi   = sm + 16384;
  char*  hLo   = sm + 49152;
  float* Xbuf  = (float*)(sm + 81920);

  const int tid  = threadIdx.x;
  const int wid  = tid >> 5;
  const int lane = tid & 31;
  const int g    = lane >> 2;
  const int t    = lane & 3;
  const int sample  = blockIdx.x >> 10;
  const int rowBase = (blockIdx.x & 1023) * 64;
  float* outp = out + (size_t)sample * NELEM;

  // ---- per-sample key chain: key(1) -> split -> sample key -> (ke, kl) ----
  uint32_t sk[2][2];
  dev_split2(0u, 1u, sk);
  uint32_t ks[2][2];
  dev_split2(sk[sample][0], sk[sample][1], ks);
  uint32_t ke0 = ks[0][0], ke1 = ks[0][1];
  uint32_t kl0 = ks[1][0], kl1 = ks[1][1];

  const int mrow = wid >> 2, ncol = wid & 3;     // 2x4 warp grid (GEMM1/2)
  const int mrow3 = wid >> 1, ncol3 = wid & 1;   // 4x2 warp grid (GEMM3)

#pragma unroll 1
  for (int n = 0; n < 64; ++n) {
    const float s = (float)n * 0.015625f;
    float cf = 0.0f;
    uint32_t nk0, nk1;
    if (n == 0) {
      nk0 = ke0; nk1 = ke1;
    } else {
      uint32_t kk[2][2];
      dev_split2(kl0, kl1, kk);
      kl0 = kk[0][0]; kl1 = kk[0][1];
      nk0 = kk[1][0]; nk1 = kk[1][1];
      const float sg = 1.0f - s;
      cf = 0.5f * (1.0f - sg * sg) / (s * sg);
    }

    // ---- phase 0: stage Xin frags (4 ki) from gmem (n=0) or Xbuf ----
#pragma unroll
    for (int it = 0; it < 2; ++it) {
      int tile = wid * 2 + it;         // 16 tiles: mi(4) x ki(4)
      int mi = tile >> 2, ki = tile & 3;
      int kc = ki * 16;
      const float *p0, *p1;
      if (n == 0) {
        p0 = X0g + (size_t)(rowBase + mi * 16 + g) * DIM + kc;
        p1 = p0 + 8 * DIM;
      } else {
        p0 = Xbuf + (mi * 16 + g) * XSTRIDE + kc;
        p1 = p0 + 8 * XSTRIDE;
      }
      float2 v00 = *(const float2*)(p0 + 2 * t);
      float2 v01 = *(const float2*)(p0 + 2 * t + 8);
      float2 v10 = *(const float2*)(p1 + 2 * t);
      float2 v11 = *(const float2*)(p1 + 2 * t + 8);
      uint32_t h0, l0, h1, l1, h2, l2, h3, l3;
      split_pack(v00.x, v00.y, h0, l0);
      split_pack(v10.x, v10.y, h1, l1);
      split_pack(v01.x, v01.y, h2, l2);
      split_pack(v11.x, v11.y, h3, l3);
      int off = (mi * 4 + ki) * 512 + lane * 16;
      *(uint4*)(actHi + off) = make_uint4(h0, h1, h2, h3);
      *(uint4*)(actLo + off) = make_uint4(l0, l1, l2, l3);
    }
    __syncthreads();

    // ---- phase 1: h1 = relu(P0 + Xin @ W1a + s*w1s) ----
    {
      float acc[2][8][4];
#pragma unroll
      for (int j = 0; j < 8; ++j) {
        int c0 = (ncol * 8 + j) * 8 + 2 * t;
#pragma unroll
        for (int mt = 0; mt < 2; ++mt) {
          int r = rowBase + (mrow * 2 + mt) * 16 + g;
          float2 pA = *(const float2*)&g_p0[(size_t)r * 256 + c0];
          float2 pB = *(const float2*)&g_p0[(size_t)(r + 8) * 256 + c0];
          acc[mt][j][0] = pA.x; acc[mt][j][1] = pA.y;
          acc[mt][j][2] = pB.x; acc[mt][j][3] = pB.y;
        }
      }
      gemm_frags<4, 8, 2>(acc, actHi, actLo, mrow * 2, lane, g_w1af, ncol * 8);
#pragma unroll
      for (int j = 0; j < 8; ++j) {
        int nj = ncol * 8 + j;
        int c0 = nj * 8 + 2 * t;
        float bb0 = s * w1s[c0];
        float bb1 = s * w1s[c0 + 1];
#pragma unroll
        for (int mt = 0; mt < 2; ++mt) {
          int mi = mrow * 2 + mt;
          float v00 = fmaxf(acc[mt][j][0] + bb0, 0.f);
          float v01 = fmaxf(acc[mt][j][1] + bb1, 0.f);
          float v10 = fmaxf(acc[mt][j][2] + bb0, 0.f);
          float v11 = fmaxf(acc[mt][j][3] + bb1, 0.f);
          uint32_t h0, l0, h1, l1;
          split_pack(v00, v01, h0, l0);
          split_pack(v10, v11, h1, l1);
          int off = (mi * 16 + (nj >> 1)) * 512 + lane * 16 + (nj & 1) * 8;
          *(uint2*)(hHi + off) = make_uint2(h0, h1);
          *(uint2*)(hLo + off) = make_uint2(l0, l1);
        }
      }
    }
    __syncthreads();

    // ---- phase 2: h2 = relu(h1 @ W2' + b2), overwrite h ----
    {
      float acc[2][8][4];
#pragma unroll
      for (int a = 0; a < 2; ++a)
#pragma unroll
        for (int b = 0; b < 8; ++b)
#pragma unroll
          for (int c = 0; c < 4; ++c) acc[a][b][c] = 0.f;
      gemm_frags<16, 8, 2>(acc, hHi, hLo, mrow * 2, lane, g_w2f, ncol * 8);
      __syncthreads();
#pragma unroll
      for (int j = 0; j < 8; ++j) {
        int nj = ncol * 8 + j;
        int c0 = nj * 8 + 2 * t;
        float bb0 = b2[c0];
        float bb1 = b2[c0 + 1];
#pragma unroll
        for (int mt = 0; mt < 2; ++mt) {
          int mi = mrow * 2 + mt;
          float v00 = fmaxf(acc[mt][j][0] + bb0, 0.f);
          float v01 = fmaxf(acc[mt][j][1] + bb1, 0.f);
          float v10 = fmaxf(acc[mt][j][2] + bb0, 0.f);
          float v11 = fmaxf(acc[mt][j][3] + bb1, 0.f);
          uint32_t h0, l0, h1, l1;
          split_pack(v00, v01, h0, l0);
          split_pack(v10, v11, h1, l1);
          int off = (mi * 16 + (nj >> 1)) * 512 + lane * 16 + (nj & 1) * 8;
          *(uint2*)(hHi + off) = make_uint2(h0, h1);
          *(uint2*)(hLo + off) = make_uint2(l0, l1);
        }
      }
    }
    __syncthreads();

    // ---- phase 3: bd = h2 @ W3' + b3; SDE update + threefry; X -> Xbuf ----
    {
      float acc[1][4][4];
#pragma unroll
      for (int b = 0; b < 4; ++b)
#pragma unroll
        for (int c = 0; c < 4; ++c) acc[0][b][c] = 0.f;
      gemm_frags<16, 4, 1>(acc, hHi, hLo, mrow3, lane, g_w3f, ncol3 * 4);
#pragma unroll
      for (int j = 0; j < 4; ++j) {
        int nj = ncol3 * 4 + j;
        int c0 = nj * 8 + 2 * t;
        float bb0 = b3[c0], bb1 = b3[c0 + 1];
#pragma unroll
        for (int half = 0; half < 2; ++half) {
          int rl = mrow3 * 16 + g + half * 8;     // row within tile
          int r  = rowBase + rl;                  // global row
          float bA = acc[0][j][half * 2 + 0] + bb0;
          float bB = acc[0][j][half * 2 + 1] + bb1;
          int i0 = r * DIM + c0;
          float2 x0v = *(const float2*)(X0g + i0);
          float2 Xo;
          if (n == 0) Xo = x0v;
          else        Xo = *(const float2*)&Xbuf[rl * XSTRIDE + c0];
          uint32_t u0 = 0u, u1 = (uint32_t)i0;
          tf2x32(nk0, nk1, u0, u1);
          float e0 = bits_to_normal(u0 ^ u1);
          uint32_t w0 = 0u, w1 = (uint32_t)(i0 + 1);
          tf2x32(nk0, nk1, w0, w1);
          float e1 = bits_to_normal(w0 ^ w1);
          float d0 = bA + cf * (s * bA - Xo.x + x0v.x);
          float d1 = bB + cf * (s * bB - Xo.y + x0v.y);
          float2 o;
          o.x = Xo.x + 0.015625f * d0 + 0.125f * e0;
          o.y = Xo.y + 0.015625f * d1 + 0.125f * e1;
          *(float2*)&Xbuf[rl * XSTRIDE + c0] = o;
          if (n == 63) *(float2*)(outp + i0) = o;
        }
      }
    }
    __syncthreads();   // Xbuf/h hazard barrier before next step
  }
}

// ---------------------------------------------------------------------------
// Host
// ---------------------------------------------------------------------------
extern "C" void kernel_launch(void* const* d_in, const int* in_sizes, int n_in,
                              void* d_out, int out_size) {
  (void)in_sizes; (void)n_in; (void)out_size;
  const float* X0 = (const float*)d_in[0];
  const float* W1 = (const float*)d_in[1];   // [129, 256]
  const float* b1 = (const float*)d_in[2];
  const float* W2 = (const float*)d_in[3];   // [256, 256]
  const float* b2 = (const float*)d_in[4];
  const float* W3 = (const float*)d_in[5];   // [256, 64]
  const float* b3 = (const float*)d_in[6];
  float* out = (float*)d_out;                // [2, 65536, 64]

  const float* w1s = W1 + 128 * 256;         // s-feature row

  constexpr int SMEM_P0 = 16384;
  constexpr int SMEM = 81920 + 64 * XSTRIDE * 4;   // 98816 B -> 2 CTAs/SM
  cudaFuncSetAttribute((const void*)persist_sde,
                       cudaFuncAttributeMaxDynamicSharedMemorySize, SMEM);

  prep_weights<<<112, 256>>>(W1, W2, W3);
  prep_p0<<<1024, 256, SMEM_P0>>>(X0, b1);
  persist_sde<<<2048, 256, SMEM>>>(X0, out, w1s, b2, b3);
}

// round 12
// speedup vs baseline: 3.7999x; 1.1693x over previous
#include <cuda_runtime.h>
#include <cuda_fp16.h>
#include <cstdint>
#include <math.h>

#define NOBS   65536
#define DIM    64
#define NELEM  (NOBS * DIM)

// ---------------------------------------------------------------------------
// Weight fragments (fp16 split), interleaved uint4 = {b0_hi, b1_hi, b0_lo, b1_lo}
// entry (nj*KT + ki)*32 + lane, mma.sync.m16n8k16 B-fragment order.
// ---------------------------------------------------------------------------
__device__ uint4 g_w1af[128 * 32];  // 32 nj x 4 ki  (X part of W1)
__device__ uint4 g_w1bf[128 * 32];  // 32 nj x 4 ki  (X0 part, used once)
__device__ uint4 g_w2f[512 * 32];   // 32 nj x 16 ki
__device__ uint4 g_w3f[128 * 32];   //  8 nj x 16 ki

// Step-invariant partial: P0 = X0 @ W1[64:128] + b1   [65536 x 256] f32
__device__ float g_p0[(size_t)NOBS * 256];

// ---------------------------------------------------------------------------
// threefry2x32 (JAX partitionable, exact)
// ---------------------------------------------------------------------------
__host__ __device__ __forceinline__ void tf2x32(uint32_t k0, uint32_t k1,
                                                uint32_t& x0, uint32_t& x1) {
  uint32_t ks2 = k0 ^ k1 ^ 0x1BD11BDAu;
  x0 += k0; x1 += k1;
#define TFR(r) { x0 += x1; x1 = (x1 << (r)) | (x1 >> (32 - (r))); x1 ^= x0; }
  TFR(13) TFR(15) TFR(26) TFR(6)
  x0 += k1;  x1 += ks2 + 1u;
  TFR(17) TFR(29) TFR(16) TFR(24)
  x0 += ks2; x1 += k0 + 2u;
  TFR(13) TFR(15) TFR(26) TFR(6)
  x0 += k0;  x1 += k1 + 3u;
  TFR(17) TFR(29) TFR(16) TFR(24)
  x0 += k1;  x1 += ks2 + 4u;
  TFR(13) TFR(15) TFR(26) TFR(6)
  x0 += ks2; x1 += k0 + 5u;
#undef TFR
}

__device__ __forceinline__ void dev_split2(uint32_t k0, uint32_t k1,
                                           uint32_t out[2][2]) {
#pragma unroll
  for (uint32_t j = 0; j < 2; j++) {
    uint32_t a = 0u, b = j;
    tf2x32(k0, k1, a, b);
    out[j][0] = a; out[j][1] = b;
  }
}

__device__ __forceinline__ float erfinv_xla(float x) {
  float w = -log1pf(-x * x);
  float p;
  if (w < 5.0f) {
    w -= 2.5f;
    p = 2.81022636e-08f;
    p = fmaf(p, w, 3.43273939e-07f);
    p = fmaf(p, w, -3.5233877e-06f);
    p = fmaf(p, w, -4.39150654e-06f);
    p = fmaf(p, w, 0.00021858087f);
    p = fmaf(p, w, -0.00125372503f);
    p = fmaf(p, w, -0.00417768164f);
    p = fmaf(p, w, 0.246640727f);
    p = fmaf(p, w, 1.50140941f);
  } else {
    w = sqrtf(w) - 3.0f;
    p = -0.000200214257f;
    p = fmaf(p, w, 0.000100950558f);
    p = fmaf(p, w, 0.00134934322f);
    p = fmaf(p, w, -0.00367342844f);
    p = fmaf(p, w, 0.00573950773f);
    p = fmaf(p, w, -0.0076224613f);
    p = fmaf(p, w, 0.00943887047f);
    p = fmaf(p, w, 1.00167406f);
    p = fmaf(p, w, 2.83297682f);
  }
  return p * x;
}
__device__ __forceinline__ float bits_to_normal(uint32_t bits) {
  float f = __uint_as_float((bits >> 9) | 0x3F800000u) - 1.0f;
  const float lo = -0.99999994f;
  float u = fmaxf(lo, f * 2.0f + lo);
  return 1.41421356237f * erfinv_xla(u);
}

// ---------------------------------------------------------------------------
// fp16 helpers
// ---------------------------------------------------------------------------
__device__ __forceinline__ uint32_t pack_h2(float a, float b) {
  uint32_t la = (uint32_t)__half_as_ushort(__float2half_rn(a));
  uint32_t hb = (uint32_t)__half_as_ushort(__float2half_rn(b));
  return la | (hb << 16);
}
__device__ __forceinline__ void split_pack(float a, float b,
                                           uint32_t& hi, uint32_t& lo) {
  __half ah = __float2half_rn(a), bh = __float2half_rn(b);
  hi = (uint32_t)__half_as_ushort(ah) |
       ((uint32_t)__half_as_ushort(bh) << 16);
  lo = pack_h2(a - __half2float(ah), b - __half2float(bh));
}

__device__ __forceinline__ void mma_f16(float (&d)[4], const uint32_t (&a)[4],
                                        uint32_t b0, uint32_t b1) {
  asm volatile(
      "mma.sync.aligned.m16n8k16.row.col.f32.f16.f16.f32 "
      "{%0,%1,%2,%3}, {%4,%5,%6,%7}, {%8,%9}, {%0,%1,%2,%3};"
      : "+f"(d[0]), "+f"(d[1]), "+f"(d[2]), "+f"(d[3])
      : "r"(a[0]), "r"(a[1]), "r"(a[2]), "r"(a[3]), "r"(b0), "r"(b1));
}

// ---------------------------------------------------------------------------
// Weight prep
// ---------------------------------------------------------------------------
__global__ void prep_weights(const float* __restrict__ W1,
                             const float* __restrict__ W2,
                             const float* __restrict__ W3) {
  int tid = blockIdx.x * 256 + threadIdx.x;
  int T = tid >> 5, lane = tid & 31;
  if (T >= 896) return;
  int g = lane >> 2, t = lane & 3;
  const float* W; int ldn, ni, ki, idx; uint4* dst;
  if (T < 256) {
    ni = T >> 3; ki = T & 7; W = W1; ldn = 256;
    if (ki < 4) { dst = g_w1af; idx = ni * 4 + ki; }
    else        { dst = g_w1bf; idx = ni * 4 + (ki - 4); }
  } else if (T < 768) {
    int T2 = T - 256; ni = T2 >> 4; ki = T2 & 15; W = W2; ldn = 256;
    dst = g_w2f; idx = T2;
  } else {
    int T3 = T - 768; ni = T3 >> 4; ki = T3 & 15; W = W3; ldn = 64;
    dst = g_w3f; idx = T3;
  }
  int n  = ni * 8 + g;
  int k0 = ki * 16 + 2 * t;
  float w00 = W[(k0    ) * ldn + n], w01 = W[(k0 + 1) * ldn + n];
  float w10 = W[(k0 + 8) * ldn + n], w11 = W[(k0 + 9) * ldn + n];
  uint32_t h0, l0, h1, l1;
  split_pack(w00, w01, h0, l0);
  split_pack(w10, w11, h1, l1);
  dst[idx * 32 + lane] = make_uint4(h0, h1, l0, l1);
}

// ---------------------------------------------------------------------------
// Fragment GEMM: acc[MT][NJ][4] += A(frags smem) @ B(uint4 frags gmem)
// THREE=true : a_hi*b_hi + a_lo*b_hi + a_hi*b_lo   (needs aLo)
// THREE=false: a_hi*b_hi + a_hi*b_lo               (aLo unused)
// ---------------------------------------------------------------------------
template<int KT, int NJ, int MT, bool THREE>
__device__ __forceinline__ void gemm_frags(
    float (&acc)[MT][NJ][4],
    const char* __restrict__ aHi, const char* __restrict__ aLo,
    int mBase, int lane,
    const uint4* __restrict__ B, int njBase) {
#pragma unroll
  for (int ki = 0; ki < KT; ++ki) {
    uint32_t ah[MT][4], al[MT][4];
#pragma unroll
    for (int mt = 0; mt < MT; ++mt) {
      uint4 vh = *(const uint4*)(aHi + (((mBase + mt) * KT + ki) * 512 + lane * 16));
      ah[mt][0] = vh.x; ah[mt][1] = vh.y; ah[mt][2] = vh.z; ah[mt][3] = vh.w;
      if (THREE) {
        uint4 vl = *(const uint4*)(aLo + (((mBase + mt) * KT + ki) * 512 + lane * 16));
        al[mt][0] = vl.x; al[mt][1] = vl.y; al[mt][2] = vl.z; al[mt][3] = vl.w;
      }
    }
#pragma unroll
    for (int jc = 0; jc < NJ; jc += 4) {
      constexpr int JW = (NJ < 4) ? NJ : 4;
      uint4 bv[JW];
#pragma unroll
      for (int j = 0; j < JW; ++j)
        bv[j] = B[((njBase + jc + j) * KT + ki) * 32 + lane];
#pragma unroll
      for (int mt = 0; mt < MT; ++mt)
#pragma unroll
        for (int j = 0; j < JW; ++j) {
          mma_f16(acc[mt][jc + j], ah[mt], bv[j].x, bv[j].y);
          if (THREE) mma_f16(acc[mt][jc + j], al[mt], bv[j].x, bv[j].y);
          mma_f16(acc[mt][jc + j], ah[mt], bv[j].z, bv[j].w);
        }
    }
  }
}

// ---------------------------------------------------------------------------
// P0 prep: P0 = X0 @ W1[64:128] + b1   (3-pass fp16)
// ---------------------------------------------------------------------------
__global__ void __launch_bounds__(256)
prep_p0(const float* __restrict__ X0g, const float* __restrict__ b1) {
  extern __shared__ char sm[];
  char* actHi = sm;
  char* actLo = sm + 8192;
  const int tid = threadIdx.x;
  const int wid = tid >> 5, lane = tid & 31;
  const int g = lane >> 2, t = lane & 3;
  const int rowBase = blockIdx.x * 64;

#pragma unroll
  for (int it = 0; it < 2; ++it) {
    int tile = wid * 2 + it;
    int mi = tile >> 2, ki = tile & 3;
    int kc = ki * 16;
    const float* p0 = X0g + (size_t)(rowBase + mi * 16 + g) * DIM + kc;
    const float* p1 = p0 + 8 * DIM;
    float2 v00 = *(const float2*)(p0 + 2 * t);
    float2 v01 = *(const float2*)(p0 + 2 * t + 8);
    float2 v10 = *(const float2*)(p1 + 2 * t);
    float2 v11 = *(const float2*)(p1 + 2 * t + 8);
    uint32_t h0, l0, h1, l1, h2, l2, h3, l3;
    split_pack(v00.x, v00.y, h0, l0);
    split_pack(v10.x, v10.y, h1, l1);
    split_pack(v01.x, v01.y, h2, l2);
    split_pack(v11.x, v11.y, h3, l3);
    int off = (mi * 4 + ki) * 512 + lane * 16;
    *(uint4*)(actHi + off) = make_uint4(h0, h1, h2, h3);
    *(uint4*)(actLo + off) = make_uint4(l0, l1, l2, l3);
  }
  __syncthreads();

  const int mrow = wid >> 2, ncol = wid & 3;
  float acc[2][8][4];
#pragma unroll
  for (int a = 0; a < 2; ++a)
#pragma unroll
    for (int b = 0; b < 8; ++b)
#pragma unroll
      for (int c = 0; c < 4; ++c) acc[a][b][c] = 0.f;
  gemm_frags<4, 8, 2, true>(acc, actHi, actLo, mrow * 2, lane, g_w1bf, ncol * 8);

#pragma unroll
  for (int j = 0; j < 8; ++j) {
    int nj = ncol * 8 + j;
    int c0 = nj * 8 + 2 * t;
    float bb0 = b1[c0], bb1 = b1[c0 + 1];
#pragma unroll
    for (int mt = 0; mt < 2; ++mt) {
      int r = rowBase + (mrow * 2 + mt) * 16 + g;
      float2 oA = make_float2(acc[mt][j][0] + bb0, acc[mt][j][1] + bb1);
      float2 oB = make_float2(acc[mt][j][2] + bb0, acc[mt][j][3] + bb1);
      *(float2*)&g_p0[(size_t)r * 256 + c0]       = oA;
      *(float2*)&g_p0[(size_t)(r + 8) * 256 + c0] = oB;
    }
  }
}

// ---------------------------------------------------------------------------
// Persistent fused sampler: one CTA owns 64 rows for all 64 steps.
// GEMM1: 3-pass (A=[X|X0]); GEMM2: 2-pass (A=h1 hi only); GEMM3: 3-pass.
// smem: actHi 0..8K, actLo 8..16K, hHi 16..48K, hLo 48..80K, Xbuf 80K..96.5K
// ---------------------------------------------------------------------------
#define XSTRIDE 66

__global__ void __launch_bounds__(256, 2)
persist_sde(const float* __restrict__ X0g, float* __restrict__ out,
            const float* __restrict__ w1s,
            const float* __restrict__ b2, const float* __restrict__ b3) {
  extern __shared__ char sm[];
  char*  actHi = sm;
  char*  actLo = sm + 8192;
  char*  hHi   = sm + 16384;
  char*  hLo   = sm + 49152;
  float* Xbuf  = (float*)(sm + 81920);

  const int tid  = threadIdx.x;
  const int wid  = tid >> 5;
  const int lane = tid & 31;
  const int g    = lane >> 2;
  const int t    = lane & 3;
  const int sample  = blockIdx.x >> 10;
  const int rowBase = (blockIdx.x & 1023) * 64;
  float* outp = out + (size_t)sample * NELEM;

  uint32_t sk[2][2];
  dev_split2(0u, 1u, sk);
  uint32_t ks[2][2];
  dev_split2(sk[sample][0], sk[sample][1], ks);
  uint32_t ke0 = ks[0][0], ke1 = ks[0][1];
  uint32_t kl0 = ks[1][0], kl1 = ks[1][1];

  const int mrow = wid >> 2, ncol = wid & 3;     // 2x4 warp grid (GEMM1/2)
  const int mrow3 = wid >> 1, ncol3 = wid & 1;   // 4x2 warp grid (GEMM3)

#pragma unroll 1
  for (int n = 0; n < 64; ++n) {
    const float s = (float)n * 0.015625f;
    float cf = 0.0f;
    uint32_t nk0, nk1;
    if (n == 0) {
      nk0 = ke0; nk1 = ke1;
    } else {
      uint32_t kk[2][2];
      dev_split2(kl0, kl1, kk);
      kl0 = kk[0][0]; kl1 = kk[0][1];
      nk0 = kk[1][0]; nk1 = kk[1][1];
      const float sg = 1.0f - s;
      cf = 0.5f * (1.0f - sg * sg) / (s * sg);
    }

    // ---- phase 0: stage Xin frags (4 ki) from gmem (n=0) or Xbuf ----
#pragma unroll
    for (int it = 0; it < 2; ++it) {
      int tile = wid * 2 + it;
      int mi = tile >> 2, ki = tile & 3;
      int kc = ki * 16;
      const float *p0, *p1;
      if (n == 0) {
        p0 = X0g + (size_t)(rowBase + mi * 16 + g) * DIM + kc;
        p1 = p0 + 8 * DIM;
      } else {
        p0 = Xbuf + (mi * 16 + g) * XSTRIDE + kc;
        p1 = p0 + 8 * XSTRIDE;
      }
      float2 v00 = *(const float2*)(p0 + 2 * t);
      float2 v01 = *(const float2*)(p0 + 2 * t + 8);
      float2 v10 = *(const float2*)(p1 + 2 * t);
      float2 v11 = *(const float2*)(p1 + 2 * t + 8);
      uint32_t h0, l0, h1, l1, h2, l2, h3, l3;
      split_pack(v00.x, v00.y, h0, l0);
      split_pack(v10.x, v10.y, h1, l1);
      split_pack(v01.x, v01.y, h2, l2);
      split_pack(v11.x, v11.y, h3, l3);
      int off = (mi * 4 + ki) * 512 + lane * 16;
      *(uint4*)(actHi + off) = make_uint4(h0, h1, h2, h3);
      *(uint4*)(actLo + off) = make_uint4(l0, l1, l2, l3);
    }
    __syncthreads();

    // ---- phase 1: h1 = relu(P0 + Xin @ W1a + s*w1s), store hi plane only ----
    {
      float acc[2][8][4];
#pragma unroll
      for (int j = 0; j < 8; ++j) {
        int c0 = (ncol * 8 + j) * 8 + 2 * t;
#pragma unroll
        for (int mt = 0; mt < 2; ++mt) {
          int r = rowBase + (mrow * 2 + mt) * 16 + g;
          float2 pA = *(const float2*)&g_p0[(size_t)r * 256 + c0];
          float2 pB = *(const float2*)&g_p0[(size_t)(r + 8) * 256 + c0];
          acc[mt][j][0] = pA.x; acc[mt][j][1] = pA.y;
          acc[mt][j][2] = pB.x; acc[mt][j][3] = pB.y;
        }
      }
      gemm_frags<4, 8, 2, true>(acc, actHi, actLo, mrow * 2, lane, g_w1af, ncol * 8);
#pragma unroll
      for (int j = 0; j < 8; ++j) {
        int nj = ncol * 8 + j;
        int c0 = nj * 8 + 2 * t;
        float bb0 = s * w1s[c0];
        float bb1 = s * w1s[c0 + 1];
#pragma unroll
        for (int mt = 0; mt < 2; ++mt) {
          int mi = mrow * 2 + mt;
          float v00 = fmaxf(acc[mt][j][0] + bb0, 0.f);
          float v01 = fmaxf(acc[mt][j][1] + bb1, 0.f);
          float v10 = fmaxf(acc[mt][j][2] + bb0, 0.f);
          float v11 = fmaxf(acc[mt][j][3] + bb1, 0.f);
          uint32_t h0 = pack_h2(v00, v01);
          uint32_t h1 = pack_h2(v10, v11);
          int off = (mi * 16 + (nj >> 1)) * 512 + lane * 16 + (nj & 1) * 8;
          *(uint2*)(hHi + off) = make_uint2(h0, h1);
        }
      }
    }
    __syncthreads();

    // ---- phase 2: h2 = relu(h1_hi @ (W2hi+W2lo) + b2), 2-pass; h2 hi+lo ----
    {
      float acc[2][8][4];
#pragma unroll
      for (int a = 0; a < 2; ++a)
#pragma unroll
        for (int b = 0; b < 8; ++b)
#pragma unroll
          for (int c = 0; c < 4; ++c) acc[a][b][c] = 0.f;
      gemm_frags<16, 8, 2, false>(acc, hHi, nullptr, mrow * 2, lane, g_w2f, ncol * 8);
      __syncthreads();   // all warps done reading h1 before overwrite
#pragma unroll
      for (int j = 0; j < 8; ++j) {
        int nj = ncol * 8 + j;
        int c0 = nj * 8 + 2 * t;
        float bb0 = b2[c0];
        float bb1 = b2[c0 + 1];
#pragma unroll
        for (int mt = 0; mt < 2; ++mt) {
          int mi = mrow * 2 + mt;
          float v00 = fmaxf(acc[mt][j][0] + bb0, 0.f);
          float v01 = fmaxf(acc[mt][j][1] + bb1, 0.f);
          float v10 = fmaxf(acc[mt][j][2] + bb0, 0.f);
          float v11 = fmaxf(acc[mt][j][3] + bb1, 0.f);
          uint32_t h0, l0, h1, l1;
          split_pack(v00, v01, h0, l0);
          split_pack(v10, v11, h1, l1);
          int off = (mi * 16 + (nj >> 1)) * 512 + lane * 16 + (nj & 1) * 8;
          *(uint2*)(hHi + off) = make_uint2(h0, h1);
          *(uint2*)(hLo + off) = make_uint2(l0, l1);
        }
      }
    }
    __syncthreads();

    // ---- phase 3: bd = h2 @ W3' + b3 (3-pass); SDE update + threefry ----
    {
      float acc[1][4][4];
#pragma unroll
      for (int b = 0; b < 4; ++b)
#pragma unroll
        for (int c = 0; c < 4; ++c) acc[0][b][c] = 0.f;
      gemm_frags<16, 4, 1, true>(acc, hHi, hLo, mrow3, lane, g_w3f, ncol3 * 4);
#pragma unroll
      for (int j = 0; j < 4; ++j) {
        int nj = ncol3 * 4 + j;
        int c0 = nj * 8 + 2 * t;
        float bb0 = b3[c0], bb1 = b3[c0 + 1];
#pragma unroll
        for (int half = 0; half < 2; ++half) {
          int rl = mrow3 * 16 + g + half * 8;
          int r  = rowBase + rl;
          float bA = acc[0][j][half * 2 + 0] + bb0;
          float bB = acc[0][j][half * 2 + 1] + bb1;
          int i0 = r * DIM + c0;
          float2 x0v = *(const float2*)(X0g + i0);
          float2 Xo;
          if (n == 0) Xo = x0v;
          else        Xo = *(const float2*)&Xbuf[rl * XSTRIDE + c0];
          uint32_t u0 = 0u, u1 = (uint32_t)i0;
          tf2x32(nk0, nk1, u0, u1);
          float e0 = bits_to_normal(u0 ^ u1);
          uint32_t w0 = 0u, w1 = (uint32_t)(i0 + 1);
          tf2x32(nk0, nk1, w0, w1);
          float e1 = bits_to_normal(w0 ^ w1);
          float d0 = bA + cf * (s * bA - Xo.x + x0v.x);
          float d1 = bB + cf * (s * bB - Xo.y + x0v.y);
          float2 o;
          o.x = Xo.x + 0.015625f * d0 + 0.125f * e0;
          o.y = Xo.y + 0.015625f * d1 + 0.125f * e1;
          *(float2*)&Xbuf[rl * XSTRIDE + c0] = o;
          if (n == 63) *(float2*)(outp + i0) = o;
        }
      }
    }
    __syncthreads();
  }
}

// ---------------------------------------------------------------------------
// Host
// ---------------------------------------------------------------------------
extern "C" void kernel_launch(void* const* d_in, const int* in_sizes, int n_in,
                              void* d_out, int out_size) {
  (void)in_sizes; (void)n_in; (void)out_size;
  const float* X0 = (const float*)d_in[0];
  const float* W1 = (const float*)d_in[1];   // [129, 256]
  const float* b1 = (const float*)d_in[2];
  const float* W2 = (const float*)d_in[3];   // [256, 256]
  const float* b2 = (const float*)d_in[4];
  const float* W3 = (const float*)d_in[5];   // [256, 64]
  const float* b3 = (const float*)d_in[6];
  float* out = (float*)d_out;                // [2, 65536, 64]

  const float* w1s = W1 + 128 * 256;         // s-feature row

  constexpr int SMEM_P0 = 16384;
  constexpr int SMEM = 81920 + 64 * XSTRIDE * 4;   // 98816 B -> 2 CTAs/SM
  cudaFuncSetAttribute((const void*)persist_sde,
                       cudaFuncAttributeMaxDynamicSharedMemorySize, SMEM);

  prep_weights<<<112, 256>>>(W1, W2, W3);
  prep_p0<<<1024, 256, SMEM_P0>>>(X0, b1);
  persist_sde<<<2048, 256, SMEM>>>(X0, out, w1s, b2, b3);
}

// round 13
// speedup vs baseline: 4.3503x; 1.1449x over previous
#include <cuda_runtime.h>
#include <cuda_fp16.h>
#include <cstdint>
#include <math.h>

#define NOBS   65536
#define DIM    64
#define NELEM  (NOBS * DIM)

// ---------------------------------------------------------------------------
// Weight fragments (fp16 split), interleaved uint4 = {b0_hi, b1_hi, b0_lo, b1_lo}
// entry (nj*KT + ki)*32 + lane, mma.sync.m16n8k16 B-fragment order.
// ---------------------------------------------------------------------------
__device__ uint4 g_w1af[128 * 32];  // 32 nj x 4 ki  (X part of W1)
__device__ uint4 g_w1bf[128 * 32];  // 32 nj x 4 ki  (X0 part, used once)
__device__ uint4 g_w2f[512 * 32];   // 32 nj x 16 ki
__device__ uint4 g_w3f[128 * 32];   //  8 nj x 16 ki

// Step-invariant partial: P0 = X0 @ W1[64:128] + b1   [65536 x 256] f32
__device__ float g_p0[(size_t)NOBS * 256];

// ---------------------------------------------------------------------------
// threefry2x32 (JAX partitionable, exact)
// ---------------------------------------------------------------------------
__host__ __device__ __forceinline__ void tf2x32(uint32_t k0, uint32_t k1,
                                                uint32_t& x0, uint32_t& x1) {
  uint32_t ks2 = k0 ^ k1 ^ 0x1BD11BDAu;
  x0 += k0; x1 += k1;
#define TFR(r) { x0 += x1; x1 = (x1 << (r)) | (x1 >> (32 - (r))); x1 ^= x0; }
  TFR(13) TFR(15) TFR(26) TFR(6)
  x0 += k1;  x1 += ks2 + 1u;
  TFR(17) TFR(29) TFR(16) TFR(24)
  x0 += ks2; x1 += k0 + 2u;
  TFR(13) TFR(15) TFR(26) TFR(6)
  x0 += k0;  x1 += k1 + 3u;
  TFR(17) TFR(29) TFR(16) TFR(24)
  x0 += k1;  x1 += ks2 + 4u;
  TFR(13) TFR(15) TFR(26) TFR(6)
  x0 += ks2; x1 += k0 + 5u;
#undef TFR
}

__device__ __forceinline__ void dev_split2(uint32_t k0, uint32_t k1,
                                           uint32_t out[2][2]) {
#pragma unroll
  for (uint32_t j = 0; j < 2; j++) {
    uint32_t a = 0u, b = j;
    tf2x32(k0, k1, a, b);
    out[j][0] = a; out[j][1] = b;
  }
}

__device__ __forceinline__ float erfinv_xla(float x) {
  float w = -log1pf(-x * x);
  float p;
  if (w < 5.0f) {
    w -= 2.5f;
    p = 2.81022636e-08f;
    p = fmaf(p, w, 3.43273939e-07f);
    p = fmaf(p, w, -3.5233877e-06f);
    p = fmaf(p, w, -4.39150654e-06f);
    p = fmaf(p, w, 0.00021858087f);
    p = fmaf(p, w, -0.00125372503f);
    p = fmaf(p, w, -0.00417768164f);
    p = fmaf(p, w, 0.246640727f);
    p = fmaf(p, w, 1.50140941f);
  } else {
    w = sqrtf(w) - 3.0f;
    p = -0.000200214257f;
    p = fmaf(p, w, 0.000100950558f);
    p = fmaf(p, w, 0.00134934322f);
    p = fmaf(p, w, -0.00367342844f);
    p = fmaf(p, w, 0.00573950773f);
    p = fmaf(p, w, -0.0076224613f);
    p = fmaf(p, w, 0.00943887047f);
    p = fmaf(p, w, 1.00167406f);
    p = fmaf(p, w, 2.83297682f);
  }
  return p * x;
}
__device__ __forceinline__ float bits_to_normal(uint32_t bits) {
  float f = __uint_as_float((bits >> 9) | 0x3F800000u) - 1.0f;
  const float lo = -0.99999994f;
  float u = fmaxf(lo, f * 2.0f + lo);
  return 1.41421356237f * erfinv_xla(u);
}

// ---------------------------------------------------------------------------
// fp16 helpers
// ---------------------------------------------------------------------------
__device__ __forceinline__ uint32_t pack_h2(float a, float b) {
  uint32_t la = (uint32_t)__half_as_ushort(__float2half_rn(a));
  uint32_t hb = (uint32_t)__half_as_ushort(__float2half_rn(b));
  return la | (hb << 16);
}
__device__ __forceinline__ void split_pack(float a, float b,
                                           uint32_t& hi, uint32_t& lo) {
  __half ah = __float2half_rn(a), bh = __float2half_rn(b);
  hi = (uint32_t)__half_as_ushort(ah) |
       ((uint32_t)__half_as_ushort(bh) << 16);
  lo = pack_h2(a - __half2float(ah), b - __half2float(bh));
}

__device__ __forceinline__ void mma_f16(float (&d)[4], const uint32_t (&a)[4],
                                        uint32_t b0, uint32_t b1) {
  asm volatile(
      "mma.sync.aligned.m16n8k16.row.col.f32.f16.f16.f32 "
      "{%0,%1,%2,%3}, {%4,%5,%6,%7}, {%8,%9}, {%0,%1,%2,%3};"
      : "+f"(d[0]), "+f"(d[1]), "+f"(d[2]), "+f"(d[3])
      : "r"(a[0]), "r"(a[1]), "r"(a[2]), "r"(a[3]), "r"(b0), "r"(b1));
}

// ---------------------------------------------------------------------------
// Weight prep
// ---------------------------------------------------------------------------
__global__ void prep_weights(const float* __restrict__ W1,
                             const float* __restrict__ W2,
                             const float* __restrict__ W3) {
  int tid = blockIdx.x * 256 + threadIdx.x;
  int T = tid >> 5, lane = tid & 31;
  if (T >= 896) return;
  int g = lane >> 2, t = lane & 3;
  const float* W; int ldn, ni, ki, idx; uint4* dst;
  if (T < 256) {
    ni = T >> 3; ki = T & 7; W = W1; ldn = 256;
    if (ki < 4) { dst = g_w1af; idx = ni * 4 + ki; }
    else        { dst = g_w1bf; idx = ni * 4 + (ki - 4); }
  } else if (T < 768) {
    int T2 = T - 256; ni = T2 >> 4; ki = T2 & 15; W = W2; ldn = 256;
    dst = g_w2f; idx = T2;
  } else {
    int T3 = T - 768; ni = T3 >> 4; ki = T3 & 15; W = W3; ldn = 64;
    dst = g_w3f; idx = T3;
  }
  int n  = ni * 8 + g;
  int k0 = ki * 16 + 2 * t;
  float w00 = W[(k0    ) * ldn + n], w01 = W[(k0 + 1) * ldn + n];
  float w10 = W[(k0 + 8) * ldn + n], w11 = W[(k0 + 9) * ldn + n];
  uint32_t h0, l0, h1, l1;
  split_pack(w00, w01, h0, l0);
  split_pack(w10, w11, h1, l1);
  dst[idx * 32 + lane] = make_uint4(h0, h1, l0, l1);
}

// ---------------------------------------------------------------------------
// Fragment GEMM: acc[MT][NJ][4] += A(hi frags smem) @ B(uint4 frags gmem)
// THREE=true : a_hi*b_hi + a_lo*b_hi + a_hi*b_lo  (prep only)
// THREE=false: a_hi*b_hi + a_hi*b_lo              (main path)
// ---------------------------------------------------------------------------
template<int KT, int NJ, int MT, bool THREE>
__device__ __forceinline__ void gemm_frags(
    float (&acc)[MT][NJ][4],
    const char* __restrict__ aHi, const char* __restrict__ aLo,
    int mBase, int lane,
    const uint4* __restrict__ B, int njBase) {
#pragma unroll
  for (int ki = 0; ki < KT; ++ki) {
    uint32_t ah[MT][4], al[MT][4];
#pragma unroll
    for (int mt = 0; mt < MT; ++mt) {
      uint4 vh = *(const uint4*)(aHi + (((mBase + mt) * KT + ki) * 512 + lane * 16));
      ah[mt][0] = vh.x; ah[mt][1] = vh.y; ah[mt][2] = vh.z; ah[mt][3] = vh.w;
      if (THREE) {
        uint4 vl = *(const uint4*)(aLo + (((mBase + mt) * KT + ki) * 512 + lane * 16));
        al[mt][0] = vl.x; al[mt][1] = vl.y; al[mt][2] = vl.z; al[mt][3] = vl.w;
      }
    }
#pragma unroll
    for (int jc = 0; jc < NJ; jc += 4) {
      constexpr int JW = (NJ < 4) ? NJ : 4;
      uint4 bv[JW];
#pragma unroll
      for (int j = 0; j < JW; ++j)
        bv[j] = B[((njBase + jc + j) * KT + ki) * 32 + lane];
#pragma unroll
      for (int mt = 0; mt < MT; ++mt)
#pragma unroll
        for (int j = 0; j < JW; ++j) {
          mma_f16(acc[mt][jc + j], ah[mt], bv[j].x, bv[j].y);
          if (THREE) mma_f16(acc[mt][jc + j], al[mt], bv[j].x, bv[j].y);
          mma_f16(acc[mt][jc + j], ah[mt], bv[j].z, bv[j].w);
        }
    }
  }
}

// ---------------------------------------------------------------------------
// P0 prep: P0 = X0 @ W1[64:128] + b1   (3-pass fp16, one-time)
// ---------------------------------------------------------------------------
__global__ void __launch_bounds__(256)
prep_p0(const float* __restrict__ X0g, const float* __restrict__ b1) {
  extern __shared__ char sm[];
  char* actHi = sm;
  char* actLo = sm + 8192;
  const int tid = threadIdx.x;
  const int wid = tid >> 5, lane = tid & 31;
  const int g = lane >> 2, t = lane & 3;
  const int rowBase = blockIdx.x * 64;

#pragma unroll
  for (int it = 0; it < 2; ++it) {
    int tile = wid * 2 + it;
    int mi = tile >> 2, ki = tile & 3;
    int kc = ki * 16;
    const float* p0 = X0g + (size_t)(rowBase + mi * 16 + g) * DIM + kc;
    const float* p1 = p0 + 8 * DIM;
    float2 v00 = *(const float2*)(p0 + 2 * t);
    float2 v01 = *(const float2*)(p0 + 2 * t + 8);
    float2 v10 = *(const float2*)(p1 + 2 * t);
    float2 v11 = *(const float2*)(p1 + 2 * t + 8);
    uint32_t h0, l0, h1, l1, h2, l2, h3, l3;
    split_pack(v00.x, v00.y, h0, l0);
    split_pack(v10.x, v10.y, h1, l1);
    split_pack(v01.x, v01.y, h2, l2);
    split_pack(v11.x, v11.y, h3, l3);
    int off = (mi * 4 + ki) * 512 + lane * 16;
    *(uint4*)(actHi + off) = make_uint4(h0, h1, h2, h3);
    *(uint4*)(actLo + off) = make_uint4(l0, l1, l2, l3);
  }
  __syncthreads();

  const int mrow = wid >> 2, ncol = wid & 3;
  float acc[2][8][4];
#pragma unroll
  for (int a = 0; a < 2; ++a)
#pragma unroll
    for (int b = 0; b < 8; ++b)
#pragma unroll
      for (int c = 0; c < 4; ++c) acc[a][b][c] = 0.f;
  gemm_frags<4, 8, 2, true>(acc, actHi, actLo, mrow * 2, lane, g_w1bf, ncol * 8);

#pragma unroll
  for (int j = 0; j < 8; ++j) {
    int nj = ncol * 8 + j;
    int c0 = nj * 8 + 2 * t;
    float bb0 = b1[c0], bb1 = b1[c0 + 1];
#pragma unroll
    for (int mt = 0; mt < 2; ++mt) {
      int r = rowBase + (mrow * 2 + mt) * 16 + g;
      float2 oA = make_float2(acc[mt][j][0] + bb0, acc[mt][j][1] + bb1);
      float2 oB = make_float2(acc[mt][j][2] + bb0, acc[mt][j][3] + bb1);
      *(float2*)&g_p0[(size_t)r * 256 + c0]       = oA;
      *(float2*)&g_p0[(size_t)(r + 8) * 256 + c0] = oB;
    }
  }
}

// ---------------------------------------------------------------------------
// Persistent fused sampler: one CTA owns 64 rows for all 64 steps.
// ALL step GEMMs 2-pass fp16 (activation hi-plane only; weight residual kept).
// smem: actHi 0..8K, hHi 8..40K, Xbuf 40K..56.5K
// ---------------------------------------------------------------------------
#define XSTRIDE 66

__global__ void __launch_bounds__(256, 2)
persist_sde(const float* __restrict__ X0g, float* __restrict__ out,
            const float* __restrict__ w1s,
            const float* __restrict__ b2, const float* __restrict__ b3) {
  extern __shared__ char sm[];
  char*  actHi = sm;
  char*  hHi   = sm + 8192;
  float* Xbuf  = (float*)(sm + 40960);

  const int tid  = threadIdx.x;
  const int wid  = tid >> 5;
  const int lane = tid & 31;
  const int g    = lane >> 2;
  const int t    = lane & 3;
  const int sample  = blockIdx.x >> 10;
  const int rowBase = (blockIdx.x & 1023) * 64;
  float* outp = out + (size_t)sample * NELEM;

  uint32_t sk[2][2];
  dev_split2(0u, 1u, sk);
  uint32_t ks[2][2];
  dev_split2(sk[sample][0], sk[sample][1], ks);
  uint32_t ke0 = ks[0][0], ke1 = ks[0][1];
  uint32_t kl0 = ks[1][0], kl1 = ks[1][1];

  const int mrow = wid >> 2, ncol = wid & 3;     // 2x4 warp grid (GEMM1/2)
  const int mrow3 = wid >> 1, ncol3 = wid & 1;   // 4x2 warp grid (GEMM3)

#pragma unroll 1
  for (int n = 0; n < 64; ++n) {
    const float s = (float)n * 0.015625f;
    float cf = 0.0f;
    uint32_t nk0, nk1;
    if (n == 0) {
      nk0 = ke0; nk1 = ke1;
    } else {
      uint32_t kk[2][2];
      dev_split2(kl0, kl1, kk);
      kl0 = kk[0][0]; kl1 = kk[0][1];
      nk0 = kk[1][0]; nk1 = kk[1][1];
      const float sg = 1.0f - s;
      cf = 0.5f * (1.0f - sg * sg) / (s * sg);
    }

    // ---- phase 0: stage Xin hi-frags (4 ki) from gmem (n=0) or Xbuf ----
#pragma unroll
    for (int it = 0; it < 2; ++it) {
      int tile = wid * 2 + it;
      int mi = tile >> 2, ki = tile & 3;
      int kc = ki * 16;
      const float *p0, *p1;
      if (n == 0) {
        p0 = X0g + (size_t)(rowBase + mi * 16 + g) * DIM + kc;
        p1 = p0 + 8 * DIM;
      } else {
        p0 = Xbuf + (mi * 16 + g) * XSTRIDE + kc;
        p1 = p0 + 8 * XSTRIDE;
      }
      float2 v00 = *(const float2*)(p0 + 2 * t);
      float2 v01 = *(const float2*)(p0 + 2 * t + 8);
      float2 v10 = *(const float2*)(p1 + 2 * t);
      float2 v11 = *(const float2*)(p1 + 2 * t + 8);
      uint32_t h0 = pack_h2(v00.x, v00.y);
      uint32_t h1 = pack_h2(v10.x, v10.y);
      uint32_t h2 = pack_h2(v01.x, v01.y);
      uint32_t h3 = pack_h2(v11.x, v11.y);
      int off = (mi * 4 + ki) * 512 + lane * 16;
      *(uint4*)(actHi + off) = make_uint4(h0, h1, h2, h3);
    }
    __syncthreads();

    // ---- phase 1: h1 = relu(P0 + Xin @ W1a + s*w1s) ----
    {
      float acc[2][8][4];
#pragma unroll
      for (int j = 0; j < 8; ++j) {
        int c0 = (ncol * 8 + j) * 8 + 2 * t;
#pragma unroll
        for (int mt = 0; mt < 2; ++mt) {
          int r = rowBase + (mrow * 2 + mt) * 16 + g;
          float2 pA = *(const float2*)&g_p0[(size_t)r * 256 + c0];
          float2 pB = *(const float2*)&g_p0[(size_t)(r + 8) * 256 + c0];
          acc[mt][j][0] = pA.x; acc[mt][j][1] = pA.y;
          acc[mt][j][2] = pB.x; acc[mt][j][3] = pB.y;
        }
      }
      gemm_frags<4, 8, 2, false>(acc, actHi, nullptr, mrow * 2, lane, g_w1af, ncol * 8);
#pragma unroll
      for (int j = 0; j < 8; ++j) {
        int nj = ncol * 8 + j;
        int c0 = nj * 8 + 2 * t;
        float bb0 = s * w1s[c0];
        float bb1 = s * w1s[c0 + 1];
#pragma unroll
        for (int mt = 0; mt < 2; ++mt) {
          int mi = mrow * 2 + mt;
          float v00 = fmaxf(acc[mt][j][0] + bb0, 0.f);
          float v01 = fmaxf(acc[mt][j][1] + bb1, 0.f);
          float v10 = fmaxf(acc[mt][j][2] + bb0, 0.f);
          float v11 = fmaxf(acc[mt][j][3] + bb1, 0.f);
          uint32_t h0 = pack_h2(v00, v01);
          uint32_t h1 = pack_h2(v10, v11);
          int off = (mi * 16 + (nj >> 1)) * 512 + lane * 16 + (nj & 1) * 8;
          *(uint2*)(hHi + off) = make_uint2(h0, h1);
        }
      }
    }
    __syncthreads();

    // ---- phase 2: h2 = relu(h1 @ (W2hi+W2lo) + b2), overwrite hHi ----
    {
      float acc[2][8][4];
#pragma unroll
      for (int a = 0; a < 2; ++a)
#pragma unroll
        for (int b = 0; b < 8; ++b)
#pragma unroll
          for (int c = 0; c < 4; ++c) acc[a][b][c] = 0.f;
      gemm_frags<16, 8, 2, false>(acc, hHi, nullptr, mrow * 2, lane, g_w2f, ncol * 8);
      __syncthreads();   // all warps done reading h1 before overwrite
#pragma unroll
      for (int j = 0; j < 8; ++j) {
        int nj = ncol * 8 + j;
        int c0 = nj * 8 + 2 * t;
        float bb0 = b2[c0];
        float bb1 = b2[c0 + 1];
#pragma unroll
        for (int mt = 0; mt < 2; ++mt) {
          int mi = mrow * 2 + mt;
          float v00 = fmaxf(acc[mt][j][0] + bb0, 0.f);
          float v01 = fmaxf(acc[mt][j][1] + bb1, 0.f);
          float v10 = fmaxf(acc[mt][j][2] + bb0, 0.f);
          float v11 = fmaxf(acc[mt][j][3] + bb1, 0.f);
          uint32_t h0 = pack_h2(v00, v01);
          uint32_t h1 = pack_h2(v10, v11);
          int off = (mi * 16 + (nj >> 1)) * 512 + lane * 16 + (nj & 1) * 8;
          *(uint2*)(hHi + off) = make_uint2(h0, h1);
        }
      }
    }
    __syncthreads();

    // ---- phase 3: bd = h2 @ (W3hi+W3lo) + b3; SDE update + threefry ----
    {
      float acc[1][4][4];
#pragma unroll
      for (int b = 0; b < 4; ++b)
#pragma unroll
        for (int c = 0; c < 4; ++c) acc[0][b][c] = 0.f;
      gemm_frags<16, 4, 1, false>(acc, hHi, nullptr, mrow3, lane, g_w3f, ncol3 * 4);
#pragma unroll
      for (int j = 0; j < 4; ++j) {
        int nj = ncol3 * 4 + j;
        int c0 = nj * 8 + 2 * t;
        float bb0 = b3[c0], bb1 = b3[c0 + 1];
#pragma unroll
        for (int half = 0; half < 2; ++half) {
          int rl = mrow3 * 16 + g + half * 8;
          int r  = rowBase + rl;
          float bA = acc[0][j][half * 2 + 0] + bb0;
          float bB = acc[0][j][half * 2 + 1] + bb1;
          int i0 = r * DIM + c0;
          float2 x0v = *(const float2*)(X0g + i0);
          float2 Xo;
          if (n == 0) Xo = x0v;
          else        Xo = *(const float2*)&Xbuf[rl * XSTRIDE + c0];
          uint32_t u0 = 0u, u1 = (uint32_t)i0;
          tf2x32(nk0, nk1, u0, u1);
          float e0 = bits_to_normal(u0 ^ u1);
          uint32_t w0 = 0u, w1 = (uint32_t)(i0 + 1);
          tf2x32(nk0, nk1, w0, w1);
          float e1 = bits_to_normal(w0 ^ w1);
          float d0 = bA + cf * (s * bA - Xo.x + x0v.x);
          float d1 = bB + cf * (s * bB - Xo.y + x0v.y);
          float2 o;
          o.x = Xo.x + 0.015625f * d0 + 0.125f * e0;
          o.y = Xo.y + 0.015625f * d1 + 0.125f * e1;
          *(float2*)&Xbuf[rl * XSTRIDE + c0] = o;
          if (n == 63) *(float2*)(outp + i0) = o;
        }
      }
    }
    __syncthreads();
  }
}

// ---------------------------------------------------------------------------
// Host
// ---------------------------------------------------------------------------
extern "C" void kernel_launch(void* const* d_in, const int* in_sizes, int n_in,
                              void* d_out, int out_size) {
  (void)in_sizes; (void)n_in; (void)out_size;
  const float* X0 = (const float*)d_in[0];
  const float* W1 = (const float*)d_in[1];   // [129, 256]
  const float* b1 = (const float*)d_in[2];
  const float* W2 = (const float*)d_in[3];   // [256, 256]
  const float* b2 = (const float*)d_in[4];
  const float* W3 = (const float*)d_in[5];   // [256, 64]
  const float* b3 = (const float*)d_in[6];
  float* out = (float*)d_out;                // [2, 65536, 64]

  const float* w1s = W1 + 128 * 256;         // s-feature row

  constexpr int SMEM_P0 = 16384;
  constexpr int SMEM = 40960 + 64 * XSTRIDE * 4;   // 57856 B
  cudaFuncSetAttribute((const void*)persist_sde,
                       cudaFuncAttributeMaxDynamicSharedMemorySize, SMEM);

  prep_weights<<<112, 256>>>(W1, W2, W3);
  prep_p0<<<1024, 256, SMEM_P0>>>(X0, b1);
  persist_sde<<<2048, 256, SMEM>>>(X0, out, w1s, b2, b3);
}

// round 14
// speedup vs baseline: 5.6411x; 1.2967x over previous
#include <cuda_runtime.h>
#include <cuda_fp16.h>
#include <cstdint>
#include <math.h>

#define NOBS   65536
#define DIM    64
#define NELEM  (NOBS * DIM)

// ---------------------------------------------------------------------------
// Weight fragments (fp16), mma.sync.m16n8k16 B-fragment order.
// Step-path weights: uint2 = {b0_hi, b1_hi} (single-pass).
// W1 X0-half: uint4 = {b0_hi, b1_hi, b0_lo, b1_lo} (3-pass, P0 prep only).
// entry (nj*KT + ki)*32 + lane.
// ---------------------------------------------------------------------------
__device__ uint2 g_w1af[128 * 32];  // 32 nj x 4 ki  (X part of W1)
__device__ uint4 g_w1bf[128 * 32];  // 32 nj x 4 ki  (X0 part, used once)
__device__ uint2 g_w2f[512 * 32];   // 32 nj x 16 ki
__device__ uint2 g_w3f[128 * 32];   //  8 nj x 16 ki

// Step-invariant partial: P0 = X0 @ W1[64:128] + b1   [65536 x 256] f32
__device__ float g_p0[(size_t)NOBS * 256];

// ---------------------------------------------------------------------------
// threefry2x32 (JAX partitionable, exact)
// ---------------------------------------------------------------------------
__host__ __device__ __forceinline__ void tf2x32(uint32_t k0, uint32_t k1,
                                                uint32_t& x0, uint32_t& x1) {
  uint32_t ks2 = k0 ^ k1 ^ 0x1BD11BDAu;
  x0 += k0; x1 += k1;
#define TFR(r) { x0 += x1; x1 = (x1 << (r)) | (x1 >> (32 - (r))); x1 ^= x0; }
  TFR(13) TFR(15) TFR(26) TFR(6)
  x0 += k1;  x1 += ks2 + 1u;
  TFR(17) TFR(29) TFR(16) TFR(24)
  x0 += ks2; x1 += k0 + 2u;
  TFR(13) TFR(15) TFR(26) TFR(6)
  x0 += k0;  x1 += k1 + 3u;
  TFR(17) TFR(29) TFR(16) TFR(24)
  x0 += k1;  x1 += ks2 + 4u;
  TFR(13) TFR(15) TFR(26) TFR(6)
  x0 += ks2; x1 += k0 + 5u;
#undef TFR
}

__device__ __forceinline__ void dev_split2(uint32_t k0, uint32_t k1,
                                           uint32_t out[2][2]) {
#pragma unroll
  for (uint32_t j = 0; j < 2; j++) {
    uint32_t a = 0u, b = j;
    tf2x32(k0, k1, a, b);
    out[j][0] = a; out[j][1] = b;
  }
}

__device__ __forceinline__ float erfinv_xla(float x) {
  float w = -log1pf(-x * x);
  float p;
  if (w < 5.0f) {
    w -= 2.5f;
    p = 2.81022636e-08f;
    p = fmaf(p, w, 3.43273939e-07f);
    p = fmaf(p, w, -3.5233877e-06f);
    p = fmaf(p, w, -4.39150654e-06f);
    p = fmaf(p, w, 0.00021858087f);
    p = fmaf(p, w, -0.00125372503f);
    p = fmaf(p, w, -0.00417768164f);
    p = fmaf(p, w, 0.246640727f);
    p = fmaf(p, w, 1.50140941f);
  } else {
    w = sqrtf(w) - 3.0f;
    p = -0.000200214257f;
    p = fmaf(p, w, 0.000100950558f);
    p = fmaf(p, w, 0.00134934322f);
    p = fmaf(p, w, -0.00367342844f);
    p = fmaf(p, w, 0.00573950773f);
    p = fmaf(p, w, -0.0076224613f);
    p = fmaf(p, w, 0.00943887047f);
    p = fmaf(p, w, 1.00167406f);
    p = fmaf(p, w, 2.83297682f);
  }
  return p * x;
}
__device__ __forceinline__ float bits_to_normal(uint32_t bits) {
  float f = __uint_as_float((bits >> 9) | 0x3F800000u) - 1.0f;
  const float lo = -0.99999994f;
  float u = fmaxf(lo, f * 2.0f + lo);
  return 1.41421356237f * erfinv_xla(u);
}

// ---------------------------------------------------------------------------
// fp16 helpers
// ---------------------------------------------------------------------------
__device__ __forceinline__ uint32_t pack_h2(float a, float b) {
  uint32_t la = (uint32_t)__half_as_ushort(__float2half_rn(a));
  uint32_t hb = (uint32_t)__half_as_ushort(__float2half_rn(b));
  return la | (hb << 16);
}
__device__ __forceinline__ void split_pack(float a, float b,
                                           uint32_t& hi, uint32_t& lo) {
  __half ah = __float2half_rn(a), bh = __float2half_rn(b);
  hi = (uint32_t)__half_as_ushort(ah) |
       ((uint32_t)__half_as_ushort(bh) << 16);
  lo = pack_h2(a - __half2float(ah), b - __half2float(bh));
}

__device__ __forceinline__ void mma_f16(float (&d)[4], const uint32_t (&a)[4],
                                        uint32_t b0, uint32_t b1) {
  asm volatile(
      "mma.sync.aligned.m16n8k16.row.col.f32.f16.f16.f32 "
      "{%0,%1,%2,%3}, {%4,%5,%6,%7}, {%8,%9}, {%0,%1,%2,%3};"
      : "+f"(d[0]), "+f"(d[1]), "+f"(d[2]), "+f"(d[3])
      : "r"(a[0]), "r"(a[1]), "r"(a[2]), "r"(a[3]), "r"(b0), "r"(b1));
}

// ---------------------------------------------------------------------------
// Weight prep
// ---------------------------------------------------------------------------
__global__ void prep_weights(const float* __restrict__ W1,
                             const float* __restrict__ W2,
                             const float* __restrict__ W3) {
  int tid = blockIdx.x * 256 + threadIdx.x;
  int T = tid >> 5, lane = tid & 31;
  if (T >= 896) return;
  int g = lane >> 2, t = lane & 3;
  const float* W; int ldn, ni, ki;
  if (T < 256)      { ni = (T) >> 3;       ki = T & 7;          W = W1; ldn = 256; }
  else if (T < 768) { int T2 = T - 256; ni = T2 >> 4; ki = T2 & 15; W = W2; ldn = 256; }
  else              { int T3 = T - 768; ni = T3 >> 4; ki = T3 & 15; W = W3; ldn = 64;  }
  int n  = ni * 8 + g;
  int k0 = ki * 16 + 2 * t;
  float w00 = W[(k0    ) * ldn + n], w01 = W[(k0 + 1) * ldn + n];
  float w10 = W[(k0 + 8) * ldn + n], w11 = W[(k0 + 9) * ldn + n];
  uint32_t h0, l0, h1, l1;
  split_pack(w00, w01, h0, l0);
  split_pack(w10, w11, h1, l1);
  if (T < 256) {
    if (ki < 4) g_w1af[(ni * 4 + ki) * 32 + lane] = make_uint2(h0, h1);
    else        g_w1bf[(ni * 4 + (ki - 4)) * 32 + lane] = make_uint4(h0, h1, l0, l1);
  } else if (T < 768) {
    g_w2f[(T - 256) * 32 + lane] = make_uint2(h0, h1);
  } else {
    g_w3f[(T - 768) * 32 + lane] = make_uint2(h0, h1);
  }
}

// ---------------------------------------------------------------------------
// Single-pass fragment GEMM: acc += A_hi(frags smem) @ B_hi(uint2 frags gmem)
// ---------------------------------------------------------------------------
template<int KT, int NJ, int MT>
__device__ __forceinline__ void gemm1p(
    float (&acc)[MT][NJ][4],
    const char* __restrict__ aHi, int mBase, int lane,
    const uint2* __restrict__ B, int njBase) {
#pragma unroll
  for (int ki = 0; ki < KT; ++ki) {
    uint32_t ah[MT][4];
#pragma unroll
    for (int mt = 0; mt < MT; ++mt) {
      uint4 vh = *(const uint4*)(aHi + (((mBase + mt) * KT + ki) * 512 + lane * 16));
      ah[mt][0] = vh.x; ah[mt][1] = vh.y; ah[mt][2] = vh.z; ah[mt][3] = vh.w;
    }
#pragma unroll
    for (int jc = 0; jc < NJ; jc += 4) {
      constexpr int JW = (NJ < 4) ? NJ : 4;
      uint2 bv[JW];
#pragma unroll
      for (int j = 0; j < JW; ++j)
        bv[j] = B[((njBase + jc + j) * KT + ki) * 32 + lane];
#pragma unroll
      for (int mt = 0; mt < MT; ++mt)
#pragma unroll
        for (int j = 0; j < JW; ++j)
          mma_f16(acc[mt][jc + j], ah[mt], bv[j].x, bv[j].y);
    }
  }
}

// 3-pass variant (P0 prep only): a_hi*b_hi + a_lo*b_hi + a_hi*b_lo
template<int KT, int NJ, int MT>
__device__ __forceinline__ void gemm3p(
    float (&acc)[MT][NJ][4],
    const char* __restrict__ aHi, const char* __restrict__ aLo,
    int mBase, int lane,
    const uint4* __restrict__ B, int njBase) {
#pragma unroll
  for (int ki = 0; ki < KT; ++ki) {
    uint32_t ah[MT][4], al[MT][4];
#pragma unroll
    for (int mt = 0; mt < MT; ++mt) {
      uint4 vh = *(const uint4*)(aHi + (((mBase + mt) * KT + ki) * 512 + lane * 16));
      ah[mt][0] = vh.x; ah[mt][1] = vh.y; ah[mt][2] = vh.z; ah[mt][3] = vh.w;
      uint4 vl = *(const uint4*)(aLo + (((mBase + mt) * KT + ki) * 512 + lane * 16));
      al[mt][0] = vl.x; al[mt][1] = vl.y; al[mt][2] = vl.z; al[mt][3] = vl.w;
    }
#pragma unroll
    for (int jc = 0; jc < NJ; jc += 4) {
      constexpr int JW = (NJ < 4) ? NJ : 4;
      uint4 bv[JW];
#pragma unroll
      for (int j = 0; j < JW; ++j)
        bv[j] = B[((njBase + jc + j) * KT + ki) * 32 + lane];
#pragma unroll
      for (int mt = 0; mt < MT; ++mt)
#pragma unroll
        for (int j = 0; j < JW; ++j) {
          mma_f16(acc[mt][jc + j], ah[mt], bv[j].x, bv[j].y);
          mma_f16(acc[mt][jc + j], al[mt], bv[j].x, bv[j].y);
          mma_f16(acc[mt][jc + j], ah[mt], bv[j].z, bv[j].w);
        }
    }
  }
}

// ---------------------------------------------------------------------------
// P0 prep: P0 = X0 @ W1[64:128] + b1   (3-pass fp16, one-time)
// ---------------------------------------------------------------------------
__global__ void __launch_bounds__(256)
prep_p0(const float* __restrict__ X0g, const float* __restrict__ b1) {
  extern __shared__ char sm[];
  char* actHi = sm;
  char* actLo = sm + 8192;
  const int tid = threadIdx.x;
  const int wid = tid >> 5, lane = tid & 31;
  const int g = lane >> 2, t = lane & 3;
  const int rowBase = blockIdx.x * 64;

#pragma unroll
  for (int it = 0; it < 2; ++it) {
    int tile = wid * 2 + it;
    int mi = tile >> 2, ki = tile & 3;
    int kc = ki * 16;
    const float* p0 = X0g + (size_t)(rowBase + mi * 16 + g) * DIM + kc;
    const float* p1 = p0 + 8 * DIM;
    float2 v00 = *(const float2*)(p0 + 2 * t);
    float2 v01 = *(const float2*)(p0 + 2 * t + 8);
    float2 v10 = *(const float2*)(p1 + 2 * t);
    float2 v11 = *(const float2*)(p1 + 2 * t + 8);
    uint32_t h0, l0, h1, l1, h2, l2, h3, l3;
    split_pack(v00.x, v00.y, h0, l0);
    split_pack(v10.x, v10.y, h1, l1);
    split_pack(v01.x, v01.y, h2, l2);
    split_pack(v11.x, v11.y, h3, l3);
    int off = (mi * 4 + ki) * 512 + lane * 16;
    *(uint4*)(actHi + off) = make_uint4(h0, h1, h2, h3);
    *(uint4*)(actLo + off) = make_uint4(l0, l1, l2, l3);
  }
  __syncthreads();

  const int mrow = wid >> 2, ncol = wid & 3;
  float acc[2][8][4];
#pragma unroll
  for (int a = 0; a < 2; ++a)
#pragma unroll
    for (int b = 0; b < 8; ++b)
#pragma unroll
      for (int c = 0; c < 4; ++c) acc[a][b][c] = 0.f;
  gemm3p<4, 8, 2>(acc, actHi, actLo, mrow * 2, lane, g_w1bf, ncol * 8);

#pragma unroll
  for (int j = 0; j < 8; ++j) {
    int nj = ncol * 8 + j;
    int c0 = nj * 8 + 2 * t;
    float bb0 = b1[c0], bb1 = b1[c0 + 1];
#pragma unroll
    for (int mt = 0; mt < 2; ++mt) {
      int r = rowBase + (mrow * 2 + mt) * 16 + g;
      float2 oA = make_float2(acc[mt][j][0] + bb0, acc[mt][j][1] + bb1);
      float2 oB = make_float2(acc[mt][j][2] + bb0, acc[mt][j][3] + bb1);
      *(float2*)&g_p0[(size_t)r * 256 + c0]       = oA;
      *(float2*)&g_p0[(size_t)(r + 8) * 256 + c0] = oB;
    }
  }
}

// ---------------------------------------------------------------------------
// Persistent fused sampler: one CTA owns 64 rows for all 64 steps.
// ALL step GEMMs single-pass fp16 (minimum MMA count).
// smem: actHi 0..8K, hHi 8..40K, Xbuf 40K..56.5K
// ---------------------------------------------------------------------------
#define XSTRIDE 66

__global__ void __launch_bounds__(256, 2)
persist_sde(const float* __restrict__ X0g, float* __restrict__ out,
            const float* __restrict__ w1s,
            const float* __restrict__ b2, const float* __restrict__ b3) {
  extern __shared__ char sm[];
  char*  actHi = sm;
  char*  hHi   = sm + 8192;
  float* Xbuf  = (float*)(sm + 40960);

  const int tid  = threadIdx.x;
  const int wid  = tid >> 5;
  const int lane = tid & 31;
  const int g    = lane >> 2;
  const int t    = lane & 3;
  const int sample  = blockIdx.x >> 10;
  const int rowBase = (blockIdx.x & 1023) * 64;
  float* outp = out + (size_t)sample * NELEM;

  uint32_t sk[2][2];
  dev_split2(0u, 1u, sk);
  uint32_t ks[2][2];
  dev_split2(sk[sample][0], sk[sample][1], ks);
  uint32_t ke0 = ks[0][0], ke1 = ks[0][1];
  uint32_t kl0 = ks[1][0], kl1 = ks[1][1];

  const int mrow = wid >> 2, ncol = wid & 3;     // 2x4 warp grid (GEMM1/2)
  const int mrow3 = wid >> 1, ncol3 = wid & 1;   // 4x2 warp grid (GEMM3)

#pragma unroll 1
  for (int n = 0; n < 64; ++n) {
    const float s = (float)n * 0.015625f;
    float cf = 0.0f;
    uint32_t nk0, nk1;
    if (n == 0) {
      nk0 = ke0; nk1 = ke1;
    } else {
      uint32_t kk[2][2];
      dev_split2(kl0, kl1, kk);
      kl0 = kk[0][0]; kl1 = kk[0][1];
      nk0 = kk[1][0]; nk1 = kk[1][1];
      const float sg = 1.0f - s;
      cf = 0.5f * (1.0f - sg * sg) / (s * sg);
    }

    // ---- phase 0: stage Xin hi-frags (4 ki) from gmem (n=0) or Xbuf ----
#pragma unroll
    for (int it = 0; it < 2; ++it) {
      int tile = wid * 2 + it;
      int mi = tile >> 2, ki = tile & 3;
      int kc = ki * 16;
      const float *p0, *p1;
      if (n == 0) {
        p0 = X0g + (size_t)(rowBase + mi * 16 + g) * DIM + kc;
        p1 = p0 + 8 * DIM;
      } else {
        p0 = Xbuf + (mi * 16 + g) * XSTRIDE + kc;
        p1 = p0 + 8 * XSTRIDE;
      }
      float2 v00 = *(const float2*)(p0 + 2 * t);
      float2 v01 = *(const float2*)(p0 + 2 * t + 8);
      float2 v10 = *(const float2*)(p1 + 2 * t);
      float2 v11 = *(const float2*)(p1 + 2 * t + 8);
      uint32_t h0 = pack_h2(v00.x, v00.y);
      uint32_t h1 = pack_h2(v10.x, v10.y);
      uint32_t h2 = pack_h2(v01.x, v01.y);
      uint32_t h3 = pack_h2(v11.x, v11.y);
      int off = (mi * 4 + ki) * 512 + lane * 16;
      *(uint4*)(actHi + off) = make_uint4(h0, h1, h2, h3);
    }
    __syncthreads();

    // ---- phase 1: h1 = relu(P0 + Xin @ W1a + s*w1s) ----
    {
      float acc[2][8][4];
#pragma unroll
      for (int j = 0; j < 8; ++j) {
        int c0 = (ncol * 8 + j) * 8 + 2 * t;
#pragma unroll
        for (int mt = 0; mt < 2; ++mt) {
          int r = rowBase + (mrow * 2 + mt) * 16 + g;
          float2 pA = *(const float2*)&g_p0[(size_t)r * 256 + c0];
          float2 pB = *(const float2*)&g_p0[(size_t)(r + 8) * 256 + c0];
          acc[mt][j][0] = pA.x; acc[mt][j][1] = pA.y;
          acc[mt][j][2] = pB.x; acc[mt][j][3] = pB.y;
        }
      }
      gemm1p<4, 8, 2>(acc, actHi, mrow * 2, lane, g_w1af, ncol * 8);
#pragma unroll
      for (int j = 0; j < 8; ++j) {
        int nj = ncol * 8 + j;
        int c0 = nj * 8 + 2 * t;
        float bb0 = s * w1s[c0];
        float bb1 = s * w1s[c0 + 1];
#pragma unroll
        for (int mt = 0; mt < 2; ++mt) {
          int mi = mrow * 2 + mt;
          float v00 = fmaxf(acc[mt][j][0] + bb0, 0.f);
          float v01 = fmaxf(acc[mt][j][1] + bb1, 0.f);
          float v10 = fmaxf(acc[mt][j][2] + bb0, 0.f);
          float v11 = fmaxf(acc[mt][j][3] + bb1, 0.f);
          uint32_t h0 = pack_h2(v00, v01);
          uint32_t h1 = pack_h2(v10, v11);
          int off = (mi * 16 + (nj >> 1)) * 512 + lane * 16 + (nj & 1) * 8;
          *(uint2*)(hHi + off) = make_uint2(h0, h1);
        }
      }
    }
    __syncthreads();

    // ---- phase 2: h2 = relu(h1 @ W2 + b2), overwrite hHi ----
    {
      float acc[2][8][4];
#pragma unroll
      for (int a = 0; a < 2; ++a)
#pragma unroll
        for (int b = 0; b < 8; ++b)
#pragma unroll
          for (int c = 0; c < 4; ++c) acc[a][b][c] = 0.f;
      gemm1p<16, 8, 2>(acc, hHi, mrow * 2, lane, g_w2f, ncol * 8);
      __syncthreads();   // all warps done reading h1 before overwrite
#pragma unroll
      for (int j = 0; j < 8; ++j) {
        int nj = ncol * 8 + j;
        int c0 = nj * 8 + 2 * t;
        float bb0 = b2[c0];
        float bb1 = b2[c0 + 1];
#pragma unroll
        for (int mt = 0; mt < 2; ++mt) {
          int mi = mrow * 2 + mt;
          float v00 = fmaxf(acc[mt][j][0] + bb0, 0.f);
          float v01 = fmaxf(acc[mt][j][1] + bb1, 0.f);
          float v10 = fmaxf(acc[mt][j][2] + bb0, 0.f);
          float v11 = fmaxf(acc[mt][j][3] + bb1, 0.f);
          uint32_t h0 = pack_h2(v00, v01);
          uint32_t h1 = pack_h2(v10, v11);
          int off = (mi * 16 + (nj >> 1)) * 512 + lane * 16 + (nj & 1) * 8;
          *(uint2*)(hHi + off) = make_uint2(h0, h1);
        }
      }
    }
    __syncthreads();

    // ---- phase 3: bd = h2 @ W3 + b3; SDE update + threefry ----
    {
      float acc[1][4][4];
#pragma unroll
      for (int b = 0; b < 4; ++b)
#pragma unroll
        for (int c = 0; c < 4; ++c) acc[0][b][c] = 0.f;
      gemm1p<16, 4, 1>(acc, hHi, mrow3, lane, g_w3f, ncol3 * 4);
#pragma unroll
      for (int j = 0; j < 4; ++j) {
        int nj = ncol3 * 4 + j;
        int c0 = nj * 8 + 2 * t;
        float bb0 = b3[c0], bb1 = b3[c0 + 1];
#pragma unroll
        for (int half = 0; half < 2; ++half) {
          int rl = mrow3 * 16 + g + half * 8;
          int r  = rowBase + rl;
          float bA = acc[0][j][half * 2 + 0] + bb0;
          float bB = acc[0][j][half * 2 + 1] + bb1;
          int i0 = r * DIM + c0;
          float2 x0v = *(const float2*)(X0g + i0);
          float2 Xo;
          if (n == 0) Xo = x0v;
          else        Xo = *(const float2*)&Xbuf[rl * XSTRIDE + c0];
          uint32_t u0 = 0u, u1 = (uint32_t)i0;
          tf2x32(nk0, nk1, u0, u1);
          float e0 = bits_to_normal(u0 ^ u1);
          uint32_t w0 = 0u, w1 = (uint32_t)(i0 + 1);
          tf2x32(nk0, nk1, w0, w1);
          float e1 = bits_to_normal(w0 ^ w1);
          float d0 = bA + cf * (s * bA - Xo.x + x0v.x);
          float d1 = bB + cf * (s * bB - Xo.y + x0v.y);
          float2 o;
          o.x = Xo.x + 0.015625f * d0 + 0.125f * e0;
          o.y = Xo.y + 0.015625f * d1 + 0.125f * e1;
          *(float2*)&Xbuf[rl * XSTRIDE + c0] = o;
          if (n == 63) *(float2*)(outp + i0) = o;
        }
      }
    }
    __syncthreads();
  }
}

// ---------------------------------------------------------------------------
// Host
// ---------------------------------------------------------------------------
extern "C" void kernel_launch(void* const* d_in, const int* in_sizes, int n_in,
                              void* d_out, int out_size) {
  (void)in_sizes; (void)n_in; (void)out_size;
  const float* X0 = (const float*)d_in[0];
  const float* W1 = (const float*)d_in[1];   // [129, 256]
  const float* b1 = (const float*)d_in[2];
  const float* W2 = (const float*)d_in[3];   // [256, 256]
  const float* b2 = (const float*)d_in[4];
  const float* W3 = (const float*)d_in[5];   // [256, 64]
  const float* b3 = (const float*)d_in[6];
  float* out = (float*)d_out;                // [2, 65536, 64]

  const float* w1s = W1 + 128 * 256;         // s-feature row

  constexpr int SMEM_P0 = 16384;
  constexpr int SMEM = 40960 + 64 * XSTRIDE * 4;   // 57856 B
  cudaFuncSetAttribute((const void*)persist_sde,
                       cudaFuncAttributeMaxDynamicSharedMemorySize, SMEM);

  prep_weights<<<112, 256>>>(W1, W2, W3);
  prep_p0<<<1024, 256, SMEM_P0>>>(X0, b1);
  persist_sde<<<2048, 256, SMEM>>>(X0, out, w1s, b2, b3);
}

// round 15
// speedup vs baseline: 5.7187x; 1.0137x over previous
#include <cuda_runtime.h>
#include <cuda_fp16.h>
#include <cstdint>
#include <math.h>

#define NOBS   65536
#define DIM    64
#define NELEM  (NOBS * DIM)

// ---------------------------------------------------------------------------
// Weight fragments (fp16), mma.sync.m16n8k16 B-fragment order.
// Step-path weights: uint2 = {b0_hi, b1_hi} (single-pass).
// W1 X0-half: uint4 = {b0_hi, b1_hi, b0_lo, b1_lo} (3-pass, P0 prep only).
// ---------------------------------------------------------------------------
__device__ uint2 g_w1af[128 * 32];  // 32 nj x 4 ki  (X part of W1)
__device__ uint4 g_w1bf[128 * 32];  // 32 nj x 4 ki  (X0 part, used once)
__device__ uint2 g_w2f[512 * 32];   // 32 nj x 16 ki
__device__ uint2 g_w3f[128 * 32];   //  8 nj x 16 ki

// Step-invariant partial: P0 = X0 @ W1[64:128] + b1   [65536 x 256] f32
__device__ float g_p0[(size_t)NOBS * 256];

// ---------------------------------------------------------------------------
// threefry2x32 (JAX partitionable, exact)
// ---------------------------------------------------------------------------
__host__ __device__ __forceinline__ void tf2x32(uint32_t k0, uint32_t k1,
                                                uint32_t& x0, uint32_t& x1) {
  uint32_t ks2 = k0 ^ k1 ^ 0x1BD11BDAu;
  x0 += k0; x1 += k1;
#define TFR(r) { x0 += x1; x1 = (x1 << (r)) | (x1 >> (32 - (r))); x1 ^= x0; }
  TFR(13) TFR(15) TFR(26) TFR(6)
  x0 += k1;  x1 += ks2 + 1u;
  TFR(17) TFR(29) TFR(16) TFR(24)
  x0 += ks2; x1 += k0 + 2u;
  TFR(13) TFR(15) TFR(26) TFR(6)
  x0 += k0;  x1 += k1 + 3u;
  TFR(17) TFR(29) TFR(16) TFR(24)
  x0 += k1;  x1 += ks2 + 4u;
  TFR(13) TFR(15) TFR(26) TFR(6)
  x0 += ks2; x1 += k0 + 5u;
#undef TFR
}

__device__ __forceinline__ void dev_split2(uint32_t k0, uint32_t k1,
                                           uint32_t out[2][2]) {
#pragma unroll
  for (uint32_t j = 0; j < 2; j++) {
    uint32_t a = 0u, b = j;
    tf2x32(k0, k1, a, b);
    out[j][0] = a; out[j][1] = b;
  }
}

__device__ __forceinline__ float erfinv_xla(float x) {
  float w = -log1pf(-x * x);
  float p;
  if (w < 5.0f) {
    w -= 2.5f;
    p = 2.81022636e-08f;
    p = fmaf(p, w, 3.43273939e-07f);
    p = fmaf(p, w, -3.5233877e-06f);
    p = fmaf(p, w, -4.39150654e-06f);
    p = fmaf(p, w, 0.00021858087f);
    p = fmaf(p, w, -0.00125372503f);
    p = fmaf(p, w, -0.00417768164f);
    p = fmaf(p, w, 0.246640727f);
    p = fmaf(p, w, 1.50140941f);
  } else {
    w = sqrtf(w) - 3.0f;
    p = -0.000200214257f;
    p = fmaf(p, w, 0.000100950558f);
    p = fmaf(p, w, 0.00134934322f);
    p = fmaf(p, w, -0.00367342844f);
    p = fmaf(p, w, 0.00573950773f);
    p = fmaf(p, w, -0.0076224613f);
    p = fmaf(p, w, 0.00943887047f);
    p = fmaf(p, w, 1.00167406f);
    p = fmaf(p, w, 2.83297682f);
  }
  return p * x;
}
__device__ __forceinline__ float bits_to_normal(uint32_t bits) {
  float f = __uint_as_float((bits >> 9) | 0x3F800000u) - 1.0f;
  const float lo = -0.99999994f;
  float u = fmaxf(lo, f * 2.0f + lo);
  return 1.41421356237f * erfinv_xla(u);
}

// ---------------------------------------------------------------------------
// fp16 helpers
// ---------------------------------------------------------------------------
__device__ __forceinline__ uint32_t pack_h2(float a, float b) {
  uint32_t la = (uint32_t)__half_as_ushort(__float2half_rn(a));
  uint32_t hb = (uint32_t)__half_as_ushort(__float2half_rn(b));
  return la | (hb << 16);
}
__device__ __forceinline__ void split_pack(float a, float b,
                                           uint32_t& hi, uint32_t& lo) {
  __half ah = __float2half_rn(a), bh = __float2half_rn(b);
  hi = (uint32_t)__half_as_ushort(ah) |
       ((uint32_t)__half_as_ushort(bh) << 16);
  lo = pack_h2(a - __half2float(ah), b - __half2float(bh));
}

__device__ __forceinline__ void mma_f16(float (&d)[4], const uint32_t (&a)[4],
                                        uint32_t b0, uint32_t b1) {
  asm volatile(
      "mma.sync.aligned.m16n8k16.row.col.f32.f16.f16.f32 "
      "{%0,%1,%2,%3}, {%4,%5,%6,%7}, {%8,%9}, {%0,%1,%2,%3};"
      : "+f"(d[0]), "+f"(d[1]), "+f"(d[2]), "+f"(d[3])
      : "r"(a[0]), "r"(a[1]), "r"(a[2]), "r"(a[3]), "r"(b0), "r"(b1));
}

// ---------------------------------------------------------------------------
// Weight prep
// ---------------------------------------------------------------------------
__global__ void prep_weights(const float* __restrict__ W1,
                             const float* __restrict__ W2,
                             const float* __restrict__ W3) {
  int tid = blockIdx.x * 256 + threadIdx.x;
  int T = tid >> 5, lane = tid & 31;
  if (T >= 896) return;
  int g = lane >> 2, t = lane & 3;
  const float* W; int ldn, ni, ki;
  if (T < 256)      { ni = (T) >> 3;       ki = T & 7;          W = W1; ldn = 256; }
  else if (T < 768) { int T2 = T - 256; ni = T2 >> 4; ki = T2 & 15; W = W2; ldn = 256; }
  else              { int T3 = T - 768; ni = T3 >> 4; ki = T3 & 15; W = W3; ldn = 64;  }
  int n  = ni * 8 + g;
  int k0 = ki * 16 + 2 * t;
  float w00 = W[(k0    ) * ldn + n], w01 = W[(k0 + 1) * ldn + n];
  float w10 = W[(k0 + 8) * ldn + n], w11 = W[(k0 + 9) * ldn + n];
  uint32_t h0, l0, h1, l1;
  split_pack(w00, w01, h0, l0);
  split_pack(w10, w11, h1, l1);
  if (T < 256) {
    if (ki < 4) g_w1af[(ni * 4 + ki) * 32 + lane] = make_uint2(h0, h1);
    else        g_w1bf[(ni * 4 + (ki - 4)) * 32 + lane] = make_uint4(h0, h1, l0, l1);
  } else if (T < 768) {
    g_w2f[(T - 256) * 32 + lane] = make_uint2(h0, h1);
  } else {
    g_w3f[(T - 768) * 32 + lane] = make_uint2(h0, h1);
  }
}

// ---------------------------------------------------------------------------
// Single-pass fragment GEMM: acc += A_hi(frags smem) @ B_hi(uint2 frags gmem)
// ---------------------------------------------------------------------------
template<int KT, int NJ, int MT>
__device__ __forceinline__ void gemm1p(
    float (&acc)[MT][NJ][4],
    const char* __restrict__ aHi, int mBase, int lane,
    const uint2* __restrict__ B, int njBase) {
#pragma unroll
  for (int ki = 0; ki < KT; ++ki) {
    uint32_t ah[MT][4];
#pragma unroll
    for (int mt = 0; mt < MT; ++mt) {
      uint4 vh = *(const uint4*)(aHi + (((mBase + mt) * KT + ki) * 512 + lane * 16));
      ah[mt][0] = vh.x; ah[mt][1] = vh.y; ah[mt][2] = vh.z; ah[mt][3] = vh.w;
    }
#pragma unroll
    for (int jc = 0; jc < NJ; jc += 4) {
      constexpr int JW = (NJ < 4) ? NJ : 4;
      uint2 bv[JW];
#pragma unroll
      for (int j = 0; j < JW; ++j)
        bv[j] = B[((njBase + jc + j) * KT + ki) * 32 + lane];
#pragma unroll
      for (int mt = 0; mt < MT; ++mt)
#pragma unroll
        for (int j = 0; j < JW; ++j)
          mma_f16(acc[mt][jc + j], ah[mt], bv[j].x, bv[j].y);
    }
  }
}

// 3-pass variant (P0 prep only)
template<int KT, int NJ, int MT>
__device__ __forceinline__ void gemm3p(
    float (&acc)[MT][NJ][4],
    const char* __restrict__ aHi, const char* __restrict__ aLo,
    int mBase, int lane,
    const uint4* __restrict__ B, int njBase) {
#pragma unroll
  for (int ki = 0; ki < KT; ++ki) {
    uint32_t ah[MT][4], al[MT][4];
#pragma unroll
    for (int mt = 0; mt < MT; ++mt) {
      uint4 vh = *(const uint4*)(aHi + (((mBase + mt) * KT + ki) * 512 + lane * 16));
      ah[mt][0] = vh.x; ah[mt][1] = vh.y; ah[mt][2] = vh.z; ah[mt][3] = vh.w;
      uint4 vl = *(const uint4*)(aLo + (((mBase + mt) * KT + ki) * 512 + lane * 16));
      al[mt][0] = vl.x; al[mt][1] = vl.y; al[mt][2] = vl.z; al[mt][3] = vl.w;
    }
#pragma unroll
    for (int jc = 0; jc < NJ; jc += 4) {
      constexpr int JW = (NJ < 4) ? NJ : 4;
      uint4 bv[JW];
#pragma unroll
      for (int j = 0; j < JW; ++j)
        bv[j] = B[((njBase + jc + j) * KT + ki) * 32 + lane];
#pragma unroll
      for (int mt = 0; mt < MT; ++mt)
#pragma unroll
        for (int j = 0; j < JW; ++j) {
          mma_f16(acc[mt][jc + j], ah[mt], bv[j].x, bv[j].y);
          mma_f16(acc[mt][jc + j], al[mt], bv[j].x, bv[j].y);
          mma_f16(acc[mt][jc + j], ah[mt], bv[j].z, bv[j].w);
        }
    }
  }
}

// ---------------------------------------------------------------------------
// P0 prep: P0 = X0 @ W1[64:128] + b1   (3-pass fp16, one-time)
// ---------------------------------------------------------------------------
__global__ void __launch_bounds__(256)
prep_p0(const float* __restrict__ X0g, const float* __restrict__ b1) {
  extern __shared__ char sm[];
  char* actHi = sm;
  char* actLo = sm + 8192;
  const int tid = threadIdx.x;
  const int wid = tid >> 5, lane = tid & 31;
  const int g = lane >> 2, t = lane & 3;
  const int rowBase = blockIdx.x * 64;

#pragma unroll
  for (int it = 0; it < 2; ++it) {
    int tile = wid * 2 + it;
    int mi = tile >> 2, ki = tile & 3;
    int kc = ki * 16;
    const float* p0 = X0g + (size_t)(rowBase + mi * 16 + g) * DIM + kc;
    const float* p1 = p0 + 8 * DIM;
    float2 v00 = *(const float2*)(p0 + 2 * t);
    float2 v01 = *(const float2*)(p0 + 2 * t + 8);
    float2 v10 = *(const float2*)(p1 + 2 * t);
    float2 v11 = *(const float2*)(p1 + 2 * t + 8);
    uint32_t h0, l0, h1, l1, h2, l2, h3, l3;
    split_pack(v00.x, v00.y, h0, l0);
    split_pack(v10.x, v10.y, h1, l1);
    split_pack(v01.x, v01.y, h2, l2);
    split_pack(v11.x, v11.y, h3, l3);
    int off = (mi * 4 + ki) * 512 + lane * 16;
    *(uint4*)(actHi + off) = make_uint4(h0, h1, h2, h3);
    *(uint4*)(actLo + off) = make_uint4(l0, l1, l2, l3);
  }
  __syncthreads();

  const int mrow = wid >> 2, ncol = wid & 3;
  float acc[2][8][4];
#pragma unroll
  for (int a = 0; a < 2; ++a)
#pragma unroll
    for (int b = 0; b < 8; ++b)
#pragma unroll
      for (int c = 0; c < 4; ++c) acc[a][b][c] = 0.f;
  gemm3p<4, 8, 2>(acc, actHi, actLo, mrow * 2, lane, g_w1bf, ncol * 8);

#pragma unroll
  for (int j = 0; j < 8; ++j) {
    int nj = ncol * 8 + j;
    int c0 = nj * 8 + 2 * t;
    float bb0 = b1[c0], bb1 = b1[c0 + 1];
#pragma unroll
    for (int mt = 0; mt < 2; ++mt) {
      int r = rowBase + (mrow * 2 + mt) * 16 + g;
      float2 oA = make_float2(acc[mt][j][0] + bb0, acc[mt][j][1] + bb1);
      float2 oB = make_float2(acc[mt][j][2] + bb0, acc[mt][j][3] + bb1);
      *(float2*)&g_p0[(size_t)r * 256 + c0]       = oA;
      *(float2*)&g_p0[(size_t)(r + 8) * 256 + c0] = oB;
    }
  }
}

// ---------------------------------------------------------------------------
// Persistent fused sampler. Phase 3 writes next step's A-fragments DIRECTLY
// (D-frag layout == A-frag layout), eliminating phase 0 for n>=1.
// h1/h2 double-buffered (kills the mid-phase-2 barrier). 3 barriers/step.
// smem: actHi 0..8K, h1 8..40K, h2 40..72K, Xbuf 72K..88.5K
// ---------------------------------------------------------------------------
#define XSTRIDE 66

__global__ void __launch_bounds__(256, 2)
persist_sde(const float* __restrict__ X0g, float* __restrict__ out,
            const float* __restrict__ w1s,
            const float* __restrict__ b2, const float* __restrict__ b3) {
  extern __shared__ char sm[];
  char*  actHi = sm;
  char*  h1buf = sm + 8192;
  char*  h2buf = sm + 40960;
  float* Xbuf  = (float*)(sm + 73728);

  const int tid  = threadIdx.x;
  const int wid  = tid >> 5;
  const int lane = tid & 31;
  const int g    = lane >> 2;
  const int t    = lane & 3;
  const int sample  = blockIdx.x >> 10;
  const int rowBase = (blockIdx.x & 1023) * 64;
  float* outp = out + (size_t)sample * NELEM;

  uint32_t sk[2][2];
  dev_split2(0u, 1u, sk);
  uint32_t ks[2][2];
  dev_split2(sk[sample][0], sk[sample][1], ks);
  uint32_t ke0 = ks[0][0], ke1 = ks[0][1];
  uint32_t kl0 = ks[1][0], kl1 = ks[1][1];

  const int mrow = wid >> 2, ncol = wid & 3;     // 2x4 warp grid (GEMM1/2)
  const int mrow3 = wid >> 1, ncol3 = wid & 1;   // 4x2 warp grid (GEMM3)

#pragma unroll 1
  for (int n = 0; n < 64; ++n) {
    const float s = (float)n * 0.015625f;
    float cf = 0.0f;
    uint32_t nk0, nk1;
    if (n == 0) {
      nk0 = ke0; nk1 = ke1;
      // ---- one-time stage of X0 hi-frags ----
#pragma unroll
      for (int it = 0; it < 2; ++it) {
        int tile = wid * 2 + it;
        int mi = tile >> 2, ki = tile & 3;
        int kc = ki * 16;
        const float* p0 = X0g + (size_t)(rowBase + mi * 16 + g) * DIM + kc;
        const float* p1 = p0 + 8 * DIM;
        float2 v00 = *(const float2*)(p0 + 2 * t);
        float2 v01 = *(const float2*)(p0 + 2 * t + 8);
        float2 v10 = *(const float2*)(p1 + 2 * t);
        float2 v11 = *(const float2*)(p1 + 2 * t + 8);
        uint32_t h0 = pack_h2(v00.x, v00.y);
        uint32_t h1 = pack_h2(v10.x, v10.y);
        uint32_t h2 = pack_h2(v01.x, v01.y);
        uint32_t h3 = pack_h2(v11.x, v11.y);
        int off = (mi * 4 + ki) * 512 + lane * 16;
        *(uint4*)(actHi + off) = make_uint4(h0, h1, h2, h3);
      }
      __syncthreads();
    } else {
      uint32_t kk[2][2];
      dev_split2(kl0, kl1, kk);
      kl0 = kk[0][0]; kl1 = kk[0][1];
      nk0 = kk[1][0]; nk1 = kk[1][1];
      const float sg = 1.0f - s;
      cf = 0.5f * (1.0f - sg * sg) / (s * sg);
    }

    // ---- phase 1: h1 = relu(P0 + Xin @ W1a + s*w1s) ----
    {
      float acc[2][8][4];
#pragma unroll
      for (int j = 0; j < 8; ++j) {
        int c0 = (ncol * 8 + j) * 8 + 2 * t;
#pragma unroll
        for (int mt = 0; mt < 2; ++mt) {
          int r = rowBase + (mrow * 2 + mt) * 16 + g;
          float2 pA = *(const float2*)&g_p0[(size_t)r * 256 + c0];
          float2 pB = *(const float2*)&g_p0[(size_t)(r + 8) * 256 + c0];
          acc[mt][j][0] = pA.x; acc[mt][j][1] = pA.y;
          acc[mt][j][2] = pB.x; acc[mt][j][3] = pB.y;
        }
      }
      gemm1p<4, 8, 2>(acc, actHi, mrow * 2, lane, g_w1af, ncol * 8);
#pragma unroll
      for (int j = 0; j < 8; ++j) {
        int nj = ncol * 8 + j;
        int c0 = nj * 8 + 2 * t;
        float bb0 = s * w1s[c0];
        float bb1 = s * w1s[c0 + 1];
#pragma unroll
        for (int mt = 0; mt < 2; ++mt) {
          int mi = mrow * 2 + mt;
          float v00 = fmaxf(acc[mt][j][0] + bb0, 0.f);
          float v01 = fmaxf(acc[mt][j][1] + bb1, 0.f);
          float v10 = fmaxf(acc[mt][j][2] + bb0, 0.f);
          float v11 = fmaxf(acc[mt][j][3] + bb1, 0.f);
          uint32_t h0 = pack_h2(v00, v01);
          uint32_t h1 = pack_h2(v10, v11);
          int off = (mi * 16 + (nj >> 1)) * 512 + lane * 16 + (nj & 1) * 8;
          *(uint2*)(h1buf + off) = make_uint2(h0, h1);
        }
      }
    }
    __syncthreads();

    // ---- phase 2: h2 = relu(h1 @ W2 + b2) -> h2buf (no mid barrier) ----
    {
      float acc[2][8][4];
#pragma unroll
      for (int a = 0; a < 2; ++a)
#pragma unroll
        for (int b = 0; b < 8; ++b)
#pragma unroll
          for (int c = 0; c < 4; ++c) acc[a][b][c] = 0.f;
      gemm1p<16, 8, 2>(acc, h1buf, mrow * 2, lane, g_w2f, ncol * 8);
#pragma unroll
      for (int j = 0; j < 8; ++j) {
        int nj = ncol * 8 + j;
        int c0 = nj * 8 + 2 * t;
        float bb0 = b2[c0];
        float bb1 = b2[c0 + 1];
#pragma unroll
        for (int mt = 0; mt < 2; ++mt) {
          int mi = mrow * 2 + mt;
          float v00 = fmaxf(acc[mt][j][0] + bb0, 0.f);
          float v01 = fmaxf(acc[mt][j][1] + bb1, 0.f);
          float v10 = fmaxf(acc[mt][j][2] + bb0, 0.f);
          float v11 = fmaxf(acc[mt][j][3] + bb1, 0.f);
          uint32_t h0 = pack_h2(v00, v01);
          uint32_t h1 = pack_h2(v10, v11);
          int off = (mi * 16 + (nj >> 1)) * 512 + lane * 16 + (nj & 1) * 8;
          *(uint2*)(h2buf + off) = make_uint2(h0, h1);
        }
      }
    }
    __syncthreads();

    // ---- phase 3: bd = h2 @ W3 + b3; SDE update + threefry;
    //      write Xbuf (f32 carry) AND next step's A-frags directly ----
    {
      float acc[1][4][4];
#pragma unroll
      for (int b = 0; b < 4; ++b)
#pragma unroll
        for (int c = 0; c < 4; ++c) acc[0][b][c] = 0.f;
      gemm1p<16, 4, 1>(acc, h2buf, mrow3, lane, g_w3f, ncol3 * 4);
#pragma unroll
      for (int j = 0; j < 4; ++j) {
        int nj = ncol3 * 4 + j;
        int c0 = nj * 8 + 2 * t;
        float bb0 = b3[c0], bb1 = b3[c0 + 1];
        float ox[2], oy[2];
#pragma unroll
        for (int half = 0; half < 2; ++half) {
          int rl = mrow3 * 16 + g + half * 8;
          int r  = rowBase + rl;
          float bA = acc[0][j][half * 2 + 0] + bb0;
          float bB = acc[0][j][half * 2 + 1] + bb1;
          int i0 = r * DIM + c0;
          float2 x0v = *(const float2*)(X0g + i0);
          float2 Xo;
          if (n == 0) Xo = x0v;
          else        Xo = *(const float2*)&Xbuf[rl * XSTRIDE + c0];
          uint32_t u0 = 0u, u1 = (uint32_t)i0;
          tf2x32(nk0, nk1, u0, u1);
          float e0 = bits_to_normal(u0 ^ u1);
          uint32_t w0 = 0u, w1 = (uint32_t)(i0 + 1);
          tf2x32(nk0, nk1, w0, w1);
          float e1 = bits_to_normal(w0 ^ w1);
          float d0 = bA + cf * (s * bA - Xo.x + x0v.x);
          float d1 = bB + cf * (s * bB - Xo.y + x0v.y);
          float2 o;
          o.x = Xo.x + 0.015625f * d0 + 0.125f * e0;
          o.y = Xo.y + 0.015625f * d1 + 0.125f * e1;
          *(float2*)&Xbuf[rl * XSTRIDE + c0] = o;
          if (n == 63) *(float2*)(outp + i0) = o;
          ox[half] = o.x; oy[half] = o.y;
        }
        // D-frag -> A-frag identity: tile (mi=mrow3, ki=nj>>1),
        // even nj -> a0,a1 (offset +0); odd nj -> a2,a3 (offset +8)
        int off = (mrow3 * 4 + (nj >> 1)) * 512 + lane * 16 + (nj & 1) * 8;
        *(uint2*)(actHi + off) =
            make_uint2(pack_h2(ox[0], oy[0]), pack_h2(ox[1], oy[1]));
      }
    }
    __syncthreads();   // actHi/Xbuf ready for next step
  }
}

// ---------------------------------------------------------------------------
// Host
// ---------------------------------------------------------------------------
extern "C" void kernel_launch(void* const* d_in, const int* in_sizes, int n_in,
                              void* d_out, int out_size) {
  (void)in_sizes; (void)n_in; (void)out_size;
  const float* X0 = (const float*)d_in[0];
  const float* W1 = (const float*)d_in[1];   // [129, 256]
  const float* b1 = (const float*)d_in[2];
  const float* W2 = (const float*)d_in[3];   // [256, 256]
  const float* b2 = (const float*)d_in[4];
  const float* W3 = (const float*)d_in[5];   // [256, 64]
  const float* b3 = (const float*)d_in[6];
  float* out = (float*)d_out;                // [2, 65536, 64]

  const float* w1s = W1 + 128 * 256;         // s-feature row

  constexpr int SMEM_P0 = 16384;
  constexpr int SMEM = 73728 + 64 * XSTRIDE * 4;   // 90624 B -> 2 CTAs/SM
  cudaFuncSetAttribute((const void*)persist_sde,
                       cudaFuncAttributeMaxDynamicSharedMemorySize, SMEM);

  prep_weights<<<112, 256>>>(W1, W2, W3);
  prep_p0<<<1024, 256, SMEM_P0>>>(X0, b1);
  persist_sde<<<2048, 256, SMEM>>>(X0, out, w1s, b2, b3);
}

// round 16
// speedup vs baseline: 5.8335x; 1.0201x over previous
#include <cuda_runtime.h>
#include <cuda_fp16.h>
#include <cstdint>
#include <math.h>

#define NOBS   65536
#define DIM    64
#define NELEM  (NOBS * DIM)

// ---------------------------------------------------------------------------
// Weight fragments (fp16), mma.sync.m16n8k16 B-fragment order.
// Step-path weights: PAIRED-ki layout — one uint4 = {b0(ki),b1(ki),b0(ki+1),b1(ki+1)}
// at index ((nj*(KT/2) + kp)*32 + lane).
// W1 X0-half: uint4 = {b0_hi, b1_hi, b0_lo, b1_lo} (3-pass, P0 prep only).
// ---------------------------------------------------------------------------
__device__ uint4 g_w1af[32 * 2 * 32];   // nj 32 x kp 2
__device__ uint4 g_w1bf[128 * 32];      // 32 nj x 4 ki  (X0 part, hi/lo)
__device__ uint4 g_w2f[32 * 8 * 32];    // nj 32 x kp 8
__device__ uint4 g_w3f[8 * 8 * 32];     // nj  8 x kp 8

// Step-invariant partial: P0 = X0 @ W1[64:128] + b1   [65536 x 256] f32
__device__ float g_p0[(size_t)NOBS * 256];

// ---------------------------------------------------------------------------
// threefry2x32 (JAX partitionable, exact)
// ---------------------------------------------------------------------------
__host__ __device__ __forceinline__ void tf2x32(uint32_t k0, uint32_t k1,
                                                uint32_t& x0, uint32_t& x1) {
  uint32_t ks2 = k0 ^ k1 ^ 0x1BD11BDAu;
  x0 += k0; x1 += k1;
#define TFR(r) { x0 += x1; x1 = (x1 << (r)) | (x1 >> (32 - (r))); x1 ^= x0; }
  TFR(13) TFR(15) TFR(26) TFR(6)
  x0 += k1;  x1 += ks2 + 1u;
  TFR(17) TFR(29) TFR(16) TFR(24)
  x0 += ks2; x1 += k0 + 2u;
  TFR(13) TFR(15) TFR(26) TFR(6)
  x0 += k0;  x1 += k1 + 3u;
  TFR(17) TFR(29) TFR(16) TFR(24)
  x0 += k1;  x1 += ks2 + 4u;
  TFR(13) TFR(15) TFR(26) TFR(6)
  x0 += ks2; x1 += k0 + 5u;
#undef TFR
}

__device__ __forceinline__ void dev_split2(uint32_t k0, uint32_t k1,
                                           uint32_t out[2][2]) {
#pragma unroll
  for (uint32_t j = 0; j < 2; j++) {
    uint32_t a = 0u, b = j;
    tf2x32(k0, k1, a, b);
    out[j][0] = a; out[j][1] = b;
  }
}

__device__ __forceinline__ float erfinv_xla(float x) {
  float w = -log1pf(-x * x);
  float p;
  if (w < 5.0f) {
    w -= 2.5f;
    p = 2.81022636e-08f;
    p = fmaf(p, w, 3.43273939e-07f);
    p = fmaf(p, w, -3.5233877e-06f);
    p = fmaf(p, w, -4.39150654e-06f);
    p = fmaf(p, w, 0.00021858087f);
    p = fmaf(p, w, -0.00125372503f);
    p = fmaf(p, w, -0.00417768164f);
    p = fmaf(p, w, 0.246640727f);
    p = fmaf(p, w, 1.50140941f);
  } else {
    w = sqrtf(w) - 3.0f;
    p = -0.000200214257f;
    p = fmaf(p, w, 0.000100950558f);
    p = fmaf(p, w, 0.00134934322f);
    p = fmaf(p, w, -0.00367342844f);
    p = fmaf(p, w, 0.00573950773f);
    p = fmaf(p, w, -0.0076224613f);
    p = fmaf(p, w, 0.00943887047f);
    p = fmaf(p, w, 1.00167406f);
    p = fmaf(p, w, 2.83297682f);
  }
  return p * x;
}
__device__ __forceinline__ float bits_to_normal(uint32_t bits) {
  float f = __uint_as_float((bits >> 9) | 0x3F800000u) - 1.0f;
  const float lo = -0.99999994f;
  float u = fmaxf(lo, f * 2.0f + lo);
  return 1.41421356237f * erfinv_xla(u);
}

// ---------------------------------------------------------------------------
// fp16 helpers
// ---------------------------------------------------------------------------
__device__ __forceinline__ uint32_t pack_h2(float a, float b) {
  uint32_t la = (uint32_t)__half_as_ushort(__float2half_rn(a));
  uint32_t hb = (uint32_t)__half_as_ushort(__float2half_rn(b));
  return la | (hb << 16);
}
__device__ __forceinline__ void split_pack(float a, float b,
                                           uint32_t& hi, uint32_t& lo) {
  __half ah = __float2half_rn(a), bh = __float2half_rn(b);
  hi = (uint32_t)__half_as_ushort(ah) |
       ((uint32_t)__half_as_ushort(bh) << 16);
  lo = pack_h2(a - __half2float(ah), b - __half2float(bh));
}

__device__ __forceinline__ void mma_f16(float (&d)[4], const uint32_t (&a)[4],
                                        uint32_t b0, uint32_t b1) {
  asm volatile(
      "mma.sync.aligned.m16n8k16.row.col.f32.f16.f16.f32 "
      "{%0,%1,%2,%3}, {%4,%5,%6,%7}, {%8,%9}, {%0,%1,%2,%3};"
      : "+f"(d[0]), "+f"(d[1]), "+f"(d[2]), "+f"(d[3])
      : "r"(a[0]), "r"(a[1]), "r"(a[2]), "r"(a[3]), "r"(b0), "r"(b1));
}

// ---------------------------------------------------------------------------
// Weight prep — paired-ki layout for step-path weights
// ---------------------------------------------------------------------------
__global__ void prep_weights(const float* __restrict__ W1,
                             const float* __restrict__ W2,
                             const float* __restrict__ W3) {
  int tid = blockIdx.x * 256 + threadIdx.x;
  int T = tid >> 5, lane = tid & 31;
  if (T >= 896) return;
  int g = lane >> 2, t = lane & 3;
  const float* W; int ldn, ni, ki;
  if (T < 256)      { ni = (T) >> 3;       ki = T & 7;          W = W1; ldn = 256; }
  else if (T < 768) { int T2 = T - 256; ni = T2 >> 4; ki = T2 & 15; W = W2; ldn = 256; }
  else              { int T3 = T - 768; ni = T3 >> 4; ki = T3 & 15; W = W3; ldn = 64;  }
  int n  = ni * 8 + g;
  int k0 = ki * 16 + 2 * t;
  float w00 = W[(k0    ) * ldn + n], w01 = W[(k0 + 1) * ldn + n];
  float w10 = W[(k0 + 8) * ldn + n], w11 = W[(k0 + 9) * ldn + n];
  uint32_t h0, l0, h1, l1;
  split_pack(w00, w01, h0, l0);
  split_pack(w10, w11, h1, l1);
  if (T < 256) {
    if (ki < 4) {
      uint2* w = (uint2*)g_w1af;   // pos = ((ni*2 + ki/2)*32 + lane)*2 + (ki&1)
      w[((ni * 2 + (ki >> 1)) * 32 + lane) * 2 + (ki & 1)] = make_uint2(h0, h1);
    } else {
      g_w1bf[(ni * 4 + (ki - 4)) * 32 + lane] = make_uint4(h0, h1, l0, l1);
    }
  } else if (T < 768) {
    uint2* w = (uint2*)g_w2f;
    w[((ni * 8 + (ki >> 1)) * 32 + lane) * 2 + (ki & 1)] = make_uint2(h0, h1);
  } else {
    uint2* w = (uint2*)g_w3f;
    w[((ni * 8 + (ki >> 1)) * 32 + lane) * 2 + (ki & 1)] = make_uint2(h0, h1);
  }
}

// ---------------------------------------------------------------------------
// Single-pass fragment GEMM, paired-ki B loads (one uint4 = 2 ki of B frags).
// acc += A_hi(frags smem) @ B_hi(paired uint4 frags gmem)
// ---------------------------------------------------------------------------
template<int KT, int NJ, int MT>
__device__ __forceinline__ void gemm1p(
    float (&acc)[MT][NJ][4],
    const char* __restrict__ aHi, int mBase, int lane,
    const uint4* __restrict__ B, int njBase) {
  constexpr int KP = KT / 2;
#pragma unroll
  for (int kp = 0; kp < KP; ++kp) {
    uint32_t ah0[MT][4], ah1[MT][4];
#pragma unroll
    for (int mt = 0; mt < MT; ++mt) {
      uint4 v0 = *(const uint4*)(aHi + (((mBase + mt) * KT + 2 * kp) * 512 + lane * 16));
      ah0[mt][0] = v0.x; ah0[mt][1] = v0.y; ah0[mt][2] = v0.z; ah0[mt][3] = v0.w;
      uint4 v1 = *(const uint4*)(aHi + (((mBase + mt) * KT + 2 * kp + 1) * 512 + lane * 16));
      ah1[mt][0] = v1.x; ah1[mt][1] = v1.y; ah1[mt][2] = v1.z; ah1[mt][3] = v1.w;
    }
#pragma unroll
    for (int jc = 0; jc < NJ; jc += 4) {
      constexpr int JW = (NJ < 4) ? NJ : 4;
      uint4 bv[JW];
#pragma unroll
      for (int j = 0; j < JW; ++j)
        bv[j] = B[((njBase + jc + j) * KP + kp) * 32 + lane];
      // first ki of the pair: all independent accs
#pragma unroll
      for (int mt = 0; mt < MT; ++mt)
#pragma unroll
        for (int j = 0; j < JW; ++j)
          mma_f16(acc[mt][jc + j], ah0[mt], bv[j].x, bv[j].y);
      // second ki of the pair
#pragma unroll
      for (int mt = 0; mt < MT; ++mt)
#pragma unroll
        for (int j = 0; j < JW; ++j)
          mma_f16(acc[mt][jc + j], ah1[mt], bv[j].z, bv[j].w);
    }
  }
}

// 3-pass variant (P0 prep only; unpaired layout)
template<int KT, int NJ, int MT>
__device__ __forceinline__ void gemm3p(
    float (&acc)[MT][NJ][4],
    const char* __restrict__ aHi, const char* __restrict__ aLo,
    int mBase, int lane,
    const uint4* __restrict__ B, int njBase) {
#pragma unroll
  for (int ki = 0; ki < KT; ++ki) {
    uint32_t ah[MT][4], al[MT][4];
#pragma unroll
    for (int mt = 0; mt < MT; ++mt) {
      uint4 vh = *(const uint4*)(aHi + (((mBase + mt) * KT + ki) * 512 + lane * 16));
      ah[mt][0] = vh.x; ah[mt][1] = vh.y; ah[mt][2] = vh.z; ah[mt][3] = vh.w;
      uint4 vl = *(const uint4*)(aLo + (((mBase + mt) * KT + ki) * 512 + lane * 16));
      al[mt][0] = vl.x; al[mt][1] = vl.y; al[mt][2] = vl.z; al[mt][3] = vl.w;
    }
#pragma unroll
    for (int jc = 0; jc < NJ; jc += 4) {
      constexpr int JW = (NJ < 4) ? NJ : 4;
      uint4 bv[JW];
#pragma unroll
      for (int j = 0; j < JW; ++j)
        bv[j] = B[((njBase + jc + j) * KT + ki) * 32 + lane];
#pragma unroll
      for (int mt = 0; mt < MT; ++mt)
#pragma unroll
        for (int j = 0; j < JW; ++j) {
          mma_f16(acc[mt][jc + j], ah[mt], bv[j].x, bv[j].y);
          mma_f16(acc[mt][jc + j], al[mt], bv[j].x, bv[j].y);
          mma_f16(acc[mt][jc + j], ah[mt], bv[j].z, bv[j].w);
        }
    }
  }
}

// ---------------------------------------------------------------------------
// P0 prep: P0 = X0 @ W1[64:128] + b1   (3-pass fp16, one-time)
// ---------------------------------------------------------------------------
__global__ void __launch_bounds__(256)
prep_p0(const float* __restrict__ X0g, const float* __restrict__ b1) {
  extern __shared__ char sm[];
  char* actHi = sm;
  char* actLo = sm + 8192;
  const int tid = threadIdx.x;
  const int wid = tid >> 5, lane = tid & 31;
  const int g = lane >> 2, t = lane & 3;
  const int rowBase = blockIdx.x * 64;

#pragma unroll
  for (int it = 0; it < 2; ++it) {
    int tile = wid * 2 + it;
    int mi = tile >> 2, ki = tile & 3;
    int kc = ki * 16;
    const float* p0 = X0g + (size_t)(rowBase + mi * 16 + g) * DIM + kc;
    const float* p1 = p0 + 8 * DIM;
    float2 v00 = *(const float2*)(p0 + 2 * t);
    float2 v01 = *(const float2*)(p0 + 2 * t + 8);
    float2 v10 = *(const float2*)(p1 + 2 * t);
    float2 v11 = *(const float2*)(p1 + 2 * t + 8);
    uint32_t h0, l0, h1, l1, h2, l2, h3, l3;
    split_pack(v00.x, v00.y, h0, l0);
    split_pack(v10.x, v10.y, h1, l1);
    split_pack(v01.x, v01.y, h2, l2);
    split_pack(v11.x, v11.y, h3, l3);
    int off = (mi * 4 + ki) * 512 + lane * 16;
    *(uint4*)(actHi + off) = make_uint4(h0, h1, h2, h3);
    *(uint4*)(actLo + off) = make_uint4(l0, l1, l2, l3);
  }
  __syncthreads();

  const int mrow = wid >> 2, ncol = wid & 3;
  float acc[2][8][4];
#pragma unroll
  for (int a = 0; a < 2; ++a)
#pragma unroll
    for (int b = 0; b < 8; ++b)
#pragma unroll
      for (int c = 0; c < 4; ++c) acc[a][b][c] = 0.f;
  gemm3p<4, 8, 2>(acc, actHi, actLo, mrow * 2, lane, g_w1bf, ncol * 8);

#pragma unroll
  for (int j = 0; j < 8; ++j) {
    int nj = ncol * 8 + j;
    int c0 = nj * 8 + 2 * t;
    float bb0 = b1[c0], bb1 = b1[c0 + 1];
#pragma unroll
    for (int mt = 0; mt < 2; ++mt) {
      int r = rowBase + (mrow * 2 + mt) * 16 + g;
      float2 oA = make_float2(acc[mt][j][0] + bb0, acc[mt][j][1] + bb1);
      float2 oB = make_float2(acc[mt][j][2] + bb0, acc[mt][j][3] + bb1);
      *(float2*)&g_p0[(size_t)r * 256 + c0]       = oA;
      *(float2*)&g_p0[(size_t)(r + 8) * 256 + c0] = oB;
    }
  }
}

// ---------------------------------------------------------------------------
// Persistent fused sampler. Phase 3 writes next step's A-fragments directly.
// 3 barriers/step. Paired-ki B loads halve GEMM B LDG traffic.
// smem: actHi 0..8K, h1 8..40K, h2 40..72K, Xbuf 72K..88.5K
// ---------------------------------------------------------------------------
#define XSTRIDE 66

__global__ void __launch_bounds__(256, 2)
persist_sde(const float* __restrict__ X0g, float* __restrict__ out,
            const float* __restrict__ w1s,
            const float* __restrict__ b2, const float* __restrict__ b3) {
  extern __shared__ char sm[];
  char*  actHi = sm;
  char*  h1buf = sm + 8192;
  char*  h2buf = sm + 40960;
  float* Xbuf  = (float*)(sm + 73728);

  const int tid  = threadIdx.x;
  const int wid  = tid >> 5;
  const int lane = tid & 31;
  const int g    = lane >> 2;
  const int t    = lane & 3;
  const int sample  = blockIdx.x >> 10;
  const int rowBase = (blockIdx.x & 1023) * 64;
  float* outp = out + (size_t)sample * NELEM;

  uint32_t sk[2][2];
  dev_split2(0u, 1u, sk);
  uint32_t ks[2][2];
  dev_split2(sk[sample][0], sk[sample][1], ks);
  uint32_t ke0 = ks[0][0], ke1 = ks[0][1];
  uint32_t kl0 = ks[1][0], kl1 = ks[1][1];

  const int mrow = wid >> 2, ncol = wid & 3;     // 2x4 warp grid (GEMM1/2)
  const int mrow3 = wid >> 1, ncol3 = wid & 1;   // 4x2 warp grid (GEMM3)

#pragma unroll 1
  for (int n = 0; n < 64; ++n) {
    const float s = (float)n * 0.015625f;
    float cf = 0.0f;
    uint32_t nk0, nk1;
    if (n == 0) {
      nk0 = ke0; nk1 = ke1;
      // ---- one-time stage of X0 hi-frags ----
#pragma unroll
      for (int it = 0; it < 2; ++it) {
        int tile = wid * 2 + it;
        int mi = tile >> 2, ki = tile & 3;
        int kc = ki * 16;
        const float* p0 = X0g + (size_t)(rowBase + mi * 16 + g) * DIM + kc;
        const float* p1 = p0 + 8 * DIM;
        float2 v00 = *(const float2*)(p0 + 2 * t);
        float2 v01 = *(const float2*)(p0 + 2 * t + 8);
        float2 v10 = *(const float2*)(p1 + 2 * t);
        float2 v11 = *(const float2*)(p1 + 2 * t + 8);
        uint32_t h0 = pack_h2(v00.x, v00.y);
        uint32_t h1 = pack_h2(v10.x, v10.y);
        uint32_t h2 = pack_h2(v01.x, v01.y);
        uint32_t h3 = pack_h2(v11.x, v11.y);
        int off = (mi * 4 + ki) * 512 + lane * 16;
        *(uint4*)(actHi + off) = make_uint4(h0, h1, h2, h3);
      }
      __syncthreads();
    } else {
      uint32_t kk[2][2];
      dev_split2(kl0, kl1, kk);
      kl0 = kk[0][0]; kl1 = kk[0][1];
      nk0 = kk[1][0]; nk1 = kk[1][1];
      const float sg = 1.0f - s;
      cf = 0.5f * (1.0f - sg * sg) / (s * sg);
    }

    // ---- phase 1: h1 = relu(P0 + Xin @ W1a + s*w1s) ----
    {
      float acc[2][8][4];
#pragma unroll
      for (int j = 0; j < 8; ++j) {
        int c0 = (ncol * 8 + j) * 8 + 2 * t;
#pragma unroll
        for (int mt = 0; mt < 2; ++mt) {
          int r = rowBase + (mrow * 2 + mt) * 16 + g;
          float2 pA = *(const float2*)&g_p0[(size_t)r * 256 + c0];
          float2 pB = *(const float2*)&g_p0[(size_t)(r + 8) * 256 + c0];
          acc[mt][j][0] = pA.x; acc[mt][j][1] = pA.y;
          acc[mt][j][2] = pB.x; acc[mt][j][3] = pB.y;
        }
      }
      gemm1p<4, 8, 2>(acc, actHi, mrow * 2, lane, g_w1af, ncol * 8);
#pragma unroll
      for (int j = 0; j < 8; ++j) {
        int nj = ncol * 8 + j;
        int c0 = nj * 8 + 2 * t;
        float bb0 = s * w1s[c0];
        float bb1 = s * w1s[c0 + 1];
#pragma unroll
        for (int mt = 0; mt < 2; ++mt) {
          int mi = mrow * 2 + mt;
          float v00 = fmaxf(acc[mt][j][0] + bb0, 0.f);
          float v01 = fmaxf(acc[mt][j][1] + bb1, 0.f);
          float v10 = fmaxf(acc[mt][j][2] + bb0, 0.f);
          float v11 = fmaxf(acc[mt][j][3] + bb1, 0.f);
          uint32_t h0 = pack_h2(v00, v01);
          uint32_t h1 = pack_h2(v10, v11);
          int off = (mi * 16 + (nj >> 1)) * 512 + lane * 16 + (nj & 1) * 8;
          *(uint2*)(h1buf + off) = make_uint2(h0, h1);
        }
      }
    }
    __syncthreads();

    // ---- phase 2: h2 = relu(h1 @ W2 + b2) -> h2buf ----
    {
      float acc[2][8][4];
#pragma unroll
      for (int a = 0; a < 2; ++a)
#pragma unroll
        for (int b = 0; b < 8; ++b)
#pragma unroll
          for (int c = 0; c < 4; ++c) acc[a][b][c] = 0.f;
      gemm1p<16, 8, 2>(acc, h1buf, mrow * 2, lane, g_w2f, ncol * 8);
#pragma unroll
      for (int j = 0; j < 8; ++j) {
        int nj = ncol * 8 + j;
        int c0 = nj * 8 + 2 * t;
        float bb0 = b2[c0];
        float bb1 = b2[c0 + 1];
#pragma unroll
        for (int mt = 0; mt < 2; ++mt) {
          int mi = mrow * 2 + mt;
          float v00 = fmaxf(acc[mt][j][0] + bb0, 0.f);
          float v01 = fmaxf(acc[mt][j][1] + bb1, 0.f);
          float v10 = fmaxf(acc[mt][j][2] + bb0, 0.f);
          float v11 = fmaxf(acc[mt][j][3] + bb1, 0.f);
          uint32_t h0 = pack_h2(v00, v01);
          uint32_t h1 = pack_h2(v10, v11);
          int off = (mi * 16 + (nj >> 1)) * 512 + lane * 16 + (nj & 1) * 8;
          *(uint2*)(h2buf + off) = make_uint2(h0, h1);
        }
      }
    }
    __syncthreads();

    // ---- phase 3: bd = h2 @ W3 + b3; SDE update + threefry;
    //      write Xbuf (f32 carry) AND next step's A-frags directly ----
    {
      float acc[1][4][4];
#pragma unroll
      for (int b = 0; b < 4; ++b)
#pragma unroll
        for (int c = 0; c < 4; ++c) acc[0][b][c] = 0.f;
      gemm1p<16, 4, 1>(acc, h2buf, mrow3, lane, g_w3f, ncol3 * 4);
#pragma unroll
      for (int j = 0; j < 4; ++j) {
        int nj = ncol3 * 4 + j;
        int c0 = nj * 8 + 2 * t;
        float bb0 = b3[c0], bb1 = b3[c0 + 1];
        float ox[2], oy[2];
#pragma unroll
        for (int half = 0; half < 2; ++half) {
          int rl = mrow3 * 16 + g + half * 8;
          int r  = rowBase + rl;
          float bA = acc[0][j][half * 2 + 0] + bb0;
          float bB = acc[0][j][half * 2 + 1] + bb1;
          int i0 = r * DIM + c0;
          float2 x0v = *(const float2*)(X0g + i0);
          float2 Xo;
          if (n == 0) Xo = x0v;
          else        Xo = *(const float2*)&Xbuf[rl * XSTRIDE + c0];
          uint32_t u0 = 0u, u1 = (uint32_t)i0;
          tf2x32(nk0, nk1, u0, u1);
          float e0 = bits_to_normal(u0 ^ u1);
          uint32_t w0 = 0u, w1 = (uint32_t)(i0 + 1);
          tf2x32(nk0, nk1, w0, w1);
          float e1 = bits_to_normal(w0 ^ w1);
          float d0 = bA + cf * (s * bA - Xo.x + x0v.x);
          float d1 = bB + cf * (s * bB - Xo.y + x0v.y);
          float2 o;
          o.x = Xo.x + 0.015625f * d0 + 0.125f * e0;
          o.y = Xo.y + 0.015625f * d1 + 0.125f * e1;
          *(float2*)&Xbuf[rl * XSTRIDE + c0] = o;
          if (n == 63) *(float2*)(outp + i0) = o;
          ox[half] = o.x; oy[half] = o.y;
        }
        // D-frag -> A-frag identity: tile (mi=mrow3, ki=nj>>1)
        int off = (mrow3 * 4 + (nj >> 1)) * 512 + lane * 16 + (nj & 1) * 8;
        *(uint2*)(actHi + off) =
            make_uint2(pack_h2(ox[0], oy[0]), pack_h2(ox[1], oy[1]));
      }
    }
    __syncthreads();   // actHi/Xbuf ready for next step
  }
}

// ---------------------------------------------------------------------------
// Host
// ---------------------------------------------------------------------------
extern "C" void kernel_launch(void* const* d_in, const int* in_sizes, int n_in,
                              void* d_out, int out_size) {
  (void)in_sizes; (void)n_in; (void)out_size;
  const float* X0 = (const float*)d_in[0];
  const float* W1 = (const float*)d_in[1];   // [129, 256]
  const float* b1 = (const float*)d_in[2];
  const float* W2 = (const float*)d_in[3];   // [256, 256]
  const float* b2 = (const float*)d_in[4];
  const float* W3 = (const float*)d_in[5];   // [256, 64]
  const float* b3 = (const float*)d_in[6];
  float* out = (float*)d_out;                // [2, 65536, 64]

  const float* w1s = W1 + 128 * 256;         // s-feature row

  constexpr int SMEM_P0 = 16384;
  constexpr int SMEM = 73728 + 64 * XSTRIDE * 4;   // 90624 B -> 2 CTAs/SM
  cudaFuncSetAttribute((const void*)persist_sde,
                       cudaFuncAttributeMaxDynamicSharedMemorySize, SMEM);

  prep_weights<<<112, 256>>>(W1, W2, W3);
  prep_p0<<<1024, 256, SMEM_P0>>>(X0, b1);
  persist_sde<<<2048, 256, SMEM>>>(X0, out, w1s, b2, b3);
}